// round 1
// baseline (speedup 1.0000x reference)
#include <cuda_runtime.h>
#include <math.h>

// Problem constants
#define NSAMP 256            // B*L
#define W_    128
#define C_    512
#define HD_   256
#define MROWS 32768          // B*W  (= NSAMP*W_)
#define OUT0  ((size_t)16777216)   // B*L*W*C

// ---------------- scratch (static device globals; no allocations) ----------------
__device__ float g_ZXf[(size_t)MROWS * 1024];   // fwd input projection  [n*128+w, 1024]
__device__ float g_ZXb[(size_t)MROWS * 1024];   // bwd input projection  (original order)
__device__ float g_HS [(size_t)MROWS * 512];    // concat hidden [n*128+w, fwd(256)|bwd(256)]
__device__ float g_FC [(size_t)MROWS * 512];    // fc1 / fc2 output (reused)
__device__ float g_IZ [(size_t)MROWS * 2048];   // inter LSTM z
__device__ float g_H  [512 * 256];              // recurrence h   (rows: 0-255 fwd, 256-511 bwd)
__device__ float g_Cs [512 * 256];              // recurrence c
__device__ float g_Zb [512 * 1024];             // per-step z buffer
__device__ unsigned long long g_bar = 0ULL;     // monotonic barrier ticket

__device__ __forceinline__ float hsig(float x) {
    return fminf(fmaxf(fmaf(0.2f, x, 0.5f), 0.0f), 1.0f);
}

// ---------------- software grid barrier (128 resident CTAs) ----------------
__device__ __forceinline__ void grid_barrier(unsigned long long nb) {
    __threadfence();
    __syncthreads();
    if (threadIdx.x == 0) {
        unsigned long long t = atomicAdd(&g_bar, 1ULL) + 1ULL;
        unsigned long long target = ((t + nb - 1ULL) / nb) * nb;
        volatile unsigned long long* p = &g_bar;
        while (*p < target) { __nanosleep(64); }
        __threadfence();
    }
    __syncthreads();
}

// ---------------- generic SGEMM: C[M,N] = A[M,K] @ B[K,N] (+bias) (+=C) ----------------
// BM=BN=128, BK=16, 256 threads, 8x8 microtile. M%128==0, N%128==0, K%16==0 (always true here).
__global__ __launch_bounds__(256) void sgemm128(
    const float* __restrict__ A, const float* __restrict__ B,
    float* __restrict__ C, const float* __restrict__ bias,
    int M, int N, int K, int accumulate)
{
    __shared__ float As[16][128];   // transposed: As[k][m]
    __shared__ float Bs[16][128];

    const int tid  = threadIdx.x;
    const int row0 = blockIdx.y << 7;
    const int col0 = blockIdx.x << 7;
    const int tx = tid & 15, ty = tid >> 4;

    const int ar = tid >> 2;            // 0..63
    const int ac = (tid & 3) << 2;      // 0,4,8,12
    const int br = tid >> 5;            // 0..7
    const int bc = (tid & 31) << 2;     // 0..124

    float acc[8][8];
#pragma unroll
    for (int i = 0; i < 8; i++)
#pragma unroll
        for (int j = 0; j < 8; j++) acc[i][j] = 0.0f;

    const float* Ap = A + (size_t)row0 * K;
    const float* Bp = B + col0;

    for (int kk = 0; kk < K; kk += 16) {
        float4 a0 = *(const float4*)(Ap + (size_t)ar        * K + kk + ac);
        float4 a1 = *(const float4*)(Ap + (size_t)(ar + 64) * K + kk + ac);
        float4 b0 = *(const float4*)(Bp + (size_t)(kk + br    ) * N + bc);
        float4 b1 = *(const float4*)(Bp + (size_t)(kk + br + 8) * N + bc);

        As[ac + 0][ar] = a0.x; As[ac + 1][ar] = a0.y; As[ac + 2][ar] = a0.z; As[ac + 3][ar] = a0.w;
        As[ac + 0][ar + 64] = a1.x; As[ac + 1][ar + 64] = a1.y; As[ac + 2][ar + 64] = a1.z; As[ac + 3][ar + 64] = a1.w;
        *(float4*)&Bs[br    ][bc] = b0;
        *(float4*)&Bs[br + 8][bc] = b1;
        __syncthreads();

#pragma unroll
        for (int k = 0; k < 16; k++) {
            float a[8], b[8];
            *(float4*)&a[0] = *(const float4*)&As[k][(ty << 3)];
            *(float4*)&a[4] = *(const float4*)&As[k][(ty << 3) + 4];
            *(float4*)&b[0] = *(const float4*)&Bs[k][(tx << 3)];
            *(float4*)&b[4] = *(const float4*)&Bs[k][(tx << 3) + 4];
#pragma unroll
            for (int i = 0; i < 8; i++)
#pragma unroll
                for (int j = 0; j < 8; j++) acc[i][j] = fmaf(a[i], b[j], acc[i][j]);
        }
        __syncthreads();
    }

#pragma unroll
    for (int i = 0; i < 8; i++) {
        const int r = row0 + (ty << 3) + i;
        float* Cp = C + (size_t)r * N + col0 + (tx << 3);
        const float* bp = bias + col0 + (tx << 3);
#pragma unroll
        for (int j = 0; j < 8; j++) {
            float v = acc[i][j];
            if (bias) v += bp[j];
            if (accumulate) v += Cp[j];
            Cp[j] = v;
        }
    }
}

// ---------------- persistent bidirectional LSTM recurrence ----------------
// 128 CTAs x 256 threads. Per step: GEMM z = H @ U (tiles 64x64 over [512,1024]),
// barrier, gate update (each thread owns one float4 of [512,256] state), barrier.
__global__ __launch_bounds__(256) void recurrence_kernel(
    const float* __restrict__ Uf, const float* __restrict__ Ub)
{
    __shared__ float As[16][64];
    __shared__ float Bs[16][64];

    const int tid = threadIdx.x;
    const int blk = blockIdx.x;
    const int tile_m = blk >> 4;     // 0..7
    const int tile_n = blk & 15;     // 0..15
    const float* U = (tile_m < 4) ? Uf : Ub;
    const int row0 = tile_m << 6;
    const int col0 = tile_n << 6;
    const int tx = tid & 15, ty = tid >> 4;

    // zero init state
    {
        const int base = blk * 1024;
        for (int i = tid; i < 1024; i += 256) { g_H[base + i] = 0.0f; g_Cs[base + i] = 0.0f; }
    }

    // GEMM-phase load indices
    const int ar = tid >> 2;            // 0..63
    const int ac = (tid & 3) << 2;      // 0,4,8,12
    const int br = tid >> 4;            // 0..15
    const int bc = (tid & 15) << 2;     // 0..60

    // update-phase indices: one float4 of the 512x256 state per thread
    const int e4   = blk * 256 + tid;   // 0..32767
    const int ur   = e4 >> 6;           // 0..511
    const int uj   = (e4 & 63) << 2;    // 0..252
    const int un   = ur & 255;
    const bool ubwd = (ur >= 256);
    const float* uzx = ubwd ? g_ZXb : g_ZXf;

    grid_barrier(128ULL);

    for (int t = 0; t < 128; t++) {
        // ---- GEMM phase: g_Zb[row0:+64, col0:+64] = H @ U ----
        float acc[4][4];
#pragma unroll
        for (int i = 0; i < 4; i++)
#pragma unroll
            for (int j = 0; j < 4; j++) acc[i][j] = 0.0f;

        for (int kk = 0; kk < 256; kk += 16) {
            float4 av = *(const float4*)(g_H + (size_t)(row0 + ar) * 256 + kk + ac);
            As[ac + 0][ar] = av.x; As[ac + 1][ar] = av.y; As[ac + 2][ar] = av.z; As[ac + 3][ar] = av.w;
            *(float4*)&Bs[br][bc] = *(const float4*)(U + (size_t)(kk + br) * 1024 + col0 + bc);
            __syncthreads();
#pragma unroll
            for (int k = 0; k < 16; k++) {
                float a[4], b[4];
                *(float4*)a = *(const float4*)&As[k][(ty << 2)];
                *(float4*)b = *(const float4*)&Bs[k][(tx << 2)];
#pragma unroll
                for (int i = 0; i < 4; i++)
#pragma unroll
                    for (int j = 0; j < 4; j++) acc[i][j] = fmaf(a[i], b[j], acc[i][j]);
            }
            __syncthreads();
        }
#pragma unroll
        for (int i = 0; i < 4; i++) {
            float4 v = make_float4(acc[i][0], acc[i][1], acc[i][2], acc[i][3]);
            *(float4*)(g_Zb + (size_t)(row0 + (ty << 2) + i) * 1024 + col0 + (tx << 2)) = v;
        }

        grid_barrier(128ULL);

        // ---- update phase ----
        {
            const int w = ubwd ? (127 - t) : t;
            const float* zxp = uzx + ((size_t)un * 128 + w) * 1024;
            const float* zp  = g_Zb + (size_t)ur * 1024;

            float4 zi = *(const float4*)(zp + uj);
            float4 zf = *(const float4*)(zp + 256 + uj);
            float4 zg = *(const float4*)(zp + 512 + uj);
            float4 zo = *(const float4*)(zp + 768 + uj);
            float4 xi = *(const float4*)(zxp + uj);
            float4 xf = *(const float4*)(zxp + 256 + uj);
            float4 xg = *(const float4*)(zxp + 512 + uj);
            float4 xo = *(const float4*)(zxp + 768 + uj);
            float4 c  = *(const float4*)(g_Cs + (size_t)ur * 256 + uj);

            float ci[4] = {c.x, c.y, c.z, c.w};
            float zi_[4] = {zi.x + xi.x, zi.y + xi.y, zi.z + xi.z, zi.w + xi.w};
            float zf_[4] = {zf.x + xf.x, zf.y + xf.y, zf.z + xf.z, zf.w + xf.w};
            float zg_[4] = {zg.x + xg.x, zg.y + xg.y, zg.z + xg.z, zg.w + xg.w};
            float zo_[4] = {zo.x + xo.x, zo.y + xo.y, zo.z + xo.z, zo.w + xo.w};
            float hv[4], cv[4];
#pragma unroll
            for (int l = 0; l < 4; l++) {
                float cn = hsig(zf_[l]) * ci[l] + hsig(zi_[l]) * tanhf(zg_[l]);
                cv[l] = cn;
                hv[l] = hsig(zo_[l]) * tanhf(cn);
            }
            *(float4*)(g_Cs + (size_t)ur * 256 + uj) = make_float4(cv[0], cv[1], cv[2], cv[3]);
            *(float4*)(g_H  + (size_t)ur * 256 + uj) = make_float4(hv[0], hv[1], hv[2], hv[3]);
            *(float4*)(g_HS + ((size_t)un * 128 + w) * 512 + (ubwd ? 256 : 0) + uj) =
                make_float4(hv[0], hv[1], hv[2], hv[3]);
        }

        grid_barrier(128ULL);
    }
}

// ---------------- LayerNorm over (W,C)=65536 per sample, + residual ----------------
// mode 0: out = xres + LN(pre)*g+b ; mode 1: out += LN(pre)*g+b
__global__ __launch_bounds__(256) void ln_kernel(
    const float* __restrict__ pre, const float* __restrict__ xres,
    const float* __restrict__ gamma, const float* __restrict__ beta,
    float* __restrict__ out, int mode)
{
    __shared__ float red[256];
    const int tid = threadIdx.x;
    const size_t base = (size_t)blockIdx.x * 65536;

    float s = 0.0f, ss = 0.0f;
    for (int i = tid * 4; i < 65536; i += 1024) {
        float4 v = *(const float4*)(pre + base + i);
        s  += v.x + v.y + v.z + v.w;
        ss += v.x * v.x + v.y * v.y + v.z * v.z + v.w * v.w;
    }
    red[tid] = s; __syncthreads();
    for (int off = 128; off; off >>= 1) { if (tid < off) red[tid] += red[tid + off]; __syncthreads(); }
    const float mean = red[0] * (1.0f / 65536.0f);
    __syncthreads();
    red[tid] = ss; __syncthreads();
    for (int off = 128; off; off >>= 1) { if (tid < off) red[tid] += red[tid + off]; __syncthreads(); }
    const float var = red[0] * (1.0f / 65536.0f) - mean * mean;
    const float rstd = rsqrtf(var + 1e-3f);

    for (int i = tid * 4; i < 65536; i += 1024) {
        float4 v = *(const float4*)(pre + base + i);
        float4 g = *(const float4*)(gamma + i);
        float4 bb = *(const float4*)(beta + i);
        float4 r;
        r.x = (v.x - mean) * rstd * g.x + bb.x;
        r.y = (v.y - mean) * rstd * g.y + bb.y;
        r.z = (v.z - mean) * rstd * g.z + bb.z;
        r.w = (v.w - mean) * rstd * g.w + bb.w;
        if (mode == 0) {
            float4 xr = *(const float4*)(xres + base + i);
            r.x += xr.x; r.y += xr.y; r.z += xr.z; r.w += xr.w;
        } else {
            float4 o = *(const float4*)(out + base + i);
            r.x += o.x; r.y += o.y; r.z += o.z; r.w += o.w;
        }
        *(float4*)(out + base + i) = r;
    }
}

// ---------------- inter LSTM single-step gate update ----------------
__global__ __launch_bounds__(256) void inter_gate_kernel(
    const float* __restrict__ Z, const float* __restrict__ c0,
    float* __restrict__ h_new, float* __restrict__ c_new)
{
    const int q = blockIdx.x * blockDim.x + threadIdx.x;   // float4 index, 4194304 total
    const int m = q >> 7;
    const int j = (q & 127) << 2;
    const float* zp = Z + (size_t)m * 2048;
    float4 zi = *(const float4*)(zp + j);
    float4 zf = *(const float4*)(zp + 512 + j);
    float4 zg = *(const float4*)(zp + 1024 + j);
    float4 zo = *(const float4*)(zp + 1536 + j);
    float4 c  = *(const float4*)(c0 + (size_t)m * 512 + j);

    float zi_[4] = {zi.x, zi.y, zi.z, zi.w};
    float zf_[4] = {zf.x, zf.y, zf.z, zf.w};
    float zg_[4] = {zg.x, zg.y, zg.z, zg.w};
    float zo_[4] = {zo.x, zo.y, zo.z, zo.w};
    float ci[4]  = {c.x, c.y, c.z, c.w};
    float cv[4], hv[4];
#pragma unroll
    for (int l = 0; l < 4; l++) {
        float cn = hsig(zf_[l]) * ci[l] + hsig(zi_[l]) * tanhf(zg_[l]);
        cv[l] = cn;
        hv[l] = hsig(zo_[l]) * tanhf(cn);
    }
    *(float4*)(c_new + (size_t)m * 512 + j) = make_float4(cv[0], cv[1], cv[2], cv[3]);
    *(float4*)(h_new + (size_t)m * 512 + j) = make_float4(hv[0], hv[1], hv[2], hv[3]);
}

// ---------------- launch ----------------
extern "C" void kernel_launch(void* const* d_in, const int* in_sizes, int n_in,
                              void* d_out, int out_size)
{
    const float* x    = (const float*)d_in[0];
    const float* h0   = (const float*)d_in[1];
    const float* c0   = (const float*)d_in[2];
    const float* Wf   = (const float*)d_in[3];
    const float* Uf   = (const float*)d_in[4];
    const float* bf   = (const float*)d_in[5];
    const float* Wb   = (const float*)d_in[6];
    const float* Ub   = (const float*)d_in[7];
    const float* bb   = (const float*)d_in[8];
    const float* Wfc1 = (const float*)d_in[9];
    const float* bfc1 = (const float*)d_in[10];
    const float* g1   = (const float*)d_in[11];
    const float* b1   = (const float*)d_in[12];
    const float* Wi   = (const float*)d_in[13];
    const float* Ui   = (const float*)d_in[14];
    const float* bi   = (const float*)d_in[15];
    const float* Wfc2 = (const float*)d_in[16];
    const float* bfc2 = (const float*)d_in[17];
    const float* g2   = (const float*)d_in[18];
    const float* b2   = (const float*)d_in[19];

    float* out = (float*)d_out;
    float* h_out = out + OUT0;
    float* c_out = out + 2 * OUT0;
    const int full_out = (out_size >= (int)(3 * OUT0)) || out_size <= 0; // defensive

    float *zxf, *zxb, *hs, *fc, *iz;
    cudaGetSymbolAddress((void**)&zxf, g_ZXf);
    cudaGetSymbolAddress((void**)&zxb, g_ZXb);
    cudaGetSymbolAddress((void**)&hs,  g_HS);
    cudaGetSymbolAddress((void**)&fc,  g_FC);
    cudaGetSymbolAddress((void**)&iz,  g_IZ);

    // 1-2: intra input projections (both directions, original time order)
    sgemm128<<<dim3(8, 256), 256>>>(x, Wf, zxf, bf, MROWS, 1024, 512, 0);
    sgemm128<<<dim3(8, 256), 256>>>(x, Wb, zxb, bb, MROWS, 1024, 512, 0);

    // 3: bidirectional recurrence -> g_HS
    recurrence_kernel<<<128, 256>>>(Uf, Ub);

    // 4: fc1
    sgemm128<<<dim3(4, 256), 256>>>(hs, Wfc1, fc, bfc1, MROWS, 512, 512, 0);

    // 5: LN1 + residual -> out (= intra_out, also the inter input)
    ln_kernel<<<256, 256>>>(fc, x, g1, b1, out, 0);

    // 6-7: inter z = intra_out @ Wi + h0 @ Ui + bi
    sgemm128<<<dim3(16, 256), 256>>>(out, Wi, iz, bi, MROWS, 2048, 512, 0);
    sgemm128<<<dim3(16, 256), 256>>>(h0, Ui, iz, nullptr, MROWS, 2048, 512, 1);

    // 8: inter gates -> h_new, c_new (straight into d_out regions)
    if (full_out) {
        inter_gate_kernel<<<16384, 256>>>(iz, c0, h_out, c_out);
        // 9: fc2
        sgemm128<<<dim3(4, 256), 256>>>(h_out, Wfc2, fc, bfc2, MROWS, 512, 512, 0);
    } else {
        // fallback: use scratch for h/c if out buffer only holds main output
        inter_gate_kernel<<<16384, 256>>>(iz, c0, zxf, zxb);
        sgemm128<<<dim3(4, 256), 256>>>(zxf, Wfc2, fc, bfc2, MROWS, 512, 512, 0);
    }

    // 10: LN2, accumulate into out
    ln_kernel<<<256, 256>>>(fc, nullptr, g2, b2, out, 1);
}

// round 3
// speedup vs baseline: 1.7918x; 1.7918x over previous
#include <cuda_runtime.h>
#include <cuda_bf16.h>
#include <cstdint>
#include <math.h>

// Problem constants
#define NSAMP 256            // B*L
#define W_    128
#define C_    512
#define HD_   256
#define MROWS 32768          // B*W
#define OUT0  ((size_t)16777216)   // B*L*W*C

// ---------------- scratch (static device globals; no allocations) ----------------
__device__ float g_ZXf[(size_t)MROWS * 1024];
__device__ float g_ZXb[(size_t)MROWS * 1024];
__device__ float g_HS [(size_t)MROWS * 512];
__device__ float g_FC [(size_t)MROWS * 512];
__device__ float g_IZ [(size_t)MROWS * 2048];
__device__ float g_H  [512 * 256];
__device__ float g_Cs [512 * 256];
__device__ float g_Zb [512 * 1024];
__device__ unsigned long long g_bar = 0ULL;

// bf16 split buffers
__device__ __nv_bfloat16 g_Ahi[(size_t)MROWS * 512];
__device__ __nv_bfloat16 g_Alo[(size_t)MROWS * 512];
__device__ __nv_bfloat16 g_Bthi[(size_t)2048 * 512];
__device__ __nv_bfloat16 g_Btlo[(size_t)2048 * 512];

__device__ __forceinline__ float hsig(float x) {
    return fminf(fmaxf(fmaf(0.2f, x, 0.5f), 0.0f), 1.0f);
}

// ================= low-level helpers (sm_80-baseline ISA only) =================
__device__ __forceinline__ uint32_t smem_u32(const void* p) {
    uint32_t a;
    asm("{ .reg .u64 t; cvta.to.shared.u64 t, %1; cvt.u32.u64 %0, t; }" : "=r"(a) : "l"(p));
    return a;
}
#define CP_ASYNC16(dst, src) \
    asm volatile("cp.async.cg.shared.global [%0], [%1], 16;" :: "r"(dst), "l"(src) : "memory")
#define CP_COMMIT() asm volatile("cp.async.commit_group;" ::: "memory")
#define CP_WAIT1()  asm volatile("cp.async.wait_group 1;" ::: "memory")

__device__ __forceinline__ void ldmx4(uint32_t* r, uint32_t addr) {
    asm volatile("ldmatrix.sync.aligned.m8n8.x4.shared.b16 {%0,%1,%2,%3}, [%4];"
        : "=r"(r[0]), "=r"(r[1]), "=r"(r[2]), "=r"(r[3]) : "r"(addr));
}
__device__ __forceinline__ void mma_bf16(float* d, const uint32_t* a, const uint32_t* b) {
    asm volatile("mma.sync.aligned.m16n8k16.row.col.f32.bf16.bf16.f32 "
        "{%0,%1,%2,%3}, {%4,%5,%6,%7}, {%8,%9}, {%0,%1,%2,%3};"
        : "+f"(d[0]), "+f"(d[1]), "+f"(d[2]), "+f"(d[3])
        : "r"(a[0]), "r"(a[1]), "r"(a[2]), "r"(a[3]), "r"(b[0]), "r"(b[1]));
}

// ================= split-bf16 tensor-core GEMM (mma.sync) =================
// C[M,N] = (Ahi+Alo)[M,K] @ (Bhi+Blo)[N,K]^T (+bias) (+=C)
// Block 128x128, BK=32, 8 warps (2x4), warp tile 64x32. 2-stage cp.async pipeline.
// SMEM tile: 128 rows x 32 bf16, row stride 80B (conflict-free ldmatrix).
#define TILE_B   10240           // 128*80
#define STG_B    40960           // 4 tiles
#define GEMM_SMEM (2 * STG_B)    // 81920

__device__ __forceinline__ void load_chunk(uint32_t stage_base,
    const __nv_bfloat16* __restrict__ Ahi, const __nv_bfloat16* __restrict__ Alo,
    const __nv_bfloat16* __restrict__ Bhi, const __nv_bfloat16* __restrict__ Blo,
    int m0, int n0, int kk, int K, int tid)
{
#pragma unroll
    for (int i = 0; i < 2; i++) {
        const int c = tid + i * 256;       // 0..511
        const int row = c >> 2;
        const int seg = c & 3;
        const uint32_t doff = (uint32_t)(row * 80 + seg * 16);
        const size_t akoff = (size_t)kk + seg * 8;
        CP_ASYNC16(stage_base + 0 * TILE_B + doff, Ahi + (size_t)(m0 + row) * K + akoff);
        CP_ASYNC16(stage_base + 1 * TILE_B + doff, Alo + (size_t)(m0 + row) * K + akoff);
        CP_ASYNC16(stage_base + 2 * TILE_B + doff, Bhi + (size_t)(n0 + row) * K + akoff);
        CP_ASYNC16(stage_base + 3 * TILE_B + doff, Blo + (size_t)(n0 + row) * K + akoff);
    }
}

__global__ __launch_bounds__(256, 2) void tcgemm(
    const __nv_bfloat16* __restrict__ Ahi, const __nv_bfloat16* __restrict__ Alo,
    const __nv_bfloat16* __restrict__ Bhi, const __nv_bfloat16* __restrict__ Blo,
    float* __restrict__ Cmat, const float* __restrict__ bias,
    int M, int N, int K, int accumulate)
{
    extern __shared__ __align__(128) char smem_raw[];
    const uint32_t sb = smem_u32(smem_raw);

    const int tid = threadIdx.x;
    const int lane = tid & 31;
    const int wid = tid >> 5;
    const int wm = wid >> 2;       // 0..1
    const int wn = wid & 3;        // 0..3
    const int m0 = blockIdx.y << 7;
    const int n0 = blockIdx.x << 7;

    // ldmatrix per-lane base offsets (within a tile)
    const uint32_t a_off = (uint32_t)((wm * 64 + (lane & 15)) * 80 + (lane >> 4) * 16);
    const int bsub = lane >> 3;
    const uint32_t b_off = (uint32_t)((wn * 32 + ((bsub >> 1) << 3) + (lane & 7)) * 80 + (bsub & 1) * 16);

    float acc[4][4][4];
#pragma unroll
    for (int mf = 0; mf < 4; mf++)
#pragma unroll
        for (int nf = 0; nf < 4; nf++)
#pragma unroll
            for (int r = 0; r < 4; r++) acc[mf][nf][r] = 0.0f;

    const int NC = K >> 5;

    load_chunk(sb, Ahi, Alo, Bhi, Blo, m0, n0, 0, K, tid);
    CP_COMMIT();
    load_chunk(sb + STG_B, Ahi, Alo, Bhi, Blo, m0, n0, 32, K, tid);
    CP_COMMIT();

    for (int c = 0; c < NC; c++) {
        CP_WAIT1();
        __syncthreads();
        const uint32_t st = sb + (c & 1) * STG_B;

#pragma unroll
        for (int ks = 0; ks < 2; ks++) {
            const uint32_t kb = st + ks * 32;
            uint32_t af[4][4], bh[4][2], bl[4][2], t4[4];
            // B hi/lo fragments (each x4 covers n16 x k16 = two n8 frags)
#pragma unroll
            for (int nh = 0; nh < 2; nh++) {
                ldmx4(t4, kb + 2 * TILE_B + b_off + nh * 1280);
                bh[2 * nh][0] = t4[0]; bh[2 * nh][1] = t4[1];
                bh[2 * nh + 1][0] = t4[2]; bh[2 * nh + 1][1] = t4[3];
                ldmx4(t4, kb + 3 * TILE_B + b_off + nh * 1280);
                bl[2 * nh][0] = t4[0]; bl[2 * nh][1] = t4[1];
                bl[2 * nh + 1][0] = t4[2]; bl[2 * nh + 1][1] = t4[3];
            }
            // A hi fragments; products Ah*Bh and Ah*Bl
#pragma unroll
            for (int mf = 0; mf < 4; mf++) ldmx4(af[mf], kb + 0 * TILE_B + a_off + mf * 1280);
#pragma unroll
            for (int mf = 0; mf < 4; mf++)
#pragma unroll
                for (int nf = 0; nf < 4; nf++) {
                    mma_bf16(acc[mf][nf], af[mf], bh[nf]);
                    mma_bf16(acc[mf][nf], af[mf], bl[nf]);
                }
            // A lo fragments; product Al*Bh
#pragma unroll
            for (int mf = 0; mf < 4; mf++) ldmx4(af[mf], kb + 1 * TILE_B + a_off + mf * 1280);
#pragma unroll
            for (int mf = 0; mf < 4; mf++)
#pragma unroll
                for (int nf = 0; nf < 4; nf++)
                    mma_bf16(acc[mf][nf], af[mf], bh[nf]);
        }

        __syncthreads();
        if (c + 2 < NC)
            load_chunk(sb + (c & 1) * STG_B, Ahi, Alo, Bhi, Blo, m0, n0, (c + 2) << 5, K, tid);
        CP_COMMIT();
    }

    // ---- epilogue: direct global writes ----
    const int qr = lane >> 2;
    const int qc = (lane & 3) << 1;
#pragma unroll
    for (int mf = 0; mf < 4; mf++) {
        const int row = m0 + wm * 64 + mf * 16 + qr;
#pragma unroll
        for (int nf = 0; nf < 4; nf++) {
            const int col = n0 + wn * 32 + nf * 8 + qc;
            float2 v0 = make_float2(acc[mf][nf][0], acc[mf][nf][1]);
            float2 v1 = make_float2(acc[mf][nf][2], acc[mf][nf][3]);
            if (bias) {
                const float2 bv = *(const float2*)(bias + col);
                v0.x += bv.x; v0.y += bv.y; v1.x += bv.x; v1.y += bv.y;
            }
            float* p0 = Cmat + (size_t)row * N + col;
            float* p1 = p0 + 8 * (size_t)N;
            if (accumulate) {
                const float2 o0 = *(const float2*)p0;
                const float2 o1 = *(const float2*)p1;
                v0.x += o0.x; v0.y += o0.y; v1.x += o1.x; v1.y += o1.y;
            }
            *(float2*)p0 = v0;
            *(float2*)p1 = v1;
        }
    }
}

// ================= split kernels =================
__global__ __launch_bounds__(256) void split_kernel(
    const float* __restrict__ in, __nv_bfloat16* __restrict__ hi,
    __nv_bfloat16* __restrict__ lo, int n4)
{
    const int i = blockIdx.x * blockDim.x + threadIdx.x;
    if (i >= n4) return;
    const float4 v = ((const float4*)in)[i];
    float f[4] = {v.x, v.y, v.z, v.w};
    __nv_bfloat16 h[4], l[4];
#pragma unroll
    for (int k = 0; k < 4; k++) {
        h[k] = __float2bfloat16_rn(f[k]);
        l[k] = __float2bfloat16_rn(f[k] - __bfloat162float(h[k]));
    }
    ((__nv_bfloat162*)hi)[2 * i] = __nv_bfloat162(h[0], h[1]);
    ((__nv_bfloat162*)hi)[2 * i + 1] = __nv_bfloat162(h[2], h[3]);
    ((__nv_bfloat162*)lo)[2 * i] = __nv_bfloat162(l[0], l[1]);
    ((__nv_bfloat162*)lo)[2 * i + 1] = __nv_bfloat162(l[2], l[3]);
}

// transpose-split: W [K,N] fp32 -> Bt_hi/Bt_lo [N,K] bf16
__global__ void splitT_kernel(const float* __restrict__ Wm,
                              __nv_bfloat16* __restrict__ hi, __nv_bfloat16* __restrict__ lo,
                              int K, int N)
{
    __shared__ float t[32][33];
    const int kb = blockIdx.y * 32, nb = blockIdx.x * 32;
    const int tx = threadIdx.x, ty = threadIdx.y;
    for (int r = ty; r < 32; r += 8)
        t[r][tx] = Wm[(size_t)(kb + r) * N + nb + tx];
    __syncthreads();
    for (int r = ty; r < 32; r += 8) {
        const float v = t[tx][r];
        const __nv_bfloat16 h = __float2bfloat16_rn(v);
        const __nv_bfloat16 l = __float2bfloat16_rn(v - __bfloat162float(h));
        hi[(size_t)(nb + r) * K + kb + tx] = h;
        lo[(size_t)(nb + r) * K + kb + tx] = l;
    }
}

// ---------------- software grid barrier ----------------
__device__ __forceinline__ void grid_barrier(unsigned long long nb) {
    __threadfence();
    __syncthreads();
    if (threadIdx.x == 0) {
        unsigned long long t = atomicAdd(&g_bar, 1ULL) + 1ULL;
        unsigned long long target = ((t + nb - 1ULL) / nb) * nb;
        volatile unsigned long long* p = &g_bar;
        while (*p < target) { __nanosleep(64); }
        __threadfence();
    }
    __syncthreads();
}

// ---------------- persistent bidirectional LSTM recurrence ----------------
__global__ __launch_bounds__(256) void recurrence_kernel(
    const float* __restrict__ Uf, const float* __restrict__ Ub)
{
    __shared__ float As[16][64];
    __shared__ float Bs[16][64];

    const int tid = threadIdx.x;
    const int blk = blockIdx.x;
    const int tile_m = blk >> 4;
    const int tile_n = blk & 15;
    const float* U = (tile_m < 4) ? Uf : Ub;
    const int row0 = tile_m << 6;
    const int col0 = tile_n << 6;
    const int tx = tid & 15, ty = tid >> 4;

    {
        const int base = blk * 1024;
        for (int i = tid; i < 1024; i += 256) { g_H[base + i] = 0.0f; g_Cs[base + i] = 0.0f; }
    }

    const int ar = tid >> 2;
    const int ac = (tid & 3) << 2;
    const int br = tid >> 4;
    const int bc = (tid & 15) << 2;

    const int e4 = blk * 256 + tid;
    const int ur = e4 >> 6;
    const int uj = (e4 & 63) << 2;
    const int un = ur & 255;
    const bool ubwd = (ur >= 256);
    const float* uzx = ubwd ? g_ZXb : g_ZXf;

    grid_barrier(128ULL);

    for (int t = 0; t < 128; t++) {
        float acc[4][4];
#pragma unroll
        for (int i = 0; i < 4; i++)
#pragma unroll
            for (int j = 0; j < 4; j++) acc[i][j] = 0.0f;

        for (int kk = 0; kk < 256; kk += 16) {
            float4 av = *(const float4*)(g_H + (size_t)(row0 + ar) * 256 + kk + ac);
            As[ac + 0][ar] = av.x; As[ac + 1][ar] = av.y; As[ac + 2][ar] = av.z; As[ac + 3][ar] = av.w;
            *(float4*)&Bs[br][bc] = *(const float4*)(U + (size_t)(kk + br) * 1024 + col0 + bc);
            __syncthreads();
#pragma unroll
            for (int k = 0; k < 16; k++) {
                float a[4], b[4];
                *(float4*)a = *(const float4*)&As[k][(ty << 2)];
                *(float4*)b = *(const float4*)&Bs[k][(tx << 2)];
#pragma unroll
                for (int i = 0; i < 4; i++)
#pragma unroll
                    for (int j = 0; j < 4; j++) acc[i][j] = fmaf(a[i], b[j], acc[i][j]);
            }
            __syncthreads();
        }
#pragma unroll
        for (int i = 0; i < 4; i++) {
            float4 v = make_float4(acc[i][0], acc[i][1], acc[i][2], acc[i][3]);
            *(float4*)(g_Zb + (size_t)(row0 + (ty << 2) + i) * 1024 + col0 + (tx << 2)) = v;
        }

        grid_barrier(128ULL);

        {
            const int w = ubwd ? (127 - t) : t;
            const float* zxp = uzx + ((size_t)un * 128 + w) * 1024;
            const float* zp  = g_Zb + (size_t)ur * 1024;

            float4 zi = *(const float4*)(zp + uj);
            float4 zf = *(const float4*)(zp + 256 + uj);
            float4 zg = *(const float4*)(zp + 512 + uj);
            float4 zo = *(const float4*)(zp + 768 + uj);
            float4 xi = *(const float4*)(zxp + uj);
            float4 xf = *(const float4*)(zxp + 256 + uj);
            float4 xg = *(const float4*)(zxp + 512 + uj);
            float4 xo = *(const float4*)(zxp + 768 + uj);
            float4 c  = *(const float4*)(g_Cs + (size_t)ur * 256 + uj);

            float ci[4] = {c.x, c.y, c.z, c.w};
            float zi_[4] = {zi.x + xi.x, zi.y + xi.y, zi.z + xi.z, zi.w + xi.w};
            float zf_[4] = {zf.x + xf.x, zf.y + xf.y, zf.z + xf.z, zf.w + xf.w};
            float zg_[4] = {zg.x + xg.x, zg.y + xg.y, zg.z + xg.z, zg.w + xg.w};
            float zo_[4] = {zo.x + xo.x, zo.y + xo.y, zo.z + xo.z, zo.w + xo.w};
            float hv[4], cv[4];
#pragma unroll
            for (int l = 0; l < 4; l++) {
                float cn = hsig(zf_[l]) * ci[l] + hsig(zi_[l]) * tanhf(zg_[l]);
                cv[l] = cn;
                hv[l] = hsig(zo_[l]) * tanhf(cn);
            }
            *(float4*)(g_Cs + (size_t)ur * 256 + uj) = make_float4(cv[0], cv[1], cv[2], cv[3]);
            *(float4*)(g_H  + (size_t)ur * 256 + uj) = make_float4(hv[0], hv[1], hv[2], hv[3]);
            *(float4*)(g_HS + ((size_t)un * 128 + w) * 512 + (ubwd ? 256 : 0) + uj) =
                make_float4(hv[0], hv[1], hv[2], hv[3]);
        }

        grid_barrier(128ULL);
    }
}

// ---------------- LayerNorm over (W,C)=65536 ----------------
__global__ __launch_bounds__(256) void ln_kernel(
    const float* __restrict__ pre, const float* __restrict__ xres,
    const float* __restrict__ gamma, const float* __restrict__ beta,
    float* __restrict__ out, int mode)
{
    __shared__ float red[256];
    const int tid = threadIdx.x;
    const size_t base = (size_t)blockIdx.x * 65536;

    float s = 0.0f, ss = 0.0f;
    for (int i = tid * 4; i < 65536; i += 1024) {
        float4 v = *(const float4*)(pre + base + i);
        s  += v.x + v.y + v.z + v.w;
        ss += v.x * v.x + v.y * v.y + v.z * v.z + v.w * v.w;
    }
    red[tid] = s; __syncthreads();
    for (int off = 128; off; off >>= 1) { if (tid < off) red[tid] += red[tid + off]; __syncthreads(); }
    const float mean = red[0] * (1.0f / 65536.0f);
    __syncthreads();
    red[tid] = ss; __syncthreads();
    for (int off = 128; off; off >>= 1) { if (tid < off) red[tid] += red[tid + off]; __syncthreads(); }
    const float var = red[0] * (1.0f / 65536.0f) - mean * mean;
    const float rstd = rsqrtf(var + 1e-3f);

    for (int i = tid * 4; i < 65536; i += 1024) {
        float4 v = *(const float4*)(pre + base + i);
        float4 g = *(const float4*)(gamma + i);
        float4 bb = *(const float4*)(beta + i);
        float4 r;
        r.x = (v.x - mean) * rstd * g.x + bb.x;
        r.y = (v.y - mean) * rstd * g.y + bb.y;
        r.z = (v.z - mean) * rstd * g.z + bb.z;
        r.w = (v.w - mean) * rstd * g.w + bb.w;
        if (mode == 0) {
            float4 xr = *(const float4*)(xres + base + i);
            r.x += xr.x; r.y += xr.y; r.z += xr.z; r.w += xr.w;
        } else {
            float4 o = *(const float4*)(out + base + i);
            r.x += o.x; r.y += o.y; r.z += o.z; r.w += o.w;
        }
        *(float4*)(out + base + i) = r;
    }
}

// ---------------- inter LSTM single-step gate update ----------------
__global__ __launch_bounds__(256) void inter_gate_kernel(
    const float* __restrict__ Z, const float* __restrict__ c0,
    float* __restrict__ h_new, float* __restrict__ c_new)
{
    const int q = blockIdx.x * blockDim.x + threadIdx.x;
    const int m = q >> 7;
    const int j = (q & 127) << 2;
    const float* zp = Z + (size_t)m * 2048;
    float4 zi = *(const float4*)(zp + j);
    float4 zf = *(const float4*)(zp + 512 + j);
    float4 zg = *(const float4*)(zp + 1024 + j);
    float4 zo = *(const float4*)(zp + 1536 + j);
    float4 c  = *(const float4*)(c0 + (size_t)m * 512 + j);

    float zi_[4] = {zi.x, zi.y, zi.z, zi.w};
    float zf_[4] = {zf.x, zf.y, zf.z, zf.w};
    float zg_[4] = {zg.x, zg.y, zg.z, zg.w};
    float zo_[4] = {zo.x, zo.y, zo.z, zo.w};
    float ci[4]  = {c.x, c.y, c.z, c.w};
    float cv[4], hv[4];
#pragma unroll
    for (int l = 0; l < 4; l++) {
        float cn = hsig(zf_[l]) * ci[l] + hsig(zi_[l]) * tanhf(zg_[l]);
        cv[l] = cn;
        hv[l] = hsig(zo_[l]) * tanhf(cn);
    }
    *(float4*)(c_new + (size_t)m * 512 + j) = make_float4(cv[0], cv[1], cv[2], cv[3]);
    *(float4*)(h_new + (size_t)m * 512 + j) = make_float4(hv[0], hv[1], hv[2], hv[3]);
}

// ---------------- launch ----------------
extern "C" void kernel_launch(void* const* d_in, const int* in_sizes, int n_in,
                              void* d_out, int out_size)
{
    const float* x    = (const float*)d_in[0];
    const float* h0   = (const float*)d_in[1];
    const float* c0   = (const float*)d_in[2];
    const float* Wf   = (const float*)d_in[3];
    const float* Uf   = (const float*)d_in[4];
    const float* bf   = (const float*)d_in[5];
    const float* Wb   = (const float*)d_in[6];
    const float* Ub   = (const float*)d_in[7];
    const float* bb   = (const float*)d_in[8];
    const float* Wfc1 = (const float*)d_in[9];
    const float* bfc1 = (const float*)d_in[10];
    const float* g1   = (const float*)d_in[11];
    const float* b1   = (const float*)d_in[12];
    const float* Wi   = (const float*)d_in[13];
    const float* Ui   = (const float*)d_in[14];
    const float* bi   = (const float*)d_in[15];
    const float* Wfc2 = (const float*)d_in[16];
    const float* bfc2 = (const float*)d_in[17];
    const float* g2   = (const float*)d_in[18];
    const float* b2   = (const float*)d_in[19];

    float* out = (float*)d_out;
    float* h_out = out + OUT0;
    float* c_out = out + 2 * OUT0;
    const int full_out = (out_size >= (int)(3 * OUT0)) || out_size <= 0;

    float *zxf, *zxb, *hs, *fc, *iz;
    __nv_bfloat16 *ahi, *alo, *bthi, *btlo;
    cudaGetSymbolAddress((void**)&zxf, g_ZXf);
    cudaGetSymbolAddress((void**)&zxb, g_ZXb);
    cudaGetSymbolAddress((void**)&hs,  g_HS);
    cudaGetSymbolAddress((void**)&fc,  g_FC);
    cudaGetSymbolAddress((void**)&iz,  g_IZ);
    cudaGetSymbolAddress((void**)&ahi, g_Ahi);
    cudaGetSymbolAddress((void**)&alo, g_Alo);
    cudaGetSymbolAddress((void**)&bthi, g_Bthi);
    cudaGetSymbolAddress((void**)&btlo, g_Btlo);

    cudaFuncSetAttribute(tcgemm, cudaFuncAttributeMaxDynamicSharedMemorySize, GEMM_SMEM);

    const int n4A = MROWS * 512 / 4;   // 4194304

    // ---- intra input projections (A = x shared by both) ----
    split_kernel<<<n4A / 256, 256>>>(x, ahi, alo, n4A);
    splitT_kernel<<<dim3(1024 / 32, 512 / 32), dim3(32, 8)>>>(Wf, bthi, btlo, 512, 1024);
    tcgemm<<<dim3(8, 256), 256, GEMM_SMEM>>>(ahi, alo, bthi, btlo, zxf, bf, MROWS, 1024, 512, 0);
    splitT_kernel<<<dim3(1024 / 32, 512 / 32), dim3(32, 8)>>>(Wb, bthi, btlo, 512, 1024);
    tcgemm<<<dim3(8, 256), 256, GEMM_SMEM>>>(ahi, alo, bthi, btlo, zxb, bb, MROWS, 1024, 512, 0);

    // ---- bidirectional recurrence ----
    recurrence_kernel<<<128, 256>>>(Uf, Ub);

    // ---- fc1 ----
    split_kernel<<<n4A / 256, 256>>>(hs, ahi, alo, n4A);
    splitT_kernel<<<dim3(512 / 32, 512 / 32), dim3(32, 8)>>>(Wfc1, bthi, btlo, 512, 512);
    tcgemm<<<dim3(4, 256), 256, GEMM_SMEM>>>(ahi, alo, bthi, btlo, fc, bfc1, MROWS, 512, 512, 0);

    // ---- LN1 + residual -> out (= intra_out) ----
    ln_kernel<<<256, 256>>>(fc, x, g1, b1, out, 0);

    // ---- inter z = intra_out @ Wi + h0 @ Ui + bi ----
    split_kernel<<<n4A / 256, 256>>>(out, ahi, alo, n4A);
    splitT_kernel<<<dim3(2048 / 32, 512 / 32), dim3(32, 8)>>>(Wi, bthi, btlo, 512, 2048);
    tcgemm<<<dim3(16, 256), 256, GEMM_SMEM>>>(ahi, alo, bthi, btlo, iz, bi, MROWS, 2048, 512, 0);
    split_kernel<<<n4A / 256, 256>>>(h0, ahi, alo, n4A);
    splitT_kernel<<<dim3(2048 / 32, 512 / 32), dim3(32, 8)>>>(Ui, bthi, btlo, 512, 2048);
    tcgemm<<<dim3(16, 256), 256, GEMM_SMEM>>>(ahi, alo, bthi, btlo, iz, nullptr, MROWS, 2048, 512, 1);

    // ---- inter gates + fc2 ----
    float* hptr = full_out ? h_out : zxf;
    float* cptr = full_out ? c_out : zxb;
    inter_gate_kernel<<<16384, 256>>>(iz, c0, hptr, cptr);
    split_kernel<<<n4A / 256, 256>>>(hptr, ahi, alo, n4A);
    splitT_kernel<<<dim3(512 / 32, 512 / 32), dim3(32, 8)>>>(Wfc2, bthi, btlo, 512, 512);
    tcgemm<<<dim3(4, 256), 256, GEMM_SMEM>>>(ahi, alo, bthi, btlo, fc, bfc2, MROWS, 512, 512, 0);

    // ---- LN2 accumulate into out ----
    ln_kernel<<<256, 256>>>(fc, nullptr, g2, b2, out, 1);
}

// round 4
// speedup vs baseline: 2.6122x; 1.4578x over previous
#include <cuda_runtime.h>
#include <cuda_bf16.h>
#include <cstdint>
#include <math.h>

// Problem constants
#define NSAMP 256            // B*L
#define W_    128
#define C_    512
#define HD_   256
#define MROWS 32768          // B*W
#define OUT0  ((size_t)16777216)   // B*L*W*C

// ---------------- scratch (static device globals; no allocations) ----------------
__device__ float g_ZXf[(size_t)MROWS * 1024];
__device__ float g_ZXb[(size_t)MROWS * 1024];
__device__ float g_FC [(size_t)MROWS * 512];
__device__ float g_IZ [(size_t)MROWS * 2048];
__device__ unsigned long long g_bar = 0ULL;

// bf16 split buffers
__device__ __nv_bfloat16 g_Ahi[(size_t)MROWS * 512];
__device__ __nv_bfloat16 g_Alo[(size_t)MROWS * 512];
__device__ __nv_bfloat16 g_Bthi[(size_t)2048 * 512];
__device__ __nv_bfloat16 g_Btlo[(size_t)2048 * 512];
// recurrence state / weights / outputs (bf16 split)
__device__ __nv_bfloat16 g_Hhi[2][512 * 256];
__device__ __nv_bfloat16 g_Hlo[2][512 * 256];
__device__ __nv_bfloat16 g_Uthi[(size_t)2048 * 256];
__device__ __nv_bfloat16 g_Utlo[(size_t)2048 * 256];
__device__ __nv_bfloat16 g_HShi[(size_t)MROWS * 512];
__device__ __nv_bfloat16 g_HSlo[(size_t)MROWS * 512];

__device__ __forceinline__ float hsig(float x) {
    return fminf(fmaxf(fmaf(0.2f, x, 0.5f), 0.0f), 1.0f);
}

// ================= low-level helpers (sm_80-baseline ISA only) =================
__device__ __forceinline__ uint32_t smem_u32(const void* p) {
    uint32_t a;
    asm("{ .reg .u64 t; cvta.to.shared.u64 t, %1; cvt.u32.u64 %0, t; }" : "=r"(a) : "l"(p));
    return a;
}
#define CP_ASYNC16(dst, src) \
    asm volatile("cp.async.cg.shared.global [%0], [%1], 16;" :: "r"(dst), "l"(src) : "memory")
#define CP_COMMIT() asm volatile("cp.async.commit_group;" ::: "memory")
#define CP_WAIT1()  asm volatile("cp.async.wait_group 1;" ::: "memory")
#define CP_WAIT0()  asm volatile("cp.async.wait_group 0;" ::: "memory")

__device__ __forceinline__ void ldmx4(uint32_t* r, uint32_t addr) {
    asm volatile("ldmatrix.sync.aligned.m8n8.x4.shared.b16 {%0,%1,%2,%3}, [%4];"
        : "=r"(r[0]), "=r"(r[1]), "=r"(r[2]), "=r"(r[3]) : "r"(addr));
}
__device__ __forceinline__ void mma_bf16(float* d, const uint32_t* a, const uint32_t* b) {
    asm volatile("mma.sync.aligned.m16n8k16.row.col.f32.bf16.bf16.f32 "
        "{%0,%1,%2,%3}, {%4,%5,%6,%7}, {%8,%9}, {%0,%1,%2,%3};"
        : "+f"(d[0]), "+f"(d[1]), "+f"(d[2]), "+f"(d[3])
        : "r"(a[0]), "r"(a[1]), "r"(a[2]), "r"(a[3]), "r"(b[0]), "r"(b[1]));
}

// ================= split-bf16 tensor-core GEMM (mma.sync) =================
// C[M,N] = (Ahi+Alo)[M,K] @ (Bhi+Blo)[N,K]^T (+bias) (+=C)
#define TILE_B   10240           // 128*80
#define STG_B    40960           // 4 tiles
#define GEMM_SMEM (2 * STG_B)    // 81920

__device__ __forceinline__ void load_chunk(uint32_t stage_base,
    const __nv_bfloat16* __restrict__ Ahi, const __nv_bfloat16* __restrict__ Alo,
    const __nv_bfloat16* __restrict__ Bhi, const __nv_bfloat16* __restrict__ Blo,
    int m0, int n0, int kk, int K, int tid)
{
#pragma unroll
    for (int i = 0; i < 2; i++) {
        const int c = tid + i * 256;
        const int row = c >> 2;
        const int seg = c & 3;
        const uint32_t doff = (uint32_t)(row * 80 + seg * 16);
        const size_t akoff = (size_t)kk + seg * 8;
        CP_ASYNC16(stage_base + 0 * TILE_B + doff, Ahi + (size_t)(m0 + row) * K + akoff);
        CP_ASYNC16(stage_base + 1 * TILE_B + doff, Alo + (size_t)(m0 + row) * K + akoff);
        CP_ASYNC16(stage_base + 2 * TILE_B + doff, Bhi + (size_t)(n0 + row) * K + akoff);
        CP_ASYNC16(stage_base + 3 * TILE_B + doff, Blo + (size_t)(n0 + row) * K + akoff);
    }
}

__global__ __launch_bounds__(256, 2) void tcgemm(
    const __nv_bfloat16* __restrict__ Ahi, const __nv_bfloat16* __restrict__ Alo,
    const __nv_bfloat16* __restrict__ Bhi, const __nv_bfloat16* __restrict__ Blo,
    float* __restrict__ Cmat, const float* __restrict__ bias,
    int M, int N, int K, int accumulate)
{
    extern __shared__ __align__(128) char smem_raw[];
    const uint32_t sb = smem_u32(smem_raw);

    const int tid = threadIdx.x;
    const int lane = tid & 31;
    const int wid = tid >> 5;
    const int wm = wid >> 2;
    const int wn = wid & 3;
    const int m0 = blockIdx.y << 7;
    const int n0 = blockIdx.x << 7;

    const uint32_t a_off = (uint32_t)((wm * 64 + (lane & 15)) * 80 + (lane >> 4) * 16);
    const int bsub = lane >> 3;
    const uint32_t b_off = (uint32_t)((wn * 32 + ((bsub >> 1) << 3) + (lane & 7)) * 80 + (bsub & 1) * 16);

    float acc[4][4][4];
#pragma unroll
    for (int mf = 0; mf < 4; mf++)
#pragma unroll
        for (int nf = 0; nf < 4; nf++)
#pragma unroll
            for (int r = 0; r < 4; r++) acc[mf][nf][r] = 0.0f;

    const int NC = K >> 5;

    load_chunk(sb, Ahi, Alo, Bhi, Blo, m0, n0, 0, K, tid);
    CP_COMMIT();
    load_chunk(sb + STG_B, Ahi, Alo, Bhi, Blo, m0, n0, 32, K, tid);
    CP_COMMIT();

    for (int c = 0; c < NC; c++) {
        CP_WAIT1();
        __syncthreads();
        const uint32_t st = sb + (c & 1) * STG_B;

#pragma unroll
        for (int ks = 0; ks < 2; ks++) {
            const uint32_t kb = st + ks * 32;
            uint32_t af[4][4], bh[4][2], bl[4][2], t4[4];
#pragma unroll
            for (int nh = 0; nh < 2; nh++) {
                ldmx4(t4, kb + 2 * TILE_B + b_off + nh * 1280);
                bh[2 * nh][0] = t4[0]; bh[2 * nh][1] = t4[1];
                bh[2 * nh + 1][0] = t4[2]; bh[2 * nh + 1][1] = t4[3];
                ldmx4(t4, kb + 3 * TILE_B + b_off + nh * 1280);
                bl[2 * nh][0] = t4[0]; bl[2 * nh][1] = t4[1];
                bl[2 * nh + 1][0] = t4[2]; bl[2 * nh + 1][1] = t4[3];
            }
#pragma unroll
            for (int mf = 0; mf < 4; mf++) ldmx4(af[mf], kb + 0 * TILE_B + a_off + mf * 1280);
#pragma unroll
            for (int mf = 0; mf < 4; mf++)
#pragma unroll
                for (int nf = 0; nf < 4; nf++) {
                    mma_bf16(acc[mf][nf], af[mf], bh[nf]);
                    mma_bf16(acc[mf][nf], af[mf], bl[nf]);
                }
#pragma unroll
            for (int mf = 0; mf < 4; mf++) ldmx4(af[mf], kb + 1 * TILE_B + a_off + mf * 1280);
#pragma unroll
            for (int mf = 0; mf < 4; mf++)
#pragma unroll
                for (int nf = 0; nf < 4; nf++)
                    mma_bf16(acc[mf][nf], af[mf], bh[nf]);
        }

        __syncthreads();
        if (c + 2 < NC)
            load_chunk(sb + (c & 1) * STG_B, Ahi, Alo, Bhi, Blo, m0, n0, (c + 2) << 5, K, tid);
        CP_COMMIT();
    }

    const int qr = lane >> 2;
    const int qc = (lane & 3) << 1;
#pragma unroll
    for (int mf = 0; mf < 4; mf++) {
        const int row = m0 + wm * 64 + mf * 16 + qr;
#pragma unroll
        for (int nf = 0; nf < 4; nf++) {
            const int col = n0 + wn * 32 + nf * 8 + qc;
            float2 v0 = make_float2(acc[mf][nf][0], acc[mf][nf][1]);
            float2 v1 = make_float2(acc[mf][nf][2], acc[mf][nf][3]);
            if (bias) {
                const float2 bv = *(const float2*)(bias + col);
                v0.x += bv.x; v0.y += bv.y; v1.x += bv.x; v1.y += bv.y;
            }
            float* p0 = Cmat + (size_t)row * N + col;
            float* p1 = p0 + 8 * (size_t)N;
            if (accumulate) {
                const float2 o0 = *(const float2*)p0;
                const float2 o1 = *(const float2*)p1;
                v0.x += o0.x; v0.y += o0.y; v1.x += o1.x; v1.y += o1.y;
            }
            *(float2*)p0 = v0;
            *(float2*)p1 = v1;
        }
    }
}

// ================= split kernels =================
__global__ __launch_bounds__(256) void split_kernel(
    const float* __restrict__ in, __nv_bfloat16* __restrict__ hi,
    __nv_bfloat16* __restrict__ lo, int n4)
{
    const int i = blockIdx.x * blockDim.x + threadIdx.x;
    if (i >= n4) return;
    const float4 v = ((const float4*)in)[i];
    float f[4] = {v.x, v.y, v.z, v.w};
    __nv_bfloat16 h[4], l[4];
#pragma unroll
    for (int k = 0; k < 4; k++) {
        h[k] = __float2bfloat16_rn(f[k]);
        l[k] = __float2bfloat16_rn(f[k] - __bfloat162float(h[k]));
    }
    ((__nv_bfloat162*)hi)[2 * i] = __nv_bfloat162(h[0], h[1]);
    ((__nv_bfloat162*)hi)[2 * i + 1] = __nv_bfloat162(h[2], h[3]);
    ((__nv_bfloat162*)lo)[2 * i] = __nv_bfloat162(l[0], l[1]);
    ((__nv_bfloat162*)lo)[2 * i + 1] = __nv_bfloat162(l[2], l[3]);
}

// transpose-split: W [K,N] fp32 -> hi/lo [N,K] bf16
__global__ void splitT_kernel(const float* __restrict__ Wm,
                              __nv_bfloat16* __restrict__ hi, __nv_bfloat16* __restrict__ lo,
                              int K, int N)
{
    __shared__ float t[32][33];
    const int kb = blockIdx.y * 32, nb = blockIdx.x * 32;
    const int tx = threadIdx.x, ty = threadIdx.y;
    for (int r = ty; r < 32; r += 8)
        t[r][tx] = Wm[(size_t)(kb + r) * N + nb + tx];
    __syncthreads();
    for (int r = ty; r < 32; r += 8) {
        const float v = t[tx][r];
        const __nv_bfloat16 h = __float2bfloat16_rn(v);
        const __nv_bfloat16 l = __float2bfloat16_rn(v - __bfloat162float(h));
        hi[(size_t)(nb + r) * K + kb + tx] = h;
        lo[(size_t)(nb + r) * K + kb + tx] = l;
    }
}

// ---------------- software grid barrier ----------------
__device__ __forceinline__ void grid_barrier(unsigned long long nb) {
    __threadfence();
    __syncthreads();
    if (threadIdx.x == 0) {
        unsigned long long t = atomicAdd(&g_bar, 1ULL) + 1ULL;
        unsigned long long target = ((t + nb - 1ULL) / nb) * nb;
        volatile unsigned long long* p = &g_bar;
        while (*p < target) { __nanosleep(64); }
        __threadfence();
    }
    __syncthreads();
}

// ---------------- persistent bidirectional LSTM recurrence (HMMA, 1 barrier/step) ----------------
// 128 CTAs x 256 threads. CTA (tile_m, tile_n): rows row0..row0+63 of the 512-row state,
// hidden cols j0..j0+15 for all 4 gates. B = U^T slice resident in SMEM (bf16 hi/lo).
// H double-buffered in global (bf16 hi/lo); c state in registers.
#define RA_STR   528
#define ROFF_ALO 33792
#define ROFF_BHI 67584
#define ROFF_BLO 101376
#define ROFF_STG 135168
#define RSMEM    152576          // + 64*68*4

__global__ __launch_bounds__(256) void recurrence2(
    const __nv_bfloat16* __restrict__ Uthi, const __nv_bfloat16* __restrict__ Utlo)
{
    extern __shared__ __align__(128) char rsm[];
    const uint32_t sb = smem_u32(rsm);
    const int tid = threadIdx.x, lane = tid & 31, wid = tid >> 5;
    const int blk = blockIdx.x;
    const int tile_m = blk >> 4;         // 0..7
    const int tile_n = blk & 15;         // 0..15
    const int row0 = tile_m << 6;
    const int dir = (tile_m >= 4) ? 1 : 0;
    const int j0 = tile_n << 4;
    const int wm = wid & 3, wn = wid >> 2;   // warp tile: m16 x n32

    // ---- load B (U^T slice) to SMEM once: 64 rows (= gate*16+c) x 256 k ----
    for (int i = tid; i < 2048; i += 256) {
        const int r = i >> 5, seg = i & 31;
        const int g = r >> 4, c = r & 15;
        const size_t gr = ((size_t)(dir * 1024 + g * 256 + j0 + c)) * 256 + seg * 8;
        *(uint4*)(rsm + ROFF_BHI + r * RA_STR + seg * 16) = *(const uint4*)(Uthi + gr);
        *(uint4*)(rsm + ROFF_BLO + r * RA_STR + seg * 16) = *(const uint4*)(Utlo + gr);
    }

    // ---- zero initial H buffer 0 (one N-tile column of CTAs does it) ----
    if (tile_n == 0) {
        uint32_t* h0 = (uint32_t*)&g_Hhi[0][row0 * 256];
        uint32_t* l0 = (uint32_t*)&g_Hlo[0][row0 * 256];
        for (int i = tid; i < 8192; i += 256) { h0[i] = 0u; l0[i] = 0u; }
    }

    const uint32_t a_off = (uint32_t)((wm * 16 + (lane & 15)) * RA_STR + (lane >> 4) * 16);
    const int bsub = lane >> 3;
    const uint32_t b_off = (uint32_t)((wn * 32 + ((bsub >> 1) << 3) + (lane & 7)) * RA_STR + (bsub & 1) * 16);

    const int r_up = tid >> 2;          // 0..63
    const int c_up = (tid & 3) << 2;    // 0,4,8,12
    const int Rr = row0 + r_up;
    const int n_up = Rr & 255;
    const float* zxbase = dir ? g_ZXb : g_ZXf;
    float* stg = (float*)(rsm + ROFF_STG);
    float creg[4] = {0.0f, 0.0f, 0.0f, 0.0f};

    grid_barrier(128ULL);

    for (int t = 0; t < 128; t++) {
        const int pb = t & 1;
        // ---- load A = H rows row0..+63 (bf16 hi/lo) via cp.async.cg (L2-coherent) ----
        {
            const __nv_bfloat16* hh = g_Hhi[pb];
            const __nv_bfloat16* hl = g_Hlo[pb];
#pragma unroll
            for (int ii = 0; ii < 8; ii++) {
                const int i = tid + ii * 256;
                const int r = i >> 5, seg = i & 31;
                const size_t go = (size_t)(row0 + r) * 256 + seg * 8;
                CP_ASYNC16(sb + r * RA_STR + seg * 16, hh + go);
                CP_ASYNC16(sb + ROFF_ALO + r * RA_STR + seg * 16, hl + go);
            }
        }
        CP_COMMIT();
        CP_WAIT0();
        __syncthreads();

        // ---- MMA: z(64x64) = H(64x256) @ Uslice^T, 3-product split ----
        float acc[4][4];
#pragma unroll
        for (int nf = 0; nf < 4; nf++)
#pragma unroll
            for (int r = 0; r < 4; r++) acc[nf][r] = 0.0f;

        for (int ks = 0; ks < 16; ks++) {
            const uint32_t kb = ks * 32;
            uint32_t ah[4], al[4], bh[4][2], bl[4][2], t4[4];
            ldmx4(ah, sb + a_off + kb);
            ldmx4(al, sb + ROFF_ALO + a_off + kb);
#pragma unroll
            for (int nh = 0; nh < 2; nh++) {
                ldmx4(t4, sb + ROFF_BHI + b_off + kb + nh * 16 * RA_STR);
                bh[2 * nh][0] = t4[0]; bh[2 * nh][1] = t4[1];
                bh[2 * nh + 1][0] = t4[2]; bh[2 * nh + 1][1] = t4[3];
                ldmx4(t4, sb + ROFF_BLO + b_off + kb + nh * 16 * RA_STR);
                bl[2 * nh][0] = t4[0]; bl[2 * nh][1] = t4[1];
                bl[2 * nh + 1][0] = t4[2]; bl[2 * nh + 1][1] = t4[3];
            }
#pragma unroll
            for (int nf = 0; nf < 4; nf++) {
                mma_bf16(acc[nf], ah, bh[nf]);
                mma_bf16(acc[nf], ah, bl[nf]);
                mma_bf16(acc[nf], al, bh[nf]);
            }
        }

        // ---- epilogue to SMEM staging ----
        {
            const int qr = lane >> 2, qc = (lane & 3) << 1;
#pragma unroll
            for (int nf = 0; nf < 4; nf++) {
                const int col = wn * 32 + nf * 8 + qc;
                stg[(wm * 16 + qr) * 68 + col]     = acc[nf][0];
                stg[(wm * 16 + qr) * 68 + col + 1] = acc[nf][1];
                stg[(wm * 16 + qr + 8) * 68 + col]     = acc[nf][2];
                stg[(wm * 16 + qr + 8) * 68 + col + 1] = acc[nf][3];
            }
        }
        __syncthreads();

        // ---- gate update for (64 rows x 16 hidden) owned slice ----
        {
            const int w = dir ? (127 - t) : t;
            const float* zx = zxbase + ((size_t)n_up * 128 + w) * 1024 + j0 + c_up;
            __nv_bfloat16* dhh = &g_Hhi[pb ^ 1][(size_t)Rr * 256 + j0 + c_up];
            __nv_bfloat16* dhl = &g_Hlo[pb ^ 1][(size_t)Rr * 256 + j0 + c_up];
            const size_t hsoff = ((size_t)n_up * 128 + w) * 512 + dir * 256 + j0 + c_up;
            float hv[4];
#pragma unroll
            for (int l = 0; l < 4; l++) {
                const float* sr = &stg[r_up * 68 + c_up + l];
                const float zi = sr[0]  + zx[l];
                const float zf = sr[16] + zx[256 + l];
                const float zg = sr[32] + zx[512 + l];
                const float zo = sr[48] + zx[768 + l];
                const float cn = hsig(zf) * creg[l] + hsig(zi) * tanhf(zg);
                creg[l] = cn;
                hv[l] = hsig(zo) * tanhf(cn);
            }
            __nv_bfloat16 hh[4], hl[4];
#pragma unroll
            for (int l = 0; l < 4; l++) {
                hh[l] = __float2bfloat16_rn(hv[l]);
                hl[l] = __float2bfloat16_rn(hv[l] - __bfloat162float(hh[l]));
            }
            *(__nv_bfloat162*)(dhh)     = __nv_bfloat162(hh[0], hh[1]);
            *(__nv_bfloat162*)(dhh + 2) = __nv_bfloat162(hh[2], hh[3]);
            *(__nv_bfloat162*)(dhl)     = __nv_bfloat162(hl[0], hl[1]);
            *(__nv_bfloat162*)(dhl + 2) = __nv_bfloat162(hl[2], hl[3]);
            *(__nv_bfloat162*)(g_HShi + hsoff)     = __nv_bfloat162(hh[0], hh[1]);
            *(__nv_bfloat162*)(g_HShi + hsoff + 2) = __nv_bfloat162(hh[2], hh[3]);
            *(__nv_bfloat162*)(g_HSlo + hsoff)     = __nv_bfloat162(hl[0], hl[1]);
            *(__nv_bfloat162*)(g_HSlo + hsoff + 2) = __nv_bfloat162(hl[2], hl[3]);
        }

        grid_barrier(128ULL);
    }
}

// ---------------- LayerNorm over (W,C)=65536, optional fused bf16 split of result ----------------
__global__ __launch_bounds__(256) void ln_kernel(
    const float* __restrict__ pre, const float* __restrict__ xres,
    const float* __restrict__ gamma, const float* __restrict__ beta,
    float* __restrict__ out, __nv_bfloat16* __restrict__ shi,
    __nv_bfloat16* __restrict__ slo, int mode)
{
    __shared__ float red[256];
    const int tid = threadIdx.x;
    const size_t base = (size_t)blockIdx.x * 65536;

    float s = 0.0f, ss = 0.0f;
    for (int i = tid * 4; i < 65536; i += 1024) {
        float4 v = *(const float4*)(pre + base + i);
        s  += v.x + v.y + v.z + v.w;
        ss += v.x * v.x + v.y * v.y + v.z * v.z + v.w * v.w;
    }
    red[tid] = s; __syncthreads();
    for (int off = 128; off; off >>= 1) { if (tid < off) red[tid] += red[tid + off]; __syncthreads(); }
    const float mean = red[0] * (1.0f / 65536.0f);
    __syncthreads();
    red[tid] = ss; __syncthreads();
    for (int off = 128; off; off >>= 1) { if (tid < off) red[tid] += red[tid + off]; __syncthreads(); }
    const float var = red[0] * (1.0f / 65536.0f) - mean * mean;
    const float rstd = rsqrtf(var + 1e-3f);

    for (int i = tid * 4; i < 65536; i += 1024) {
        float4 v = *(const float4*)(pre + base + i);
        float4 g = *(const float4*)(gamma + i);
        float4 bb = *(const float4*)(beta + i);
        float4 r;
        r.x = (v.x - mean) * rstd * g.x + bb.x;
        r.y = (v.y - mean) * rstd * g.y + bb.y;
        r.z = (v.z - mean) * rstd * g.z + bb.z;
        r.w = (v.w - mean) * rstd * g.w + bb.w;
        if (mode == 0) {
            float4 xr = *(const float4*)(xres + base + i);
            r.x += xr.x; r.y += xr.y; r.z += xr.z; r.w += xr.w;
        } else {
            float4 o = *(const float4*)(out + base + i);
            r.x += o.x; r.y += o.y; r.z += o.z; r.w += o.w;
        }
        *(float4*)(out + base + i) = r;
        if (shi) {
            float f[4] = {r.x, r.y, r.z, r.w};
            __nv_bfloat16 h[4], l[4];
#pragma unroll
            for (int k = 0; k < 4; k++) {
                h[k] = __float2bfloat16_rn(f[k]);
                l[k] = __float2bfloat16_rn(f[k] - __bfloat162float(h[k]));
            }
            *(__nv_bfloat162*)(shi + base + i)     = __nv_bfloat162(h[0], h[1]);
            *(__nv_bfloat162*)(shi + base + i + 2) = __nv_bfloat162(h[2], h[3]);
            *(__nv_bfloat162*)(slo + base + i)     = __nv_bfloat162(l[0], l[1]);
            *(__nv_bfloat162*)(slo + base + i + 2) = __nv_bfloat162(l[2], l[3]);
        }
    }
}

// ---------------- inter LSTM single-step gate update (+ fused split of h) ----------------
__global__ __launch_bounds__(256) void inter_gate_kernel(
    const float* __restrict__ Z, const float* __restrict__ c0,
    float* __restrict__ h_new, float* __restrict__ c_new,
    __nv_bfloat16* __restrict__ hhi, __nv_bfloat16* __restrict__ hlo)
{
    const int q = blockIdx.x * blockDim.x + threadIdx.x;
    const int m = q >> 7;
    const int j = (q & 127) << 2;
    const float* zp = Z + (size_t)m * 2048;
    float4 zi = *(const float4*)(zp + j);
    float4 zf = *(const float4*)(zp + 512 + j);
    float4 zg = *(const float4*)(zp + 1024 + j);
    float4 zo = *(const float4*)(zp + 1536 + j);
    float4 c  = *(const float4*)(c0 + (size_t)m * 512 + j);

    float zi_[4] = {zi.x, zi.y, zi.z, zi.w};
    float zf_[4] = {zf.x, zf.y, zf.z, zf.w};
    float zg_[4] = {zg.x, zg.y, zg.z, zg.w};
    float zo_[4] = {zo.x, zo.y, zo.z, zo.w};
    float ci[4]  = {c.x, c.y, c.z, c.w};
    float cv[4], hv[4];
#pragma unroll
    for (int l = 0; l < 4; l++) {
        float cn = hsig(zf_[l]) * ci[l] + hsig(zi_[l]) * tanhf(zg_[l]);
        cv[l] = cn;
        hv[l] = hsig(zo_[l]) * tanhf(cn);
    }
    *(float4*)(c_new + (size_t)m * 512 + j) = make_float4(cv[0], cv[1], cv[2], cv[3]);
    *(float4*)(h_new + (size_t)m * 512 + j) = make_float4(hv[0], hv[1], hv[2], hv[3]);

    __nv_bfloat16 h[4], l[4];
#pragma unroll
    for (int k = 0; k < 4; k++) {
        h[k] = __float2bfloat16_rn(hv[k]);
        l[k] = __float2bfloat16_rn(hv[k] - __bfloat162float(h[k]));
    }
    const size_t so = (size_t)m * 512 + j;
    *(__nv_bfloat162*)(hhi + so)     = __nv_bfloat162(h[0], h[1]);
    *(__nv_bfloat162*)(hhi + so + 2) = __nv_bfloat162(h[2], h[3]);
    *(__nv_bfloat162*)(hlo + so)     = __nv_bfloat162(l[0], l[1]);
    *(__nv_bfloat162*)(hlo + so + 2) = __nv_bfloat162(l[2], l[3]);
}

// ---------------- launch ----------------
extern "C" void kernel_launch(void* const* d_in, const int* in_sizes, int n_in,
                              void* d_out, int out_size)
{
    const float* x    = (const float*)d_in[0];
    const float* h0   = (const float*)d_in[1];
    const float* c0   = (const float*)d_in[2];
    const float* Wf   = (const float*)d_in[3];
    const float* Uf   = (const float*)d_in[4];
    const float* bf   = (const float*)d_in[5];
    const float* Wb   = (const float*)d_in[6];
    const float* Ub   = (const float*)d_in[7];
    const float* bb   = (const float*)d_in[8];
    const float* Wfc1 = (const float*)d_in[9];
    const float* bfc1 = (const float*)d_in[10];
    const float* g1   = (const float*)d_in[11];
    const float* b1   = (const float*)d_in[12];
    const float* Wi   = (const float*)d_in[13];
    const float* Ui   = (const float*)d_in[14];
    const float* bi   = (const float*)d_in[15];
    const float* Wfc2 = (const float*)d_in[16];
    const float* bfc2 = (const float*)d_in[17];
    const float* g2   = (const float*)d_in[18];
    const float* b2   = (const float*)d_in[19];

    float* out = (float*)d_out;
    float* h_out = out + OUT0;
    float* c_out = out + 2 * OUT0;
    const int full_out = (out_size >= (int)(3 * OUT0)) || out_size <= 0;

    float *zxf, *zxb, *fc, *iz;
    __nv_bfloat16 *ahi, *alo, *bthi, *btlo, *uthi, *utlo, *hshi, *hslo;
    cudaGetSymbolAddress((void**)&zxf, g_ZXf);
    cudaGetSymbolAddress((void**)&zxb, g_ZXb);
    cudaGetSymbolAddress((void**)&fc,  g_FC);
    cudaGetSymbolAddress((void**)&iz,  g_IZ);
    cudaGetSymbolAddress((void**)&ahi, g_Ahi);
    cudaGetSymbolAddress((void**)&alo, g_Alo);
    cudaGetSymbolAddress((void**)&bthi, g_Bthi);
    cudaGetSymbolAddress((void**)&btlo, g_Btlo);
    cudaGetSymbolAddress((void**)&uthi, g_Uthi);
    cudaGetSymbolAddress((void**)&utlo, g_Utlo);
    cudaGetSymbolAddress((void**)&hshi, g_HShi);
    cudaGetSymbolAddress((void**)&hslo, g_HSlo);

    cudaFuncSetAttribute(tcgemm, cudaFuncAttributeMaxDynamicSharedMemorySize, GEMM_SMEM);
    cudaFuncSetAttribute(recurrence2, cudaFuncAttributeMaxDynamicSharedMemorySize, RSMEM);

    const int n4A = MROWS * 512 / 4;

    // ---- intra input projections ----
    split_kernel<<<n4A / 256, 256>>>(x, ahi, alo, n4A);
    splitT_kernel<<<dim3(1024 / 32, 512 / 32), dim3(32, 8)>>>(Wf, bthi, btlo, 512, 1024);
    tcgemm<<<dim3(8, 256), 256, GEMM_SMEM>>>(ahi, alo, bthi, btlo, zxf, bf, MROWS, 1024, 512, 0);
    splitT_kernel<<<dim3(1024 / 32, 512 / 32), dim3(32, 8)>>>(Wb, bthi, btlo, 512, 1024);
    tcgemm<<<dim3(8, 256), 256, GEMM_SMEM>>>(ahi, alo, bthi, btlo, zxb, bb, MROWS, 1024, 512, 0);

    // ---- recurrent weights: U^T split (fwd rows 0..1023, bwd rows 1024..2047) ----
    splitT_kernel<<<dim3(1024 / 32, 256 / 32), dim3(32, 8)>>>(Uf, uthi, utlo, 256, 1024);
    splitT_kernel<<<dim3(1024 / 32, 256 / 32), dim3(32, 8)>>>(Ub, uthi + 1024 * 256, utlo + 1024 * 256, 256, 1024);

    // ---- bidirectional recurrence (writes g_HShi/g_HSlo) ----
    recurrence2<<<128, 256, RSMEM>>>(uthi, utlo);

    // ---- fc1 ----
    splitT_kernel<<<dim3(512 / 32, 512 / 32), dim3(32, 8)>>>(Wfc1, bthi, btlo, 512, 512);
    tcgemm<<<dim3(4, 256), 256, GEMM_SMEM>>>(hshi, hslo, bthi, btlo, fc, bfc1, MROWS, 512, 512, 0);

    // ---- LN1 + residual -> out, fused split of intra_out ----
    ln_kernel<<<256, 256>>>(fc, x, g1, b1, out, ahi, alo, 0);

    // ---- inter z = intra_out @ Wi + h0 @ Ui + bi ----
    splitT_kernel<<<dim3(2048 / 32, 512 / 32), dim3(32, 8)>>>(Wi, bthi, btlo, 512, 2048);
    tcgemm<<<dim3(16, 256), 256, GEMM_SMEM>>>(ahi, alo, bthi, btlo, iz, bi, MROWS, 2048, 512, 0);
    split_kernel<<<n4A / 256, 256>>>(h0, ahi, alo, n4A);
    splitT_kernel<<<dim3(2048 / 32, 512 / 32), dim3(32, 8)>>>(Ui, bthi, btlo, 512, 2048);
    tcgemm<<<dim3(16, 256), 256, GEMM_SMEM>>>(ahi, alo, bthi, btlo, iz, nullptr, MROWS, 2048, 512, 1);

    // ---- inter gates (+ fused split of h_new) + fc2 ----
    float* hptr = full_out ? h_out : zxf;
    float* cptr = full_out ? c_out : zxb;
    inter_gate_kernel<<<16384, 256>>>(iz, c0, hptr, cptr, ahi, alo);
    splitT_kernel<<<dim3(512 / 32, 512 / 32), dim3(32, 8)>>>(Wfc2, bthi, btlo, 512, 512);
    tcgemm<<<dim3(4, 256), 256, GEMM_SMEM>>>(ahi, alo, bthi, btlo, fc, bfc2, MROWS, 512, 512, 0);

    // ---- LN2 accumulate into out ----
    ln_kernel<<<256, 256>>>(fc, nullptr, g2, b2, out, nullptr, nullptr, 1);
}

// round 5
// speedup vs baseline: 2.7633x; 1.0578x over previous
#include <cuda_runtime.h>
#include <cuda_bf16.h>
#include <cstdint>
#include <math.h>

// Problem constants
#define NSAMP 256            // B*L
#define W_    128
#define C_    512
#define HD_   256
#define MROWS 32768          // B*W
#define OUT0  ((size_t)16777216)   // B*L*W*C

// ---------------- scratch (static device globals; no allocations) ----------------
__device__ float g_ZX [(size_t)MROWS * 2048];   // combined intra projections (fwd|bwd)
__device__ float g_FC [(size_t)MROWS * 512];
__device__ float g_bfc[2048];
__device__ float g_biP[2048];
__device__ unsigned long long g_barG[8 * 16];   // per-group monotonic tickets

// bf16 split buffers
__device__ __nv_bfloat16 g_Ahi[(size_t)MROWS * 1024];
__device__ __nv_bfloat16 g_Alo[(size_t)MROWS * 1024];
__device__ __nv_bfloat16 g_Bthi[(size_t)2048 * 1024];
__device__ __nv_bfloat16 g_Btlo[(size_t)2048 * 1024];
// recurrence state / weights / outputs (bf16 split)
__device__ __nv_bfloat16 g_Hhi[2][512 * 256];
__device__ __nv_bfloat16 g_Hlo[2][512 * 256];
__device__ __nv_bfloat16 g_Uthi[(size_t)2048 * 256];
__device__ __nv_bfloat16 g_Utlo[(size_t)2048 * 256];
__device__ __nv_bfloat16 g_HShi[(size_t)MROWS * 512];
__device__ __nv_bfloat16 g_HSlo[(size_t)MROWS * 512];

__device__ __forceinline__ float hsig(float x) {
    return fminf(fmaxf(fmaf(0.2f, x, 0.5f), 0.0f), 1.0f);
}

// ================= low-level helpers (sm_80-baseline ISA only) =================
__device__ __forceinline__ uint32_t smem_u32(const void* p) {
    uint32_t a;
    asm("{ .reg .u64 t; cvta.to.shared.u64 t, %1; cvt.u32.u64 %0, t; }" : "=r"(a) : "l"(p));
    return a;
}
#define CP_ASYNC16(dst, src) \
    asm volatile("cp.async.cg.shared.global [%0], [%1], 16;" :: "r"(dst), "l"(src) : "memory")
#define CP_COMMIT() asm volatile("cp.async.commit_group;" ::: "memory")
#define CP_WAIT1()  asm volatile("cp.async.wait_group 1;" ::: "memory")
#define CP_WAIT0()  asm volatile("cp.async.wait_group 0;" ::: "memory")

__device__ __forceinline__ void ldmx4(uint32_t* r, uint32_t addr) {
    asm volatile("ldmatrix.sync.aligned.m8n8.x4.shared.b16 {%0,%1,%2,%3}, [%4];"
        : "=r"(r[0]), "=r"(r[1]), "=r"(r[2]), "=r"(r[3]) : "r"(addr));
}
__device__ __forceinline__ void mma_bf16(float* d, const uint32_t* a, const uint32_t* b) {
    asm volatile("mma.sync.aligned.m16n8k16.row.col.f32.bf16.bf16.f32 "
        "{%0,%1,%2,%3}, {%4,%5,%6,%7}, {%8,%9}, {%0,%1,%2,%3};"
        : "+f"(d[0]), "+f"(d[1]), "+f"(d[2]), "+f"(d[3])
        : "r"(a[0]), "r"(a[1]), "r"(a[2]), "r"(a[3]), "r"(b[0]), "r"(b[1]));
}

// ================= split-bf16 tensor-core GEMM (mma.sync) =================
#define TILE_B   10240           // 128*80
#define STG_B    40960           // 4 tiles
#define GEMM_SMEM (2 * STG_B)    // 81920

__device__ __forceinline__ void load_chunk(uint32_t stage_base,
    const __nv_bfloat16* __restrict__ Ahi, const __nv_bfloat16* __restrict__ Alo,
    const __nv_bfloat16* __restrict__ Bhi, const __nv_bfloat16* __restrict__ Blo,
    int m0, int n0, int kk, int K, int tid)
{
#pragma unroll
    for (int i = 0; i < 2; i++) {
        const int c = tid + i * 256;
        const int row = c >> 2;
        const int seg = c & 3;
        const uint32_t doff = (uint32_t)(row * 80 + seg * 16);
        const size_t akoff = (size_t)kk + seg * 8;
        CP_ASYNC16(stage_base + 0 * TILE_B + doff, Ahi + (size_t)(m0 + row) * K + akoff);
        CP_ASYNC16(stage_base + 1 * TILE_B + doff, Alo + (size_t)(m0 + row) * K + akoff);
        CP_ASYNC16(stage_base + 2 * TILE_B + doff, Bhi + (size_t)(n0 + row) * K + akoff);
        CP_ASYNC16(stage_base + 3 * TILE_B + doff, Blo + (size_t)(n0 + row) * K + akoff);
    }
}

// mainloop shared by both GEMM kernels: accumulates 128x128 with 3-product split
#define GEMM_MAINLOOP(Ahi, Alo, Bhi, Blo, m0, n0, K, acc)                         \
    {                                                                             \
        const int NC = (K) >> 5;                                                  \
        load_chunk(sb, Ahi, Alo, Bhi, Blo, m0, n0, 0, K, tid);                    \
        CP_COMMIT();                                                              \
        load_chunk(sb + STG_B, Ahi, Alo, Bhi, Blo, m0, n0, 32, K, tid);           \
        CP_COMMIT();                                                              \
        for (int c = 0; c < NC; c++) {                                            \
            CP_WAIT1();                                                           \
            __syncthreads();                                                      \
            const uint32_t st = sb + (c & 1) * STG_B;                             \
            _Pragma("unroll")                                                     \
            for (int ks = 0; ks < 2; ks++) {                                      \
                const uint32_t kb = st + ks * 32;                                 \
                uint32_t af[4][4], bhf[4][2], blf[4][2], t4[4];                   \
                _Pragma("unroll")                                                 \
                for (int nh = 0; nh < 2; nh++) {                                  \
                    ldmx4(t4, kb + 2 * TILE_B + b_off + nh * 1280);               \
                    bhf[2*nh][0] = t4[0]; bhf[2*nh][1] = t4[1];                   \
                    bhf[2*nh+1][0] = t4[2]; bhf[2*nh+1][1] = t4[3];               \
                    ldmx4(t4, kb + 3 * TILE_B + b_off + nh * 1280);               \
                    blf[2*nh][0] = t4[0]; blf[2*nh][1] = t4[1];                   \
                    blf[2*nh+1][0] = t4[2]; blf[2*nh+1][1] = t4[3];               \
                }                                                                 \
                _Pragma("unroll")                                                 \
                for (int mf = 0; mf < 4; mf++) ldmx4(af[mf], kb + a_off + mf * 1280); \
                _Pragma("unroll")                                                 \
                for (int mf = 0; mf < 4; mf++)                                    \
                    _Pragma("unroll")                                             \
                    for (int nf = 0; nf < 4; nf++) {                              \
                        mma_bf16(acc[mf][nf], af[mf], bhf[nf]);                   \
                        mma_bf16(acc[mf][nf], af[mf], blf[nf]);                   \
                    }                                                             \
                _Pragma("unroll")                                                 \
                for (int mf = 0; mf < 4; mf++) ldmx4(af[mf], kb + TILE_B + a_off + mf * 1280); \
                _Pragma("unroll")                                                 \
                for (int mf = 0; mf < 4; mf++)                                    \
                    _Pragma("unroll")                                             \
                    for (int nf = 0; nf < 4; nf++)                                \
                        mma_bf16(acc[mf][nf], af[mf], bhf[nf]);                   \
            }                                                                     \
            __syncthreads();                                                      \
            if (c + 2 < NC)                                                       \
                load_chunk(sb + (c & 1) * STG_B, Ahi, Alo, Bhi, Blo, m0, n0, (c + 2) << 5, K, tid); \
            CP_COMMIT();                                                          \
        }                                                                         \
    }

__global__ __launch_bounds__(256, 2) void tcgemm(
    const __nv_bfloat16* __restrict__ Ahi, const __nv_bfloat16* __restrict__ Alo,
    const __nv_bfloat16* __restrict__ Bhi, const __nv_bfloat16* __restrict__ Blo,
    float* __restrict__ Cmat, const float* __restrict__ bias,
    int M, int N, int K, int accumulate)
{
    extern __shared__ __align__(128) char smem_raw[];
    const uint32_t sb = smem_u32(smem_raw);

    const int tid = threadIdx.x;
    const int lane = tid & 31;
    const int wid = tid >> 5;
    const int wm = wid >> 2;
    const int wn = wid & 3;
    const int m0 = blockIdx.y << 7;
    const int n0 = blockIdx.x << 7;

    const uint32_t a_off = (uint32_t)((wm * 64 + (lane & 15)) * 80 + (lane >> 4) * 16);
    const int bsub = lane >> 3;
    const uint32_t b_off = (uint32_t)((wn * 32 + ((bsub >> 1) << 3) + (lane & 7)) * 80 + (bsub & 1) * 16);

    float acc[4][4][4];
#pragma unroll
    for (int mf = 0; mf < 4; mf++)
#pragma unroll
        for (int nf = 0; nf < 4; nf++)
#pragma unroll
            for (int r = 0; r < 4; r++) acc[mf][nf][r] = 0.0f;

    GEMM_MAINLOOP(Ahi, Alo, Bhi, Blo, m0, n0, K, acc);

    const int qr = lane >> 2;
    const int qc = (lane & 3) << 1;
#pragma unroll
    for (int mf = 0; mf < 4; mf++) {
        const int row = m0 + wm * 64 + mf * 16 + qr;
#pragma unroll
        for (int nf = 0; nf < 4; nf++) {
            const int col = n0 + wn * 32 + nf * 8 + qc;
            float2 v0 = make_float2(acc[mf][nf][0], acc[mf][nf][1]);
            float2 v1 = make_float2(acc[mf][nf][2], acc[mf][nf][3]);
            if (bias) {
                const float2 bv = *(const float2*)(bias + col);
                v0.x += bv.x; v0.y += bv.y; v1.x += bv.x; v1.y += bv.y;
            }
            float* p0 = Cmat + (size_t)row * N + col;
            float* p1 = p0 + 8 * (size_t)N;
            if (accumulate) {
                const float2 o0 = *(const float2*)p0;
                const float2 o1 = *(const float2*)p1;
                v0.x += o0.x; v0.y += o0.y; v1.x += o1.x; v1.y += o1.y;
            }
            *(float2*)p0 = v0;
            *(float2*)p1 = v1;
        }
    }
}

// ---- inter GEMM with fused LSTM gate epilogue (gate-interleaved B layout) ----
// N-tile n holds cols {g*32+c} = gates of hidden slice [n*32, n*32+32).
__global__ __launch_bounds__(256, 2) void tcgemm_gates(
    const __nv_bfloat16* __restrict__ Ahi, const __nv_bfloat16* __restrict__ Alo,
    const __nv_bfloat16* __restrict__ Bhi, const __nv_bfloat16* __restrict__ Blo,
    const float* __restrict__ biasP, const float* __restrict__ c0,
    float* __restrict__ h_out, float* __restrict__ c_out,
    __nv_bfloat16* __restrict__ hhi, __nv_bfloat16* __restrict__ hlo, int K)
{
    extern __shared__ __align__(128) char smem_raw[];
    const uint32_t sb = smem_u32(smem_raw);

    const int tid = threadIdx.x;
    const int lane = tid & 31;
    const int wid = tid >> 5;
    const int wm = wid >> 2;
    const int wn = wid & 3;
    const int m0 = blockIdx.y << 7;
    const int n0 = blockIdx.x << 7;
    const int hid0 = blockIdx.x << 5;

    const uint32_t a_off = (uint32_t)((wm * 64 + (lane & 15)) * 80 + (lane >> 4) * 16);
    const int bsub = lane >> 3;
    const uint32_t b_off = (uint32_t)((wn * 32 + ((bsub >> 1) << 3) + (lane & 7)) * 80 + (bsub & 1) * 16);

    float acc[4][4][4];
#pragma unroll
    for (int mf = 0; mf < 4; mf++)
#pragma unroll
        for (int nf = 0; nf < 4; nf++)
#pragma unroll
            for (int r = 0; r < 4; r++) acc[mf][nf][r] = 0.0f;

    GEMM_MAINLOOP(Ahi, Alo, Bhi, Blo, m0, n0, K, acc);

    // ---- stage z (+bias) into SMEM ----
    __syncthreads();
    float* stg = (float*)smem_raw;    // 128 x 132
    const int qr = lane >> 2;
    const int qc = (lane & 3) << 1;
#pragma unroll
    for (int mf = 0; mf < 4; mf++) {
        const int rl = wm * 64 + mf * 16 + qr;
#pragma unroll
        for (int nf = 0; nf < 4; nf++) {
            const int col = wn * 32 + nf * 8 + qc;
            const float2 bv = *(const float2*)(biasP + n0 + col);
            stg[rl * 132 + col]           = acc[mf][nf][0] + bv.x;
            stg[rl * 132 + col + 1]       = acc[mf][nf][1] + bv.y;
            stg[(rl + 8) * 132 + col]     = acc[mf][nf][2] + bv.x;
            stg[(rl + 8) * 132 + col + 1] = acc[mf][nf][3] + bv.y;
        }
    }
    __syncthreads();

    // ---- gate update: thread handles (rows wid*16..+16, hidden col lane) ----
    {
        const int c = lane;
#pragma unroll
        for (int i = 0; i < 16; i++) {
            const int r = wid * 16 + i;
            const float zi = stg[r * 132 + c];
            const float zf = stg[r * 132 + 32 + c];
            const float zg = stg[r * 132 + 64 + c];
            const float zo = stg[r * 132 + 96 + c];
            const size_t go = (size_t)(m0 + r) * 512 + hid0 + c;
            const float cn = hsig(zf) * c0[go] + hsig(zi) * tanhf(zg);
            const float hv = hsig(zo) * tanhf(cn);
            c_out[go] = cn;
            h_out[go] = hv;
            const __nv_bfloat16 hh = __float2bfloat16_rn(hv);
            hhi[go] = hh;
            hlo[go] = __float2bfloat16_rn(hv - __bfloat162float(hh));
        }
    }
}

// ================= split kernels =================
// x -> ahi/alo, stride 512
__global__ __launch_bounds__(256) void split_kernel(
    const float* __restrict__ in, __nv_bfloat16* __restrict__ hi,
    __nv_bfloat16* __restrict__ lo, int n4)
{
    const int i = blockIdx.x * blockDim.x + threadIdx.x;
    if (i >= n4) return;
    const float4 v = ((const float4*)in)[i];
    float f[4] = {v.x, v.y, v.z, v.w};
    __nv_bfloat16 h[4], l[4];
#pragma unroll
    for (int k = 0; k < 4; k++) {
        h[k] = __float2bfloat16_rn(f[k]);
        l[k] = __float2bfloat16_rn(f[k] - __bfloat162float(h[k]));
    }
    ((__nv_bfloat162*)hi)[2 * i] = __nv_bfloat162(h[0], h[1]);
    ((__nv_bfloat162*)hi)[2 * i + 1] = __nv_bfloat162(h[2], h[3]);
    ((__nv_bfloat162*)lo)[2 * i] = __nv_bfloat162(l[0], l[1]);
    ((__nv_bfloat162*)lo)[2 * i + 1] = __nv_bfloat162(l[2], l[3]);
}

// h0 [32768,512] -> ahi/alo at row*1024 + 512 + col (concat A for inter GEMM)
__global__ __launch_bounds__(256) void split_off_kernel(
    const float* __restrict__ in, __nv_bfloat16* __restrict__ hi,
    __nv_bfloat16* __restrict__ lo)
{
    const int q = blockIdx.x * blockDim.x + threadIdx.x;   // float4 idx
    const int row = q >> 7;
    const int col = (q & 127) << 2;
    const float4 v = ((const float4*)in)[q];
    float f[4] = {v.x, v.y, v.z, v.w};
    __nv_bfloat16 h[4], l[4];
#pragma unroll
    for (int k = 0; k < 4; k++) {
        h[k] = __float2bfloat16_rn(f[k]);
        l[k] = __float2bfloat16_rn(f[k] - __bfloat162float(h[k]));
    }
    const size_t o = (size_t)row * 1024 + 512 + col;
    *(__nv_bfloat162*)(hi + o)     = __nv_bfloat162(h[0], h[1]);
    *(__nv_bfloat162*)(hi + o + 2) = __nv_bfloat162(h[2], h[3]);
    *(__nv_bfloat162*)(lo + o)     = __nv_bfloat162(l[0], l[1]);
    *(__nv_bfloat162*)(lo + o + 2) = __nv_bfloat162(l[2], l[3]);
}

// transpose-split: W [K,N] fp32 -> hi/lo [N,K] bf16 (row stride Kout)
__global__ void splitT_kernel(const float* __restrict__ Wm,
                              __nv_bfloat16* __restrict__ hi, __nv_bfloat16* __restrict__ lo,
                              int K, int N)
{
    __shared__ float t[32][33];
    const int kb = blockIdx.y * 32, nb = blockIdx.x * 32;
    const int tx = threadIdx.x, ty = threadIdx.y;
    for (int r = ty; r < 32; r += 8)
        t[r][tx] = Wm[(size_t)(kb + r) * N + nb + tx];
    __syncthreads();
    for (int r = ty; r < 32; r += 8) {
        const float v = t[tx][r];
        const __nv_bfloat16 h = __float2bfloat16_rn(v);
        const __nv_bfloat16 l = __float2bfloat16_rn(v - __bfloat162float(h));
        hi[(size_t)(nb + r) * K + kb + tx] = h;
        lo[(size_t)(nb + r) * K + kb + tx] = l;
    }
}

// transpose-split with gate-interleave permutation; writes [2048, Kout] at koff
__global__ void splitT_perm_kernel(const float* __restrict__ Wm,
                                   __nv_bfloat16* __restrict__ hi, __nv_bfloat16* __restrict__ lo,
                                   int N, int Kout, int koff)
{
    __shared__ float t[32][33];
    const int kb = blockIdx.y * 32, nb = blockIdx.x * 32;
    const int tx = threadIdx.x, ty = threadIdx.y;
    for (int r = ty; r < 32; r += 8)
        t[r][tx] = Wm[(size_t)(kb + r) * N + nb + tx];
    __syncthreads();
    for (int r = ty; r < 32; r += 8) {
        const float v = t[tx][r];
        const int n = nb + r;
        const int g = n >> 9, s = n & 511;
        const int nr = ((s >> 5) << 7) + (g << 5) + (s & 31);
        const __nv_bfloat16 h = __float2bfloat16_rn(v);
        const __nv_bfloat16 l = __float2bfloat16_rn(v - __bfloat162float(h));
        hi[(size_t)nr * Kout + koff + kb + tx] = h;
        lo[(size_t)nr * Kout + koff + kb + tx] = l;
    }
}

// bias prep: bfc = [bf|bb]; biP = gate-permuted bi
__global__ void bias_prep(const float* __restrict__ bf, const float* __restrict__ bb,
                          const float* __restrict__ bi,
                          float* __restrict__ bfc, float* __restrict__ biP)
{
    const int i = blockIdx.x * blockDim.x + threadIdx.x;
    if (i < 1024) bfc[i] = bf[i];
    else if (i < 2048) bfc[i] = bb[i - 1024];
    else {
        const int n = i - 2048;
        const int g = n >> 9, s = n & 511;
        const int nr = ((s >> 5) << 7) + (g << 5) + (s & 31);
        biP[nr] = bi[n];
    }
}

// ---------------- group barrier (16 CTAs per group) ----------------
__device__ __forceinline__ void group_barrier(int grp) {
    __threadfence();
    __syncthreads();
    if (threadIdx.x == 0) {
        unsigned long long* ctr = &g_barG[grp * 16];
        unsigned long long t = atomicAdd(ctr, 1ULL) + 1ULL;
        unsigned long long target = ((t + 15ULL) >> 4) << 4;
        volatile unsigned long long* p = ctr;
        while (*p < target) { __nanosleep(32); }
        __threadfence();
    }
    __syncthreads();
}

// ---------------- persistent bidirectional LSTM recurrence (HMMA, group barriers) ----------------
#define RA_STR   528
#define ROFF_ALO 33792
#define ROFF_BHI 67584
#define ROFF_BLO 101376
#define ROFF_STG 135168
#define RSMEM    152576

__global__ __launch_bounds__(256) void recurrence2(
    const __nv_bfloat16* __restrict__ Uthi, const __nv_bfloat16* __restrict__ Utlo)
{
    extern __shared__ __align__(128) char rsm[];
    const uint32_t sb = smem_u32(rsm);
    const int tid = threadIdx.x, lane = tid & 31, wid = tid >> 5;
    const int blk = blockIdx.x;
    const int tile_m = blk >> 4;         // 0..7 (= barrier group)
    const int tile_n = blk & 15;
    const int row0 = tile_m << 6;
    const int dir = (tile_m >= 4) ? 1 : 0;
    const int j0 = tile_n << 4;
    const int wm = wid & 3, wn = wid >> 2;

    for (int i = tid; i < 2048; i += 256) {
        const int r = i >> 5, seg = i & 31;
        const int g = r >> 4, c = r & 15;
        const size_t gr = ((size_t)(dir * 1024 + g * 256 + j0 + c)) * 256 + seg * 8;
        *(uint4*)(rsm + ROFF_BHI + r * RA_STR + seg * 16) = *(const uint4*)(Uthi + gr);
        *(uint4*)(rsm + ROFF_BLO + r * RA_STR + seg * 16) = *(const uint4*)(Utlo + gr);
    }

    if (tile_n == 0) {
        uint32_t* h0 = (uint32_t*)&g_Hhi[0][row0 * 256];
        uint32_t* l0 = (uint32_t*)&g_Hlo[0][row0 * 256];
        for (int i = tid; i < 8192; i += 256) { h0[i] = 0u; l0[i] = 0u; }
    }

    const uint32_t a_off = (uint32_t)((wm * 16 + (lane & 15)) * RA_STR + (lane >> 4) * 16);
    const int bsub = lane >> 3;
    const uint32_t b_off = (uint32_t)((wn * 32 + ((bsub >> 1) << 3) + (lane & 7)) * RA_STR + (bsub & 1) * 16);

    const int r_up = tid >> 2;
    const int c_up = (tid & 3) << 2;
    const int Rr = row0 + r_up;
    const int n_up = Rr & 255;
    float* stg = (float*)(rsm + ROFF_STG);
    float creg[4] = {0.0f, 0.0f, 0.0f, 0.0f};

    group_barrier(tile_m);

    for (int t = 0; t < 128; t++) {
        const int pb = t & 1;
        {
            const __nv_bfloat16* hh = g_Hhi[pb];
            const __nv_bfloat16* hl = g_Hlo[pb];
#pragma unroll
            for (int ii = 0; ii < 8; ii++) {
                const int i = tid + ii * 256;
                const int r = i >> 5, seg = i & 31;
                const size_t go = (size_t)(row0 + r) * 256 + seg * 8;
                CP_ASYNC16(sb + r * RA_STR + seg * 16, hh + go);
                CP_ASYNC16(sb + ROFF_ALO + r * RA_STR + seg * 16, hl + go);
            }
        }
        CP_COMMIT();
        CP_WAIT0();
        __syncthreads();

        float acc[4][4];
#pragma unroll
        for (int nf = 0; nf < 4; nf++)
#pragma unroll
            for (int r = 0; r < 4; r++) acc[nf][r] = 0.0f;

        for (int ks = 0; ks < 16; ks++) {
            const uint32_t kb = ks * 32;
            uint32_t ah[4], al[4], bh[4][2], bl[4][2], t4[4];
            ldmx4(ah, sb + a_off + kb);
            ldmx4(al, sb + ROFF_ALO + a_off + kb);
#pragma unroll
            for (int nh = 0; nh < 2; nh++) {
                ldmx4(t4, sb + ROFF_BHI + b_off + kb + nh * 16 * RA_STR);
                bh[2 * nh][0] = t4[0]; bh[2 * nh][1] = t4[1];
                bh[2 * nh + 1][0] = t4[2]; bh[2 * nh + 1][1] = t4[3];
                ldmx4(t4, sb + ROFF_BLO + b_off + kb + nh * 16 * RA_STR);
                bl[2 * nh][0] = t4[0]; bl[2 * nh][1] = t4[1];
                bl[2 * nh + 1][0] = t4[2]; bl[2 * nh + 1][1] = t4[3];
            }
#pragma unroll
            for (int nf = 0; nf < 4; nf++) {
                mma_bf16(acc[nf], ah, bh[nf]);
                mma_bf16(acc[nf], ah, bl[nf]);
                mma_bf16(acc[nf], al, bh[nf]);
            }
        }

        {
            const int qr = lane >> 2, qc = (lane & 3) << 1;
#pragma unroll
            for (int nf = 0; nf < 4; nf++) {
                const int col = wn * 32 + nf * 8 + qc;
                stg[(wm * 16 + qr) * 68 + col]     = acc[nf][0];
                stg[(wm * 16 + qr) * 68 + col + 1] = acc[nf][1];
                stg[(wm * 16 + qr + 8) * 68 + col]     = acc[nf][2];
                stg[(wm * 16 + qr + 8) * 68 + col + 1] = acc[nf][3];
            }
        }
        __syncthreads();

        {
            const int w = dir ? (127 - t) : t;
            const float* zx = g_ZX + ((size_t)n_up * 128 + w) * 2048 + dir * 1024 + j0 + c_up;
            __nv_bfloat16* dhh = &g_Hhi[pb ^ 1][(size_t)Rr * 256 + j0 + c_up];
            __nv_bfloat16* dhl = &g_Hlo[pb ^ 1][(size_t)Rr * 256 + j0 + c_up];
            const size_t hsoff = ((size_t)n_up * 128 + w) * 512 + dir * 256 + j0 + c_up;
            float hv[4];
#pragma unroll
            for (int l = 0; l < 4; l++) {
                const float* sr = &stg[r_up * 68 + c_up + l];
                const float zi = sr[0]  + zx[l];
                const float zf = sr[16] + zx[256 + l];
                const float zg = sr[32] + zx[512 + l];
                const float zo = sr[48] + zx[768 + l];
                const float cn = hsig(zf) * creg[l] + hsig(zi) * tanhf(zg);
                creg[l] = cn;
                hv[l] = hsig(zo) * tanhf(cn);
            }
            __nv_bfloat16 hh[4], hl[4];
#pragma unroll
            for (int l = 0; l < 4; l++) {
                hh[l] = __float2bfloat16_rn(hv[l]);
                hl[l] = __float2bfloat16_rn(hv[l] - __bfloat162float(hh[l]));
            }
            *(__nv_bfloat162*)(dhh)     = __nv_bfloat162(hh[0], hh[1]);
            *(__nv_bfloat162*)(dhh + 2) = __nv_bfloat162(hh[2], hh[3]);
            *(__nv_bfloat162*)(dhl)     = __nv_bfloat162(hl[0], hl[1]);
            *(__nv_bfloat162*)(dhl + 2) = __nv_bfloat162(hl[2], hl[3]);
            *(__nv_bfloat162*)(g_HShi + hsoff)     = __nv_bfloat162(hh[0], hh[1]);
            *(__nv_bfloat162*)(g_HShi + hsoff + 2) = __nv_bfloat162(hh[2], hh[3]);
            *(__nv_bfloat162*)(g_HSlo + hsoff)     = __nv_bfloat162(hl[0], hl[1]);
            *(__nv_bfloat162*)(g_HSlo + hsoff + 2) = __nv_bfloat162(hl[2], hl[3]);
        }

        group_barrier(tile_m);
    }
}

// ---------------- LayerNorm over (W,C)=65536, optional fused bf16 split (stride 1024) ----------------
__global__ __launch_bounds__(256) void ln_kernel(
    const float* __restrict__ pre, const float* __restrict__ xres,
    const float* __restrict__ gamma, const float* __restrict__ beta,
    float* __restrict__ out, __nv_bfloat16* __restrict__ shi,
    __nv_bfloat16* __restrict__ slo, int mode)
{
    __shared__ float red[256];
    const int tid = threadIdx.x;
    const size_t base = (size_t)blockIdx.x * 65536;

    float s = 0.0f, ss = 0.0f;
    for (int i = tid * 4; i < 65536; i += 1024) {
        float4 v = *(const float4*)(pre + base + i);
        s  += v.x + v.y + v.z + v.w;
        ss += v.x * v.x + v.y * v.y + v.z * v.z + v.w * v.w;
    }
    red[tid] = s; __syncthreads();
    for (int off = 128; off; off >>= 1) { if (tid < off) red[tid] += red[tid + off]; __syncthreads(); }
    const float mean = red[0] * (1.0f / 65536.0f);
    __syncthreads();
    red[tid] = ss; __syncthreads();
    for (int off = 128; off; off >>= 1) { if (tid < off) red[tid] += red[tid + off]; __syncthreads(); }
    const float var = red[0] * (1.0f / 65536.0f) - mean * mean;
    const float rstd = rsqrtf(var + 1e-3f);

    for (int i = tid * 4; i < 65536; i += 1024) {
        float4 v = *(const float4*)(pre + base + i);
        float4 g = *(const float4*)(gamma + i);
        float4 bb = *(const float4*)(beta + i);
        float4 r;
        r.x = (v.x - mean) * rstd * g.x + bb.x;
        r.y = (v.y - mean) * rstd * g.y + bb.y;
        r.z = (v.z - mean) * rstd * g.z + bb.z;
        r.w = (v.w - mean) * rstd * g.w + bb.w;
        if (mode == 0) {
            float4 xr = *(const float4*)(xres + base + i);
            r.x += xr.x; r.y += xr.y; r.z += xr.z; r.w += xr.w;
        } else {
            float4 o = *(const float4*)(out + base + i);
            r.x += o.x; r.y += o.y; r.z += o.z; r.w += o.w;
        }
        *(float4*)(out + base + i) = r;
        if (shi) {
            const size_t f = base + i;
            const size_t so = (f >> 9) * 1024 + (f & 511);
            float fv[4] = {r.x, r.y, r.z, r.w};
            __nv_bfloat16 h[4], l[4];
#pragma unroll
            for (int k = 0; k < 4; k++) {
                h[k] = __float2bfloat16_rn(fv[k]);
                l[k] = __float2bfloat16_rn(fv[k] - __bfloat162float(h[k]));
            }
            *(__nv_bfloat162*)(shi + so)     = __nv_bfloat162(h[0], h[1]);
            *(__nv_bfloat162*)(shi + so + 2) = __nv_bfloat162(h[2], h[3]);
            *(__nv_bfloat162*)(slo + so)     = __nv_bfloat162(l[0], l[1]);
            *(__nv_bfloat162*)(slo + so + 2) = __nv_bfloat162(l[2], l[3]);
        }
    }
}

// ---------------- launch ----------------
extern "C" void kernel_launch(void* const* d_in, const int* in_sizes, int n_in,
                              void* d_out, int out_size)
{
    const float* x    = (const float*)d_in[0];
    const float* h0   = (const float*)d_in[1];
    const float* c0   = (const float*)d_in[2];
    const float* Wf   = (const float*)d_in[3];
    const float* Uf   = (const float*)d_in[4];
    const float* bf   = (const float*)d_in[5];
    const float* Wb   = (const float*)d_in[6];
    const float* Ub   = (const float*)d_in[7];
    const float* bb   = (const float*)d_in[8];
    const float* Wfc1 = (const float*)d_in[9];
    const float* bfc1 = (const float*)d_in[10];
    const float* g1   = (const float*)d_in[11];
    const float* b1   = (const float*)d_in[12];
    const float* Wi   = (const float*)d_in[13];
    const float* Ui   = (const float*)d_in[14];
    const float* bi   = (const float*)d_in[15];
    const float* Wfc2 = (const float*)d_in[16];
    const float* bfc2 = (const float*)d_in[17];
    const float* g2   = (const float*)d_in[18];
    const float* b2   = (const float*)d_in[19];

    float* out = (float*)d_out;
    float* h_out = out + OUT0;
    float* c_out = out + 2 * OUT0;
    const int full_out = (out_size >= (int)(3 * OUT0)) || out_size <= 0;

    float *zx, *fc, *bfc, *biP;
    __nv_bfloat16 *ahi, *alo, *bthi, *btlo, *uthi, *utlo, *hshi, *hslo;
    cudaGetSymbolAddress((void**)&zx,  g_ZX);
    cudaGetSymbolAddress((void**)&fc,  g_FC);
    cudaGetSymbolAddress((void**)&bfc, g_bfc);
    cudaGetSymbolAddress((void**)&biP, g_biP);
    cudaGetSymbolAddress((void**)&ahi, g_Ahi);
    cudaGetSymbolAddress((void**)&alo, g_Alo);
    cudaGetSymbolAddress((void**)&bthi, g_Bthi);
    cudaGetSymbolAddress((void**)&btlo, g_Btlo);
    cudaGetSymbolAddress((void**)&uthi, g_Uthi);
    cudaGetSymbolAddress((void**)&utlo, g_Utlo);
    cudaGetSymbolAddress((void**)&hshi, g_HShi);
    cudaGetSymbolAddress((void**)&hslo, g_HSlo);

    cudaFuncSetAttribute(tcgemm, cudaFuncAttributeMaxDynamicSharedMemorySize, GEMM_SMEM);
    cudaFuncSetAttribute(tcgemm_gates, cudaFuncAttributeMaxDynamicSharedMemorySize, GEMM_SMEM);
    cudaFuncSetAttribute(recurrence2, cudaFuncAttributeMaxDynamicSharedMemorySize, RSMEM);

    const int n4A = MROWS * 512 / 4;

    // ---- combined intra input projection: ZX = x @ [Wf|Wb] + [bf|bb] ----
    split_kernel<<<n4A / 256, 256>>>(x, ahi, alo, n4A);
    bias_prep<<<16, 256>>>(bf, bb, bi, bfc, biP);
    splitT_kernel<<<dim3(32, 16), dim3(32, 8)>>>(Wf, bthi, btlo, 512, 1024);
    splitT_kernel<<<dim3(32, 16), dim3(32, 8)>>>(Wb, bthi + (size_t)1024 * 512, btlo + (size_t)1024 * 512, 512, 1024);
    tcgemm<<<dim3(16, 256), 256, GEMM_SMEM>>>(ahi, alo, bthi, btlo, zx, bfc, MROWS, 2048, 512, 0);

    // ---- recurrent weights + recurrence ----
    splitT_kernel<<<dim3(32, 8), dim3(32, 8)>>>(Uf, uthi, utlo, 256, 1024);
    splitT_kernel<<<dim3(32, 8), dim3(32, 8)>>>(Ub, uthi + 1024 * 256, utlo + 1024 * 256, 256, 1024);
    recurrence2<<<128, 256, RSMEM>>>(uthi, utlo);

    // ---- fc1 ----
    splitT_kernel<<<dim3(16, 16), dim3(32, 8)>>>(Wfc1, bthi, btlo, 512, 512);
    tcgemm<<<dim3(4, 256), 256, GEMM_SMEM>>>(hshi, hslo, bthi, btlo, fc, bfc1, MROWS, 512, 512, 0);

    // ---- LN1 + residual -> out, fused split (concat A cols 0..511) ----
    ln_kernel<<<256, 256>>>(fc, x, g1, b1, out, ahi, alo, 0);

    // ---- inter: single K=1024 GEMM with fused gates ----
    split_off_kernel<<<16384, 256>>>(h0, ahi, alo);
    splitT_perm_kernel<<<dim3(64, 16), dim3(32, 8)>>>(Wi, bthi, btlo, 2048, 1024, 0);
    splitT_perm_kernel<<<dim3(64, 16), dim3(32, 8)>>>(Ui, bthi, btlo, 2048, 1024, 512);
    float* hptr = full_out ? h_out : (zx);
    float* cptr = full_out ? c_out : (zx + (size_t)MROWS * 512);
    tcgemm_gates<<<dim3(16, 256), 256, GEMM_SMEM>>>(ahi, alo, bthi, btlo, biP, c0,
                                                    hptr, cptr, hshi, hslo, 1024);

    // ---- fc2 ----
    splitT_kernel<<<dim3(16, 16), dim3(32, 8)>>>(Wfc2, bthi, btlo, 512, 512);
    tcgemm<<<dim3(4, 256), 256, GEMM_SMEM>>>(hshi, hslo, bthi, btlo, fc, bfc2, MROWS, 512, 512, 0);

    // ---- LN2 accumulate into out ----
    ln_kernel<<<256, 256>>>(fc, nullptr, g2, b2, out, nullptr, nullptr, 1);
}

// round 6
// speedup vs baseline: 2.9243x; 1.0583x over previous
#include <cuda_runtime.h>
#include <cuda_bf16.h>
#include <cstdint>
#include <math.h>

// Problem constants
#define NSAMP 256            // B*L
#define W_    128
#define C_    512
#define HD_   256
#define MROWS 32768          // B*W
#define OUT0  ((size_t)16777216)   // B*L*W*C

// ---------------- scratch (static device globals; no allocations) ----------------
__device__ float g_ZX [(size_t)MROWS * 2048];   // combined intra projections (fwd|bwd)
__device__ float g_FC [(size_t)MROWS * 512];
__device__ float g_bfc[2048];
__device__ float g_biP[2048];
__device__ unsigned long long g_barG[8 * 16];   // per-group monotonic tickets

// bf16 split buffers
__device__ __nv_bfloat16 g_Ahi[(size_t)MROWS * 1024];
__device__ __nv_bfloat16 g_Alo[(size_t)MROWS * 1024];
__device__ __nv_bfloat16 g_Bthi[(size_t)2048 * 1024];
__device__ __nv_bfloat16 g_Btlo[(size_t)2048 * 1024];
// recurrence state / weights / outputs (bf16 split)
__device__ __nv_bfloat16 g_Hhi[2][512 * 256];
__device__ __nv_bfloat16 g_Hlo[2][512 * 256];
__device__ __nv_bfloat16 g_Uthi[(size_t)2048 * 256];
__device__ __nv_bfloat16 g_Utlo[(size_t)2048 * 256];
__device__ __nv_bfloat16 g_HShi[(size_t)MROWS * 512];
__device__ __nv_bfloat16 g_HSlo[(size_t)MROWS * 512];

__device__ __forceinline__ float hsig(float x) {
    return fminf(fmaxf(fmaf(0.2f, x, 0.5f), 0.0f), 1.0f);
}

// ================= low-level helpers (sm_80-baseline ISA only) =================
__device__ __forceinline__ uint32_t smem_u32(const void* p) {
    uint32_t a;
    asm("{ .reg .u64 t; cvta.to.shared.u64 t, %1; cvt.u32.u64 %0, t; }" : "=r"(a) : "l"(p));
    return a;
}
#define CP_ASYNC16(dst, src) \
    asm volatile("cp.async.cg.shared.global [%0], [%1], 16;" :: "r"(dst), "l"(src) : "memory")
#define CP_COMMIT() asm volatile("cp.async.commit_group;" ::: "memory")
#define CP_WAIT1()  asm volatile("cp.async.wait_group 1;" ::: "memory")
#define CP_WAIT0()  asm volatile("cp.async.wait_group 0;" ::: "memory")

__device__ __forceinline__ void ldmx4(uint32_t* r, uint32_t addr) {
    asm volatile("ldmatrix.sync.aligned.m8n8.x4.shared.b16 {%0,%1,%2,%3}, [%4];"
        : "=r"(r[0]), "=r"(r[1]), "=r"(r[2]), "=r"(r[3]) : "r"(addr));
}
__device__ __forceinline__ void mma_bf16(float* d, const uint32_t* a, const uint32_t* b) {
    asm volatile("mma.sync.aligned.m16n8k16.row.col.f32.bf16.bf16.f32 "
        "{%0,%1,%2,%3}, {%4,%5,%6,%7}, {%8,%9}, {%0,%1,%2,%3};"
        : "+f"(d[0]), "+f"(d[1]), "+f"(d[2]), "+f"(d[3])
        : "r"(a[0]), "r"(a[1]), "r"(a[2]), "r"(a[3]), "r"(b[0]), "r"(b[1]));
}

// ================= split-bf16 tensor-core GEMM (mma.sync) =================
#define TILE_B   10240           // 128*80
#define STG_B    40960           // 4 tiles
#define GEMM_SMEM (2 * STG_B)    // 81920

__device__ __forceinline__ void load_chunk(uint32_t stage_base,
    const __nv_bfloat16* __restrict__ Ahi, const __nv_bfloat16* __restrict__ Alo,
    const __nv_bfloat16* __restrict__ Bhi, const __nv_bfloat16* __restrict__ Blo,
    int m0, int n0, int kk, int K, int tid)
{
#pragma unroll
    for (int i = 0; i < 2; i++) {
        const int c = tid + i * 256;
        const int row = c >> 2;
        const int seg = c & 3;
        const uint32_t doff = (uint32_t)(row * 80 + seg * 16);
        const size_t akoff = (size_t)kk + seg * 8;
        CP_ASYNC16(stage_base + 0 * TILE_B + doff, Ahi + (size_t)(m0 + row) * K + akoff);
        CP_ASYNC16(stage_base + 1 * TILE_B + doff, Alo + (size_t)(m0 + row) * K + akoff);
        CP_ASYNC16(stage_base + 2 * TILE_B + doff, Bhi + (size_t)(n0 + row) * K + akoff);
        CP_ASYNC16(stage_base + 3 * TILE_B + doff, Blo + (size_t)(n0 + row) * K + akoff);
    }
}

// mainloop shared by both GEMM kernels: accumulates 128x128 with 3-product split
#define GEMM_MAINLOOP(Ahi, Alo, Bhi, Blo, m0, n0, K, acc)                         \
    {                                                                             \
        const int NC = (K) >> 5;                                                  \
        load_chunk(sb, Ahi, Alo, Bhi, Blo, m0, n0, 0, K, tid);                    \
        CP_COMMIT();                                                              \
        load_chunk(sb + STG_B, Ahi, Alo, Bhi, Blo, m0, n0, 32, K, tid);           \
        CP_COMMIT();                                                              \
        for (int c = 0; c < NC; c++) {                                            \
            CP_WAIT1();                                                           \
            __syncthreads();                                                      \
            const uint32_t st = sb + (c & 1) * STG_B;                             \
            _Pragma("unroll")                                                     \
            for (int ks = 0; ks < 2; ks++) {                                      \
                const uint32_t kb = st + ks * 32;                                 \
                uint32_t af[4][4], bhf[4][2], blf[4][2], t4[4];                   \
                _Pragma("unroll")                                                 \
                for (int nh = 0; nh < 2; nh++) {                                  \
                    ldmx4(t4, kb + 2 * TILE_B + b_off + nh * 1280);               \
                    bhf[2*nh][0] = t4[0]; bhf[2*nh][1] = t4[1];                   \
                    bhf[2*nh+1][0] = t4[2]; bhf[2*nh+1][1] = t4[3];               \
                    ldmx4(t4, kb + 3 * TILE_B + b_off + nh * 1280);               \
                    blf[2*nh][0] = t4[0]; blf[2*nh][1] = t4[1];                   \
                    blf[2*nh+1][0] = t4[2]; blf[2*nh+1][1] = t4[3];               \
                }                                                                 \
                _Pragma("unroll")                                                 \
                for (int mf = 0; mf < 4; mf++) ldmx4(af[mf], kb + a_off + mf * 1280); \
                _Pragma("unroll")                                                 \
                for (int mf = 0; mf < 4; mf++)                                    \
                    _Pragma("unroll")                                             \
                    for (int nf = 0; nf < 4; nf++) {                              \
                        mma_bf16(acc[mf][nf], af[mf], bhf[nf]);                   \
                        mma_bf16(acc[mf][nf], af[mf], blf[nf]);                   \
                    }                                                             \
                _Pragma("unroll")                                                 \
                for (int mf = 0; mf < 4; mf++) ldmx4(af[mf], kb + TILE_B + a_off + mf * 1280); \
                _Pragma("unroll")                                                 \
                for (int mf = 0; mf < 4; mf++)                                    \
                    _Pragma("unroll")                                             \
                    for (int nf = 0; nf < 4; nf++)                                \
                        mma_bf16(acc[mf][nf], af[mf], bhf[nf]);                   \
            }                                                                     \
            __syncthreads();                                                      \
            if (c + 2 < NC)                                                       \
                load_chunk(sb + (c & 1) * STG_B, Ahi, Alo, Bhi, Blo, m0, n0, (c + 2) << 5, K, tid); \
            CP_COMMIT();                                                          \
        }                                                                         \
    }

__global__ __launch_bounds__(256, 2) void tcgemm(
    const __nv_bfloat16* __restrict__ Ahi, const __nv_bfloat16* __restrict__ Alo,
    const __nv_bfloat16* __restrict__ Bhi, const __nv_bfloat16* __restrict__ Blo,
    float* __restrict__ Cmat, const float* __restrict__ bias,
    int M, int N, int K, int accumulate)
{
    extern __shared__ __align__(128) char smem_raw[];
    const uint32_t sb = smem_u32(smem_raw);

    const int tid = threadIdx.x;
    const int lane = tid & 31;
    const int wid = tid >> 5;
    const int wm = wid >> 2;
    const int wn = wid & 3;
    const int m0 = blockIdx.y << 7;
    const int n0 = blockIdx.x << 7;

    const uint32_t a_off = (uint32_t)((wm * 64 + (lane & 15)) * 80 + (lane >> 4) * 16);
    const int bsub = lane >> 3;
    const uint32_t b_off = (uint32_t)((wn * 32 + ((bsub >> 1) << 3) + (lane & 7)) * 80 + (bsub & 1) * 16);

    float acc[4][4][4];
#pragma unroll
    for (int mf = 0; mf < 4; mf++)
#pragma unroll
        for (int nf = 0; nf < 4; nf++)
#pragma unroll
            for (int r = 0; r < 4; r++) acc[mf][nf][r] = 0.0f;

    GEMM_MAINLOOP(Ahi, Alo, Bhi, Blo, m0, n0, K, acc);

    const int qr = lane >> 2;
    const int qc = (lane & 3) << 1;
#pragma unroll
    for (int mf = 0; mf < 4; mf++) {
        const int row = m0 + wm * 64 + mf * 16 + qr;
#pragma unroll
        for (int nf = 0; nf < 4; nf++) {
            const int col = n0 + wn * 32 + nf * 8 + qc;
            float2 v0 = make_float2(acc[mf][nf][0], acc[mf][nf][1]);
            float2 v1 = make_float2(acc[mf][nf][2], acc[mf][nf][3]);
            if (bias) {
                const float2 bv = *(const float2*)(bias + col);
                v0.x += bv.x; v0.y += bv.y; v1.x += bv.x; v1.y += bv.y;
            }
            float* p0 = Cmat + (size_t)row * N + col;
            float* p1 = p0 + 8 * (size_t)N;
            if (accumulate) {
                const float2 o0 = *(const float2*)p0;
                const float2 o1 = *(const float2*)p1;
                v0.x += o0.x; v0.y += o0.y; v1.x += o1.x; v1.y += o1.y;
            }
            *(float2*)p0 = v0;
            *(float2*)p1 = v1;
        }
    }
}

// ---- inter GEMM with fused LSTM gate epilogue (gate-interleaved B layout) ----
__global__ __launch_bounds__(256, 2) void tcgemm_gates(
    const __nv_bfloat16* __restrict__ Ahi, const __nv_bfloat16* __restrict__ Alo,
    const __nv_bfloat16* __restrict__ Bhi, const __nv_bfloat16* __restrict__ Blo,
    const float* __restrict__ biasP, const float* __restrict__ c0,
    float* __restrict__ h_out, float* __restrict__ c_out,
    __nv_bfloat16* __restrict__ hhi, __nv_bfloat16* __restrict__ hlo, int K)
{
    extern __shared__ __align__(128) char smem_raw[];
    const uint32_t sb = smem_u32(smem_raw);

    const int tid = threadIdx.x;
    const int lane = tid & 31;
    const int wid = tid >> 5;
    const int wm = wid >> 2;
    const int wn = wid & 3;
    const int m0 = blockIdx.y << 7;
    const int n0 = blockIdx.x << 7;
    const int hid0 = blockIdx.x << 5;

    const uint32_t a_off = (uint32_t)((wm * 64 + (lane & 15)) * 80 + (lane >> 4) * 16);
    const int bsub = lane >> 3;
    const uint32_t b_off = (uint32_t)((wn * 32 + ((bsub >> 1) << 3) + (lane & 7)) * 80 + (bsub & 1) * 16);

    float acc[4][4][4];
#pragma unroll
    for (int mf = 0; mf < 4; mf++)
#pragma unroll
        for (int nf = 0; nf < 4; nf++)
#pragma unroll
            for (int r = 0; r < 4; r++) acc[mf][nf][r] = 0.0f;

    GEMM_MAINLOOP(Ahi, Alo, Bhi, Blo, m0, n0, K, acc);

    __syncthreads();
    float* stg = (float*)smem_raw;    // 128 x 132
    const int qr = lane >> 2;
    const int qc = (lane & 3) << 1;
#pragma unroll
    for (int mf = 0; mf < 4; mf++) {
        const int rl = wm * 64 + mf * 16 + qr;
#pragma unroll
        for (int nf = 0; nf < 4; nf++) {
            const int col = wn * 32 + nf * 8 + qc;
            const float2 bv = *(const float2*)(biasP + n0 + col);
            stg[rl * 132 + col]           = acc[mf][nf][0] + bv.x;
            stg[rl * 132 + col + 1]       = acc[mf][nf][1] + bv.y;
            stg[(rl + 8) * 132 + col]     = acc[mf][nf][2] + bv.x;
            stg[(rl + 8) * 132 + col + 1] = acc[mf][nf][3] + bv.y;
        }
    }
    __syncthreads();

    {
        const int c = lane;
#pragma unroll
        for (int i = 0; i < 16; i++) {
            const int r = wid * 16 + i;
            const float zi = stg[r * 132 + c];
            const float zf = stg[r * 132 + 32 + c];
            const float zg = stg[r * 132 + 64 + c];
            const float zo = stg[r * 132 + 96 + c];
            const size_t go = (size_t)(m0 + r) * 512 + hid0 + c;
            const float cn = hsig(zf) * c0[go] + hsig(zi) * tanhf(zg);
            const float hv = hsig(zo) * tanhf(cn);
            c_out[go] = cn;
            h_out[go] = hv;
            const __nv_bfloat16 hh = __float2bfloat16_rn(hv);
            hhi[go] = hh;
            hlo[go] = __float2bfloat16_rn(hv - __bfloat162float(hh));
        }
    }
}

// ================= split kernels =================
__global__ __launch_bounds__(256) void split_kernel(
    const float* __restrict__ in, __nv_bfloat16* __restrict__ hi,
    __nv_bfloat16* __restrict__ lo, int n4)
{
    const int i = blockIdx.x * blockDim.x + threadIdx.x;
    if (i >= n4) return;
    const float4 v = ((const float4*)in)[i];
    float f[4] = {v.x, v.y, v.z, v.w};
    __nv_bfloat16 h[4], l[4];
#pragma unroll
    for (int k = 0; k < 4; k++) {
        h[k] = __float2bfloat16_rn(f[k]);
        l[k] = __float2bfloat16_rn(f[k] - __bfloat162float(h[k]));
    }
    ((__nv_bfloat162*)hi)[2 * i] = __nv_bfloat162(h[0], h[1]);
    ((__nv_bfloat162*)hi)[2 * i + 1] = __nv_bfloat162(h[2], h[3]);
    ((__nv_bfloat162*)lo)[2 * i] = __nv_bfloat162(l[0], l[1]);
    ((__nv_bfloat162*)lo)[2 * i + 1] = __nv_bfloat162(l[2], l[3]);
}

// h0 [32768,512] -> ahi/alo at row*1024 + 512 + col (concat A for inter GEMM)
__global__ __launch_bounds__(256) void split_off_kernel(
    const float* __restrict__ in, __nv_bfloat16* __restrict__ hi,
    __nv_bfloat16* __restrict__ lo)
{
    const int q = blockIdx.x * blockDim.x + threadIdx.x;
    const int row = q >> 7;
    const int col = (q & 127) << 2;
    const float4 v = ((const float4*)in)[q];
    float f[4] = {v.x, v.y, v.z, v.w};
    __nv_bfloat16 h[4], l[4];
#pragma unroll
    for (int k = 0; k < 4; k++) {
        h[k] = __float2bfloat16_rn(f[k]);
        l[k] = __float2bfloat16_rn(f[k] - __bfloat162float(h[k]));
    }
    const size_t o = (size_t)row * 1024 + 512 + col;
    *(__nv_bfloat162*)(hi + o)     = __nv_bfloat162(h[0], h[1]);
    *(__nv_bfloat162*)(hi + o + 2) = __nv_bfloat162(h[2], h[3]);
    *(__nv_bfloat162*)(lo + o)     = __nv_bfloat162(l[0], l[1]);
    *(__nv_bfloat162*)(lo + o + 2) = __nv_bfloat162(l[2], l[3]);
}

// transpose-split: W [K,N] fp32 -> hi/lo [N,K] bf16
__global__ void splitT_kernel(const float* __restrict__ Wm,
                              __nv_bfloat16* __restrict__ hi, __nv_bfloat16* __restrict__ lo,
                              int K, int N)
{
    __shared__ float t[32][33];
    const int kb = blockIdx.y * 32, nb = blockIdx.x * 32;
    const int tx = threadIdx.x, ty = threadIdx.y;
    for (int r = ty; r < 32; r += 8)
        t[r][tx] = Wm[(size_t)(kb + r) * N + nb + tx];
    __syncthreads();
    for (int r = ty; r < 32; r += 8) {
        const float v = t[tx][r];
        const __nv_bfloat16 h = __float2bfloat16_rn(v);
        const __nv_bfloat16 l = __float2bfloat16_rn(v - __bfloat162float(h));
        hi[(size_t)(nb + r) * K + kb + tx] = h;
        lo[(size_t)(nb + r) * K + kb + tx] = l;
    }
}

// transpose-split with gate-interleave permutation; writes [2048, Kout] at koff
__global__ void splitT_perm_kernel(const float* __restrict__ Wm,
                                   __nv_bfloat16* __restrict__ hi, __nv_bfloat16* __restrict__ lo,
                                   int N, int Kout, int koff)
{
    __shared__ float t[32][33];
    const int kb = blockIdx.y * 32, nb = blockIdx.x * 32;
    const int tx = threadIdx.x, ty = threadIdx.y;
    for (int r = ty; r < 32; r += 8)
        t[r][tx] = Wm[(size_t)(kb + r) * N + nb + tx];
    __syncthreads();
    for (int r = ty; r < 32; r += 8) {
        const float v = t[tx][r];
        const int n = nb + r;
        const int g = n >> 9, s = n & 511;
        const int nr = ((s >> 5) << 7) + (g << 5) + (s & 31);
        const __nv_bfloat16 h = __float2bfloat16_rn(v);
        const __nv_bfloat16 l = __float2bfloat16_rn(v - __bfloat162float(h));
        hi[(size_t)nr * Kout + koff + kb + tx] = h;
        lo[(size_t)nr * Kout + koff + kb + tx] = l;
    }
}

// bias prep: bfc = [bf|bb]; biP = gate-permuted bi
__global__ void bias_prep(const float* __restrict__ bf, const float* __restrict__ bb,
                          const float* __restrict__ bi,
                          float* __restrict__ bfc, float* __restrict__ biP)
{
    const int i = blockIdx.x * blockDim.x + threadIdx.x;
    if (i < 1024) bfc[i] = bf[i];
    else if (i < 2048) bfc[i] = bb[i - 1024];
    else {
        const int n = i - 2048;
        const int g = n >> 9, s = n & 511;
        const int nr = ((s >> 5) << 7) + (g << 5) + (s & 31);
        biP[nr] = bi[n];
    }
}

// ---------------- group barrier (16 CTAs per group) ----------------
__device__ __forceinline__ void group_barrier(int grp) {
    __threadfence();
    __syncthreads();
    if (threadIdx.x == 0) {
        unsigned long long* ctr = &g_barG[grp * 16];
        unsigned long long t = atomicAdd(ctr, 1ULL) + 1ULL;
        unsigned long long target = ((t + 15ULL) >> 4) << 4;
        volatile unsigned long long* p = ctr;
        while (*p < target) { __nanosleep(32); }
        __threadfence();
    }
    __syncthreads();
}

// ---------------- persistent bidirectional LSTM recurrence (HMMA, overlapped loads) ----------------
#define RA_STR   528
#define ROFF_ALO 33792
#define ROFF_BHI 67584
#define ROFF_BLO 101376
#define ROFF_STG 135168
#define ROFF_ZX  152576
#define RSMEM    168960

__global__ __launch_bounds__(256) void recurrence2(
    const __nv_bfloat16* __restrict__ Uthi, const __nv_bfloat16* __restrict__ Utlo)
{
    extern __shared__ __align__(128) char rsm[];
    const uint32_t sb = smem_u32(rsm);
    const int tid = threadIdx.x, lane = tid & 31, wid = tid >> 5;
    const int blk = blockIdx.x;
    const int tile_m = blk >> 4;         // 0..7 (= barrier group)
    const int tile_n = blk & 15;
    const int row0 = tile_m << 6;
    const int dir = (tile_m >= 4) ? 1 : 0;
    const int j0 = tile_n << 4;
    const int wm = wid & 3, wn = wid >> 2;

    for (int i = tid; i < 2048; i += 256) {
        const int r = i >> 5, seg = i & 31;
        const int g = r >> 4, c = r & 15;
        const size_t gr = ((size_t)(dir * 1024 + g * 256 + j0 + c)) * 256 + seg * 8;
        *(uint4*)(rsm + ROFF_BHI + r * RA_STR + seg * 16) = *(const uint4*)(Uthi + gr);
        *(uint4*)(rsm + ROFF_BLO + r * RA_STR + seg * 16) = *(const uint4*)(Utlo + gr);
    }

    if (tile_n == 0) {
        uint32_t* h0 = (uint32_t*)&g_Hhi[0][row0 * 256];
        uint32_t* l0 = (uint32_t*)&g_Hlo[0][row0 * 256];
        for (int i = tid; i < 8192; i += 256) { h0[i] = 0u; l0[i] = 0u; }
    }

    const uint32_t a_off = (uint32_t)((wm * 16 + (lane & 15)) * RA_STR + (lane >> 4) * 16);
    const int bsub = lane >> 3;
    const uint32_t b_off = (uint32_t)((wn * 32 + ((bsub >> 1) << 3) + (lane & 7)) * RA_STR + (bsub & 1) * 16);

    const int r_up = tid >> 2;
    const int c_up = (tid & 3) << 2;
    const int Rr = row0 + r_up;
    const int n_up = Rr & 255;
    float* stg = (float*)(rsm + ROFF_STG);
    float* zxs = (float*)(rsm + ROFF_ZX);
    float creg[4] = {0.0f, 0.0f, 0.0f, 0.0f};

    group_barrier(tile_m);

    for (int t = 0; t < 128; t++) {
        const int pb = t & 1;
        const int w = dir ? (127 - t) : t;
        const __nv_bfloat16* hh = g_Hhi[pb];
        const __nv_bfloat16* hl = g_Hlo[pb];

        // ---- commit group 1: H halves k 0..127 ----
#pragma unroll
        for (int ii = 0; ii < 4; ii++) {
            const int i = tid + ii * 256;
            const int r = i >> 4, seg = i & 15;
            const size_t go = (size_t)(row0 + r) * 256 + seg * 8;
            CP_ASYNC16(sb + r * RA_STR + seg * 16, hh + go);
            CP_ASYNC16(sb + ROFF_ALO + r * RA_STR + seg * 16, hl + go);
        }
        CP_COMMIT();
        // ---- commit group 2: H k 128..255 + zx prefetch ----
#pragma unroll
        for (int ii = 0; ii < 4; ii++) {
            const int i = tid + ii * 256;
            const int r = i >> 4, seg = 16 + (i & 15);
            const size_t go = (size_t)(row0 + r) * 256 + seg * 8;
            CP_ASYNC16(sb + r * RA_STR + seg * 16, hh + go);
            CP_ASYNC16(sb + ROFF_ALO + r * RA_STR + seg * 16, hl + go);
        }
        {
            const float* zxrow = g_ZX + ((size_t)n_up * 128 + w) * 2048 + dir * 1024 + j0;
#pragma unroll
            for (int g = 0; g < 4; g++)
                CP_ASYNC16(sb + (ROFF_ZX - 0) + r_up * 256 + g * 64 + c_up * 4,
                           zxrow + g * 256 + c_up);
        }
        CP_COMMIT();

        float acc[4][4];
#pragma unroll
        for (int nf = 0; nf < 4; nf++)
#pragma unroll
            for (int r = 0; r < 4; r++) acc[nf][r] = 0.0f;

        // ---- first half (k 0..127) while second half lands ----
        CP_WAIT1();
        __syncthreads();
#pragma unroll
        for (int ks = 0; ks < 8; ks++) {
            const uint32_t kb = ks * 32;
            uint32_t ah[4], al[4], bh[4][2], bl[4][2], t4[4];
            ldmx4(ah, sb + a_off + kb);
            ldmx4(al, sb + ROFF_ALO + a_off + kb);
#pragma unroll
            for (int nh = 0; nh < 2; nh++) {
                ldmx4(t4, sb + ROFF_BHI + b_off + kb + nh * 16 * RA_STR);
                bh[2 * nh][0] = t4[0]; bh[2 * nh][1] = t4[1];
                bh[2 * nh + 1][0] = t4[2]; bh[2 * nh + 1][1] = t4[3];
                ldmx4(t4, sb + ROFF_BLO + b_off + kb + nh * 16 * RA_STR);
                bl[2 * nh][0] = t4[0]; bl[2 * nh][1] = t4[1];
                bl[2 * nh + 1][0] = t4[2]; bl[2 * nh + 1][1] = t4[3];
            }
#pragma unroll
            for (int nf = 0; nf < 4; nf++) {
                mma_bf16(acc[nf], ah, bh[nf]);
                mma_bf16(acc[nf], ah, bl[nf]);
                mma_bf16(acc[nf], al, bh[nf]);
            }
        }
        // ---- second half (k 128..255) ----
        CP_WAIT0();
        __syncthreads();
#pragma unroll
        for (int ks = 8; ks < 16; ks++) {
            const uint32_t kb = ks * 32;
            uint32_t ah[4], al[4], bh[4][2], bl[4][2], t4[4];
            ldmx4(ah, sb + a_off + kb);
            ldmx4(al, sb + ROFF_ALO + a_off + kb);
#pragma unroll
            for (int nh = 0; nh < 2; nh++) {
                ldmx4(t4, sb + ROFF_BHI + b_off + kb + nh * 16 * RA_STR);
                bh[2 * nh][0] = t4[0]; bh[2 * nh][1] = t4[1];
                bh[2 * nh + 1][0] = t4[2]; bh[2 * nh + 1][1] = t4[3];
                ldmx4(t4, sb + ROFF_BLO + b_off + kb + nh * 16 * RA_STR);
                bl[2 * nh][0] = t4[0]; bl[2 * nh][1] = t4[1];
                bl[2 * nh + 1][0] = t4[2]; bl[2 * nh + 1][1] = t4[3];
            }
#pragma unroll
            for (int nf = 0; nf < 4; nf++) {
                mma_bf16(acc[nf], ah, bh[nf]);
                mma_bf16(acc[nf], ah, bl[nf]);
                mma_bf16(acc[nf], al, bh[nf]);
            }
        }

        {
            const int qr = lane >> 2, qc = (lane & 3) << 1;
#pragma unroll
            for (int nf = 0; nf < 4; nf++) {
                const int col = wn * 32 + nf * 8 + qc;
                stg[(wm * 16 + qr) * 68 + col]     = acc[nf][0];
                stg[(wm * 16 + qr) * 68 + col + 1] = acc[nf][1];
                stg[(wm * 16 + qr + 8) * 68 + col]     = acc[nf][2];
                stg[(wm * 16 + qr + 8) * 68 + col + 1] = acc[nf][3];
            }
        }
        __syncthreads();

        {
            __nv_bfloat16* dhh = &g_Hhi[pb ^ 1][(size_t)Rr * 256 + j0 + c_up];
            __nv_bfloat16* dhl = &g_Hlo[pb ^ 1][(size_t)Rr * 256 + j0 + c_up];
            const size_t hsoff = ((size_t)n_up * 128 + w) * 512 + dir * 256 + j0 + c_up;
            const float* zx = &zxs[r_up * 64 + c_up];
            float hv[4];
#pragma unroll
            for (int l = 0; l < 4; l++) {
                const float* sr = &stg[r_up * 68 + c_up + l];
                const float zi = sr[0]  + zx[l];
                const float zf = sr[16] + zx[16 + l];
                const float zg = sr[32] + zx[32 + l];
                const float zo = sr[48] + zx[48 + l];
                const float cn = hsig(zf) * creg[l] + hsig(zi) * tanhf(zg);
                creg[l] = cn;
                hv[l] = hsig(zo) * tanhf(cn);
            }
            __nv_bfloat16 hh2[4], hl2[4];
#pragma unroll
            for (int l = 0; l < 4; l++) {
                hh2[l] = __float2bfloat16_rn(hv[l]);
                hl2[l] = __float2bfloat16_rn(hv[l] - __bfloat162float(hh2[l]));
            }
            *(__nv_bfloat162*)(dhh)     = __nv_bfloat162(hh2[0], hh2[1]);
            *(__nv_bfloat162*)(dhh + 2) = __nv_bfloat162(hh2[2], hh2[3]);
            *(__nv_bfloat162*)(dhl)     = __nv_bfloat162(hl2[0], hl2[1]);
            *(__nv_bfloat162*)(dhl + 2) = __nv_bfloat162(hl2[2], hl2[3]);
            *(__nv_bfloat162*)(g_HShi + hsoff)     = __nv_bfloat162(hh2[0], hh2[1]);
            *(__nv_bfloat162*)(g_HShi + hsoff + 2) = __nv_bfloat162(hh2[2], hh2[3]);
            *(__nv_bfloat162*)(g_HSlo + hsoff)     = __nv_bfloat162(hl2[0], hl2[1]);
            *(__nv_bfloat162*)(g_HSlo + hsoff + 2) = __nv_bfloat162(hl2[2], hl2[3]);
        }

        if (t < 127) group_barrier(tile_m);
    }
}

// ---------------- LayerNorm over (W,C)=65536, optional fused bf16 split (stride 1024) ----------------
__global__ __launch_bounds__(256) void ln_kernel(
    const float* __restrict__ pre, const float* __restrict__ xres,
    const float* __restrict__ gamma, const float* __restrict__ beta,
    float* __restrict__ out, __nv_bfloat16* __restrict__ shi,
    __nv_bfloat16* __restrict__ slo, int mode)
{
    __shared__ float red[256];
    const int tid = threadIdx.x;
    const size_t base = (size_t)blockIdx.x * 65536;

    float s = 0.0f, ss = 0.0f;
    for (int i = tid * 4; i < 65536; i += 1024) {
        float4 v = *(const float4*)(pre + base + i);
        s  += v.x + v.y + v.z + v.w;
        ss += v.x * v.x + v.y * v.y + v.z * v.z + v.w * v.w;
    }
    red[tid] = s; __syncthreads();
    for (int off = 128; off; off >>= 1) { if (tid < off) red[tid] += red[tid + off]; __syncthreads(); }
    const float mean = red[0] * (1.0f / 65536.0f);
    __syncthreads();
    red[tid] = ss; __syncthreads();
    for (int off = 128; off; off >>= 1) { if (tid < off) red[tid] += red[tid + off]; __syncthreads(); }
    const float var = red[0] * (1.0f / 65536.0f) - mean * mean;
    const float rstd = rsqrtf(var + 1e-3f);

    for (int i = tid * 4; i < 65536; i += 1024) {
        float4 v = *(const float4*)(pre + base + i);
        float4 g = *(const float4*)(gamma + i);
        float4 bb = *(const float4*)(beta + i);
        float4 r;
        r.x = (v.x - mean) * rstd * g.x + bb.x;
        r.y = (v.y - mean) * rstd * g.y + bb.y;
        r.z = (v.z - mean) * rstd * g.z + bb.z;
        r.w = (v.w - mean) * rstd * g.w + bb.w;
        if (mode == 0) {
            float4 xr = *(const float4*)(xres + base + i);
            r.x += xr.x; r.y += xr.y; r.z += xr.z; r.w += xr.w;
        } else {
            float4 o = *(const float4*)(out + base + i);
            r.x += o.x; r.y += o.y; r.z += o.z; r.w += o.w;
        }
        *(float4*)(out + base + i) = r;
        if (shi) {
            const size_t f = base + i;
            const size_t so = (f >> 9) * 1024 + (f & 511);
            float fv[4] = {r.x, r.y, r.z, r.w};
            __nv_bfloat16 h[4], l[4];
#pragma unroll
            for (int k = 0; k < 4; k++) {
                h[k] = __float2bfloat16_rn(fv[k]);
                l[k] = __float2bfloat16_rn(fv[k] - __bfloat162float(h[k]));
            }
            *(__nv_bfloat162*)(shi + so)     = __nv_bfloat162(h[0], h[1]);
            *(__nv_bfloat162*)(shi + so + 2) = __nv_bfloat162(h[2], h[3]);
            *(__nv_bfloat162*)(slo + so)     = __nv_bfloat162(l[0], l[1]);
            *(__nv_bfloat162*)(slo + so + 2) = __nv_bfloat162(l[2], l[3]);
        }
    }
}

// ---------------- launch ----------------
extern "C" void kernel_launch(void* const* d_in, const int* in_sizes, int n_in,
                              void* d_out, int out_size)
{
    const float* x    = (const float*)d_in[0];
    const float* h0   = (const float*)d_in[1];
    const float* c0   = (const float*)d_in[2];
    const float* Wf   = (const float*)d_in[3];
    const float* Uf   = (const float*)d_in[4];
    const float* bf   = (const float*)d_in[5];
    const float* Wb   = (const float*)d_in[6];
    const float* Ub   = (const float*)d_in[7];
    const float* bb   = (const float*)d_in[8];
    const float* Wfc1 = (const float*)d_in[9];
    const float* bfc1 = (const float*)d_in[10];
    const float* g1   = (const float*)d_in[11];
    const float* b1   = (const float*)d_in[12];
    const float* Wi   = (const float*)d_in[13];
    const float* Ui   = (const float*)d_in[14];
    const float* bi   = (const float*)d_in[15];
    const float* Wfc2 = (const float*)d_in[16];
    const float* bfc2 = (const float*)d_in[17];
    const float* g2   = (const float*)d_in[18];
    const float* b2   = (const float*)d_in[19];

    float* out = (float*)d_out;
    float* h_out = out + OUT0;
    float* c_out = out + 2 * OUT0;
    const int full_out = (out_size >= (int)(3 * OUT0)) || out_size <= 0;

    float *zx, *fc, *bfc, *biP;
    __nv_bfloat16 *ahi, *alo, *bthi, *btlo, *uthi, *utlo, *hshi, *hslo;
    cudaGetSymbolAddress((void**)&zx,  g_ZX);
    cudaGetSymbolAddress((void**)&fc,  g_FC);
    cudaGetSymbolAddress((void**)&bfc, g_bfc);
    cudaGetSymbolAddress((void**)&biP, g_biP);
    cudaGetSymbolAddress((void**)&ahi, g_Ahi);
    cudaGetSymbolAddress((void**)&alo, g_Alo);
    cudaGetSymbolAddress((void**)&bthi, g_Bthi);
    cudaGetSymbolAddress((void**)&btlo, g_Btlo);
    cudaGetSymbolAddress((void**)&uthi, g_Uthi);
    cudaGetSymbolAddress((void**)&utlo, g_Utlo);
    cudaGetSymbolAddress((void**)&hshi, g_HShi);
    cudaGetSymbolAddress((void**)&hslo, g_HSlo);

    cudaFuncSetAttribute(tcgemm, cudaFuncAttributeMaxDynamicSharedMemorySize, GEMM_SMEM);
    cudaFuncSetAttribute(tcgemm_gates, cudaFuncAttributeMaxDynamicSharedMemorySize, GEMM_SMEM);
    cudaFuncSetAttribute(recurrence2, cudaFuncAttributeMaxDynamicSharedMemorySize, RSMEM);

    const int n4A = MROWS * 512 / 4;

    // ---- combined intra input projection: ZX = x @ [Wf|Wb] + [bf|bb] ----
    split_kernel<<<n4A / 256, 256>>>(x, ahi, alo, n4A);
    bias_prep<<<16, 256>>>(bf, bb, bi, bfc, biP);
    splitT_kernel<<<dim3(32, 16), dim3(32, 8)>>>(Wf, bthi, btlo, 512, 1024);
    splitT_kernel<<<dim3(32, 16), dim3(32, 8)>>>(Wb, bthi + (size_t)1024 * 512, btlo + (size_t)1024 * 512, 512, 1024);
    tcgemm<<<dim3(16, 256), 256, GEMM_SMEM>>>(ahi, alo, bthi, btlo, zx, bfc, MROWS, 2048, 512, 0);

    // ---- recurrent weights + recurrence ----
    splitT_kernel<<<dim3(32, 8), dim3(32, 8)>>>(Uf, uthi, utlo, 256, 1024);
    splitT_kernel<<<dim3(32, 8), dim3(32, 8)>>>(Ub, uthi + 1024 * 256, utlo + 1024 * 256, 256, 1024);
    recurrence2<<<128, 256, RSMEM>>>(uthi, utlo);

    // ---- fc1 ----
    splitT_kernel<<<dim3(16, 16), dim3(32, 8)>>>(Wfc1, bthi, btlo, 512, 512);
    tcgemm<<<dim3(4, 256), 256, GEMM_SMEM>>>(hshi, hslo, bthi, btlo, fc, bfc1, MROWS, 512, 512, 0);

    // ---- LN1 + residual -> out, fused split (concat A cols 0..511) ----
    ln_kernel<<<256, 256>>>(fc, x, g1, b1, out, ahi, alo, 0);

    // ---- inter: single K=1024 GEMM with fused gates ----
    split_off_kernel<<<16384, 256>>>(h0, ahi, alo);
    splitT_perm_kernel<<<dim3(64, 16), dim3(32, 8)>>>(Wi, bthi, btlo, 2048, 1024, 0);
    splitT_perm_kernel<<<dim3(64, 16), dim3(32, 8)>>>(Ui, bthi, btlo, 2048, 1024, 512);
    float* hptr = full_out ? h_out : (zx);
    float* cptr = full_out ? c_out : (zx + (size_t)MROWS * 512);
    tcgemm_gates<<<dim3(16, 256), 256, GEMM_SMEM>>>(ahi, alo, bthi, btlo, biP, c0,
                                                    hptr, cptr, hshi, hslo, 1024);

    // ---- fc2 ----
    splitT_kernel<<<dim3(16, 16), dim3(32, 8)>>>(Wfc2, bthi, btlo, 512, 512);
    tcgemm<<<dim3(4, 256), 256, GEMM_SMEM>>>(hshi, hslo, bthi, btlo, fc, bfc2, MROWS, 512, 512, 0);

    // ---- LN2 accumulate into out ----
    ln_kernel<<<256, 256>>>(fc, nullptr, g2, b2, out, nullptr, nullptr, 1);
}

// round 7
// speedup vs baseline: 3.9244x; 1.3420x over previous
#include <cuda_runtime.h>
#include <cuda_fp16.h>
#include <cstdint>
#include <math.h>

// Problem constants
#define NSAMP 256            // B*L
#define W_    128
#define C_    512
#define HD_   256
#define MROWS 32768          // B*W
#define OUT0  ((size_t)16777216)   // B*L*W*C

// ---------------- scratch (static device globals; no allocations) ----------------
__device__ float g_ZX [(size_t)MROWS * 2048];   // combined intra projections (fwd|bwd)
__device__ float g_FC [(size_t)MROWS * 512];
__device__ float g_bfc[2048];
__device__ float g_biP[2048];
__device__ unsigned long long g_barG[8 * 16];   // per-group monotonic tickets

// fp16 split buffers: A side hi-only; B side hi+lo
__device__ __half g_Ah [(size_t)MROWS * 1024];
__device__ __half g_Bthi[(size_t)2048 * 1024];
__device__ __half g_Btlo[(size_t)2048 * 1024];
// recurrence state / weights / outputs (fp16)
__device__ __half g_Hh[2][512 * 256];
__device__ __half g_Uthi[(size_t)2048 * 256];
__device__ __half g_Utlo[(size_t)2048 * 256];
__device__ __half g_HSh[(size_t)MROWS * 512];

__device__ __forceinline__ float hsig(float x) {
    return fminf(fmaxf(fmaf(0.2f, x, 0.5f), 0.0f), 1.0f);
}

// ================= low-level helpers (sm_80-baseline ISA only) =================
__device__ __forceinline__ uint32_t smem_u32(const void* p) {
    uint32_t a;
    asm("{ .reg .u64 t; cvta.to.shared.u64 t, %1; cvt.u32.u64 %0, t; }" : "=r"(a) : "l"(p));
    return a;
}
#define CP_ASYNC16(dst, src) \
    asm volatile("cp.async.cg.shared.global [%0], [%1], 16;" :: "r"(dst), "l"(src) : "memory")
#define CP_COMMIT() asm volatile("cp.async.commit_group;" ::: "memory")
#define CP_WAIT1()  asm volatile("cp.async.wait_group 1;" ::: "memory")
#define CP_WAIT0()  asm volatile("cp.async.wait_group 0;" ::: "memory")

__device__ __forceinline__ void ldmx4(uint32_t* r, uint32_t addr) {
    asm volatile("ldmatrix.sync.aligned.m8n8.x4.shared.b16 {%0,%1,%2,%3}, [%4];"
        : "=r"(r[0]), "=r"(r[1]), "=r"(r[2]), "=r"(r[3]) : "r"(addr));
}
__device__ __forceinline__ void mma_f16(float* d, const uint32_t* a, const uint32_t* b) {
    asm volatile("mma.sync.aligned.m16n8k16.row.col.f32.f16.f16.f32 "
        "{%0,%1,%2,%3}, {%4,%5,%6,%7}, {%8,%9}, {%0,%1,%2,%3};"
        : "+f"(d[0]), "+f"(d[1]), "+f"(d[2]), "+f"(d[3])
        : "r"(a[0]), "r"(a[1]), "r"(a[2]), "r"(a[3]), "r"(b[0]), "r"(b[1]));
}

// ================= 2-product fp16 tensor-core GEMM =================
// C[M,N] = Ah[M,K] @ (Bhi+Blo)[N,K]^T (+bias) (+=C). Error = (A - fp16(A))·B ~ 2^-11.
#define TILE_B   10240           // 128*80
#define STG_B    30720           // 3 tiles (Ah, Bhi, Blo)
#define GEMM_SMEM  61440
#define GATES_SMEM 67584         // mainloop 61440, epilogue stg 128*132*4

__device__ __forceinline__ void load_chunk(uint32_t stage_base,
    const __half* __restrict__ Ah, const __half* __restrict__ Bhi,
    const __half* __restrict__ Blo, int m0, int n0, int kk, int K, int tid)
{
#pragma unroll
    for (int i = 0; i < 2; i++) {
        const int c = tid + i * 256;
        const int row = c >> 2;
        const int seg = c & 3;
        const uint32_t doff = (uint32_t)(row * 80 + seg * 16);
        const size_t akoff = (size_t)kk + seg * 8;
        CP_ASYNC16(stage_base + 0 * TILE_B + doff, Ah  + (size_t)(m0 + row) * K + akoff);
        CP_ASYNC16(stage_base + 1 * TILE_B + doff, Bhi + (size_t)(n0 + row) * K + akoff);
        CP_ASYNC16(stage_base + 2 * TILE_B + doff, Blo + (size_t)(n0 + row) * K + akoff);
    }
}

#define GEMM_MAINLOOP(Ah, Bhi, Blo, m0, n0, K, acc)                               \
    {                                                                             \
        const int NC = (K) >> 5;                                                  \
        load_chunk(sb, Ah, Bhi, Blo, m0, n0, 0, K, tid);                          \
        CP_COMMIT();                                                              \
        load_chunk(sb + STG_B, Ah, Bhi, Blo, m0, n0, 32, K, tid);                 \
        CP_COMMIT();                                                              \
        for (int c = 0; c < NC; c++) {                                            \
            CP_WAIT1();                                                           \
            __syncthreads();                                                      \
            const uint32_t st = sb + (c & 1) * STG_B;                             \
            _Pragma("unroll")                                                     \
            for (int ks = 0; ks < 2; ks++) {                                      \
                const uint32_t kb = st + ks * 32;                                 \
                uint32_t af[4][4], bhf[4][2], blf[4][2], t4[4];                   \
                _Pragma("unroll")                                                 \
                for (int nh = 0; nh < 2; nh++) {                                  \
                    ldmx4(t4, kb + 1 * TILE_B + b_off + nh * 1280);               \
                    bhf[2*nh][0] = t4[0]; bhf[2*nh][1] = t4[1];                   \
                    bhf[2*nh+1][0] = t4[2]; bhf[2*nh+1][1] = t4[3];               \
                    ldmx4(t4, kb + 2 * TILE_B + b_off + nh * 1280);               \
                    blf[2*nh][0] = t4[0]; blf[2*nh][1] = t4[1];                   \
                    blf[2*nh+1][0] = t4[2]; blf[2*nh+1][1] = t4[3];               \
                }                                                                 \
                _Pragma("unroll")                                                 \
                for (int mf = 0; mf < 4; mf++) ldmx4(af[mf], kb + a_off + mf * 1280); \
                _Pragma("unroll")                                                 \
                for (int mf = 0; mf < 4; mf++)                                    \
                    _Pragma("unroll")                                             \
                    for (int nf = 0; nf < 4; nf++) {                              \
                        mma_f16(acc[mf][nf], af[mf], bhf[nf]);                    \
                        mma_f16(acc[mf][nf], af[mf], blf[nf]);                    \
                    }                                                             \
            }                                                                     \
            __syncthreads();                                                      \
            if (c + 2 < NC)                                                       \
                load_chunk(sb + (c & 1) * STG_B, Ah, Bhi, Blo, m0, n0, (c + 2) << 5, K, tid); \
            CP_COMMIT();                                                          \
        }                                                                         \
    }

__global__ __launch_bounds__(256, 2) void tcgemm(
    const __half* __restrict__ Ah, const __half* __restrict__ Bhi,
    const __half* __restrict__ Blo,
    float* __restrict__ Cmat, const float* __restrict__ bias,
    int M, int N, int K, int accumulate)
{
    extern __shared__ __align__(128) char smem_raw[];
    const uint32_t sb = smem_u32(smem_raw);

    const int tid = threadIdx.x;
    const int lane = tid & 31;
    const int wid = tid >> 5;
    const int wm = wid >> 2;
    const int wn = wid & 3;
    const int m0 = blockIdx.y << 7;
    const int n0 = blockIdx.x << 7;

    const uint32_t a_off = (uint32_t)((wm * 64 + (lane & 15)) * 80 + (lane >> 4) * 16);
    const int bsub = lane >> 3;
    const uint32_t b_off = (uint32_t)((wn * 32 + ((bsub >> 1) << 3) + (lane & 7)) * 80 + (bsub & 1) * 16);

    float acc[4][4][4];
#pragma unroll
    for (int mf = 0; mf < 4; mf++)
#pragma unroll
        for (int nf = 0; nf < 4; nf++)
#pragma unroll
            for (int r = 0; r < 4; r++) acc[mf][nf][r] = 0.0f;

    GEMM_MAINLOOP(Ah, Bhi, Blo, m0, n0, K, acc);

    const int qr = lane >> 2;
    const int qc = (lane & 3) << 1;
#pragma unroll
    for (int mf = 0; mf < 4; mf++) {
        const int row = m0 + wm * 64 + mf * 16 + qr;
#pragma unroll
        for (int nf = 0; nf < 4; nf++) {
            const int col = n0 + wn * 32 + nf * 8 + qc;
            float2 v0 = make_float2(acc[mf][nf][0], acc[mf][nf][1]);
            float2 v1 = make_float2(acc[mf][nf][2], acc[mf][nf][3]);
            if (bias) {
                const float2 bv = *(const float2*)(bias + col);
                v0.x += bv.x; v0.y += bv.y; v1.x += bv.x; v1.y += bv.y;
            }
            float* p0 = Cmat + (size_t)row * N + col;
            float* p1 = p0 + 8 * (size_t)N;
            if (accumulate) {
                const float2 o0 = *(const float2*)p0;
                const float2 o1 = *(const float2*)p1;
                v0.x += o0.x; v0.y += o0.y; v1.x += o1.x; v1.y += o1.y;
            }
            *(float2*)p0 = v0;
            *(float2*)p1 = v1;
        }
    }
}

// ---- inter GEMM with fused LSTM gate epilogue (gate-interleaved B layout) ----
__global__ __launch_bounds__(256, 2) void tcgemm_gates(
    const __half* __restrict__ Ah, const __half* __restrict__ Bhi,
    const __half* __restrict__ Blo,
    const float* __restrict__ biasP, const float* __restrict__ c0,
    float* __restrict__ h_out, float* __restrict__ c_out,
    __half* __restrict__ hh_out, int K)
{
    extern __shared__ __align__(128) char smem_raw[];
    const uint32_t sb = smem_u32(smem_raw);

    const int tid = threadIdx.x;
    const int lane = tid & 31;
    const int wid = tid >> 5;
    const int wm = wid >> 2;
    const int wn = wid & 3;
    const int m0 = blockIdx.y << 7;
    const int n0 = blockIdx.x << 7;
    const int hid0 = blockIdx.x << 5;

    const uint32_t a_off = (uint32_t)((wm * 64 + (lane & 15)) * 80 + (lane >> 4) * 16);
    const int bsub = lane >> 3;
    const uint32_t b_off = (uint32_t)((wn * 32 + ((bsub >> 1) << 3) + (lane & 7)) * 80 + (bsub & 1) * 16);

    float acc[4][4][4];
#pragma unroll
    for (int mf = 0; mf < 4; mf++)
#pragma unroll
        for (int nf = 0; nf < 4; nf++)
#pragma unroll
            for (int r = 0; r < 4; r++) acc[mf][nf][r] = 0.0f;

    GEMM_MAINLOOP(Ah, Bhi, Blo, m0, n0, K, acc);

    __syncthreads();
    float* stg = (float*)smem_raw;    // 128 x 132
    const int qr = lane >> 2;
    const int qc = (lane & 3) << 1;
#pragma unroll
    for (int mf = 0; mf < 4; mf++) {
        const int rl = wm * 64 + mf * 16 + qr;
#pragma unroll
        for (int nf = 0; nf < 4; nf++) {
            const int col = wn * 32 + nf * 8 + qc;
            const float2 bv = *(const float2*)(biasP + n0 + col);
            stg[rl * 132 + col]           = acc[mf][nf][0] + bv.x;
            stg[rl * 132 + col + 1]       = acc[mf][nf][1] + bv.y;
            stg[(rl + 8) * 132 + col]     = acc[mf][nf][2] + bv.x;
            stg[(rl + 8) * 132 + col + 1] = acc[mf][nf][3] + bv.y;
        }
    }
    __syncthreads();

    {
        const int c = lane;
#pragma unroll
        for (int i = 0; i < 16; i++) {
            const int r = wid * 16 + i;
            const float zi = stg[r * 132 + c];
            const float zf = stg[r * 132 + 32 + c];
            const float zg = stg[r * 132 + 64 + c];
            const float zo = stg[r * 132 + 96 + c];
            const size_t go = (size_t)(m0 + r) * 512 + hid0 + c;
            const float cn = hsig(zf) * c0[go] + hsig(zi) * tanhf(zg);
            const float hv = hsig(zo) * tanhf(cn);
            c_out[go] = cn;
            h_out[go] = hv;
            hh_out[go] = __float2half_rn(hv);
        }
    }
}

// ================= convert / split kernels =================
// fp32 -> fp16 (hi only), contiguous
__global__ __launch_bounds__(256) void cvt_kernel(
    const float* __restrict__ in, __half* __restrict__ out, int n4)
{
    const int i = blockIdx.x * blockDim.x + threadIdx.x;
    if (i >= n4) return;
    const float4 v = ((const float4*)in)[i];
    __half2 a = __half2(__float2half_rn(v.x), __float2half_rn(v.y));
    __half2 b = __half2(__float2half_rn(v.z), __float2half_rn(v.w));
    ((__half2*)out)[2 * i] = a;
    ((__half2*)out)[2 * i + 1] = b;
}

// h0 [32768,512] -> g_Ah at row*1024 + 512 + col (concat A for inter GEMM)
__global__ __launch_bounds__(256) void cvt_off_kernel(
    const float* __restrict__ in, __half* __restrict__ out)
{
    const int q = blockIdx.x * blockDim.x + threadIdx.x;
    const int row = q >> 7;
    const int col = (q & 127) << 2;
    const float4 v = ((const float4*)in)[q];
    const size_t o = (size_t)row * 1024 + 512 + col;
    *(__half2*)(out + o)     = __half2(__float2half_rn(v.x), __float2half_rn(v.y));
    *(__half2*)(out + o + 2) = __half2(__float2half_rn(v.z), __float2half_rn(v.w));
}

// transpose-split: W [K,N] fp32 -> hi/lo [N,K] fp16
__global__ void splitT_kernel(const float* __restrict__ Wm,
                              __half* __restrict__ hi, __half* __restrict__ lo,
                              int K, int N)
{
    __shared__ float t[32][33];
    const int kb = blockIdx.y * 32, nb = blockIdx.x * 32;
    const int tx = threadIdx.x, ty = threadIdx.y;
    for (int r = ty; r < 32; r += 8)
        t[r][tx] = Wm[(size_t)(kb + r) * N + nb + tx];
    __syncthreads();
    for (int r = ty; r < 32; r += 8) {
        const float v = t[tx][r];
        const __half h = __float2half_rn(v);
        const __half l = __float2half_rn(v - __half2float(h));
        hi[(size_t)(nb + r) * K + kb + tx] = h;
        lo[(size_t)(nb + r) * K + kb + tx] = l;
    }
}

// transpose-split with gate-interleave permutation; writes [2048, Kout] at koff
__global__ void splitT_perm_kernel(const float* __restrict__ Wm,
                                   __half* __restrict__ hi, __half* __restrict__ lo,
                                   int N, int Kout, int koff)
{
    __shared__ float t[32][33];
    const int kb = blockIdx.y * 32, nb = blockIdx.x * 32;
    const int tx = threadIdx.x, ty = threadIdx.y;
    for (int r = ty; r < 32; r += 8)
        t[r][tx] = Wm[(size_t)(kb + r) * N + nb + tx];
    __syncthreads();
    for (int r = ty; r < 32; r += 8) {
        const float v = t[tx][r];
        const int n = nb + r;
        const int g = n >> 9, s = n & 511;
        const int nr = ((s >> 5) << 7) + (g << 5) + (s & 31);
        const __half h = __float2half_rn(v);
        const __half l = __float2half_rn(v - __half2float(h));
        hi[(size_t)nr * Kout + koff + kb + tx] = h;
        lo[(size_t)nr * Kout + koff + kb + tx] = l;
    }
}

// bias prep: bfc = [bf|bb]; biP = gate-permuted bi
__global__ void bias_prep(const float* __restrict__ bf, const float* __restrict__ bb,
                          const float* __restrict__ bi,
                          float* __restrict__ bfc, float* __restrict__ biP)
{
    const int i = blockIdx.x * blockDim.x + threadIdx.x;
    if (i < 1024) bfc[i] = bf[i];
    else if (i < 2048) bfc[i] = bb[i - 1024];
    else {
        const int n = i - 2048;
        const int g = n >> 9, s = n & 511;
        const int nr = ((s >> 5) << 7) + (g << 5) + (s & 31);
        biP[nr] = bi[n];
    }
}

// ---------------- group barrier (16 CTAs per group) ----------------
__device__ __forceinline__ void group_barrier(int grp) {
    __threadfence();
    __syncthreads();
    if (threadIdx.x == 0) {
        unsigned long long* ctr = &g_barG[grp * 16];
        unsigned long long t = atomicAdd(ctr, 1ULL) + 1ULL;
        unsigned long long target = ((t + 15ULL) >> 4) << 4;
        volatile unsigned long long* p = ctr;
        while (*p < target) { __nanosleep(32); }
        __threadfence();
    }
    __syncthreads();
}

// ---------------- persistent bidirectional LSTM recurrence (fp16, 2-product) ----------------
#define RA_STR   528
#define ROFF_BHI 33792
#define ROFF_BLO 67584
#define ROFF_STG 101376
#define ROFF_ZX  118784
#define RSMEM    135168

__global__ __launch_bounds__(256) void recurrence2(
    const __half* __restrict__ Uthi, const __half* __restrict__ Utlo)
{
    extern __shared__ __align__(128) char rsm[];
    const uint32_t sb = smem_u32(rsm);
    const int tid = threadIdx.x, lane = tid & 31, wid = tid >> 5;
    const int blk = blockIdx.x;
    const int tile_m = blk >> 4;         // 0..7 (= barrier group)
    const int tile_n = blk & 15;
    const int row0 = tile_m << 6;
    const int dir = (tile_m >= 4) ? 1 : 0;
    const int j0 = tile_n << 4;
    const int wm = wid & 3, wn = wid >> 2;

    // U^T slice resident: 64 rows (gate*16+c) x 256 k, hi+lo
    for (int i = tid; i < 2048; i += 256) {
        const int r = i >> 5, seg = i & 31;
        const int g = r >> 4, c = r & 15;
        const size_t gr = ((size_t)(dir * 1024 + g * 256 + j0 + c)) * 256 + seg * 8;
        *(uint4*)(rsm + ROFF_BHI + r * RA_STR + seg * 16) = *(const uint4*)(Uthi + gr);
        *(uint4*)(rsm + ROFF_BLO + r * RA_STR + seg * 16) = *(const uint4*)(Utlo + gr);
    }

    if (tile_n == 0) {
        uint32_t* h0 = (uint32_t*)&g_Hh[0][row0 * 256];
        for (int i = tid; i < 8192; i += 256) h0[i] = 0u;
    }

    const uint32_t a_off = (uint32_t)((wm * 16 + (lane & 15)) * RA_STR + (lane >> 4) * 16);
    const int bsub = lane >> 3;
    const uint32_t b_off = (uint32_t)((wn * 32 + ((bsub >> 1) << 3) + (lane & 7)) * RA_STR + (bsub & 1) * 16);

    const int r_up = tid >> 2;
    const int c_up = (tid & 3) << 2;
    const int Rr = row0 + r_up;
    const int n_up = Rr & 255;
    float* stg = (float*)(rsm + ROFF_STG);
    float* zxs = (float*)(rsm + ROFF_ZX);
    float creg[4] = {0.0f, 0.0f, 0.0f, 0.0f};

    group_barrier(tile_m);

    for (int t = 0; t < 128; t++) {
        const int pb = t & 1;
        const int w = dir ? (127 - t) : t;
        const __half* hh = g_Hh[pb];

        // ---- commit group 1: H k 0..127 ----
#pragma unroll
        for (int ii = 0; ii < 4; ii++) {
            const int i = tid + ii * 256;
            const int r = i >> 4, seg = i & 15;
            CP_ASYNC16(sb + r * RA_STR + seg * 16, hh + (size_t)(row0 + r) * 256 + seg * 8);
        }
        CP_COMMIT();
        // ---- commit group 2: H k 128..255 + zx prefetch ----
#pragma unroll
        for (int ii = 0; ii < 4; ii++) {
            const int i = tid + ii * 256;
            const int r = i >> 4, seg = 16 + (i & 15);
            CP_ASYNC16(sb + r * RA_STR + seg * 16, hh + (size_t)(row0 + r) * 256 + seg * 8);
        }
        {
            const float* zxrow = g_ZX + ((size_t)n_up * 128 + w) * 2048 + dir * 1024 + j0;
#pragma unroll
            for (int g = 0; g < 4; g++)
                CP_ASYNC16(sb + ROFF_ZX + r_up * 256 + g * 64 + c_up * 4,
                           zxrow + g * 256 + c_up);
        }
        CP_COMMIT();

        float acc[4][4];
#pragma unroll
        for (int nf = 0; nf < 4; nf++)
#pragma unroll
            for (int r = 0; r < 4; r++) acc[nf][r] = 0.0f;

        // ---- first half (k 0..127) while second half lands ----
        CP_WAIT1();
        __syncthreads();
#pragma unroll
        for (int ks = 0; ks < 8; ks++) {
            const uint32_t kb = ks * 32;
            uint32_t ah[4], bh[4][2], bl[4][2], t4[4];
            ldmx4(ah, sb + a_off + kb);
#pragma unroll
            for (int nh = 0; nh < 2; nh++) {
                ldmx4(t4, sb + ROFF_BHI + b_off + kb + nh * 16 * RA_STR);
                bh[2 * nh][0] = t4[0]; bh[2 * nh][1] = t4[1];
                bh[2 * nh + 1][0] = t4[2]; bh[2 * nh + 1][1] = t4[3];
                ldmx4(t4, sb + ROFF_BLO + b_off + kb + nh * 16 * RA_STR);
                bl[2 * nh][0] = t4[0]; bl[2 * nh][1] = t4[1];
                bl[2 * nh + 1][0] = t4[2]; bl[2 * nh + 1][1] = t4[3];
            }
#pragma unroll
            for (int nf = 0; nf < 4; nf++) {
                mma_f16(acc[nf], ah, bh[nf]);
                mma_f16(acc[nf], ah, bl[nf]);
            }
        }
        // ---- second half (k 128..255) ----
        CP_WAIT0();
        __syncthreads();
#pragma unroll
        for (int ks = 8; ks < 16; ks++) {
            const uint32_t kb = ks * 32;
            uint32_t ah[4], bh[4][2], bl[4][2], t4[4];
            ldmx4(ah, sb + a_off + kb);
#pragma unroll
            for (int nh = 0; nh < 2; nh++) {
                ldmx4(t4, sb + ROFF_BHI + b_off + kb + nh * 16 * RA_STR);
                bh[2 * nh][0] = t4[0]; bh[2 * nh][1] = t4[1];
                bh[2 * nh + 1][0] = t4[2]; bh[2 * nh + 1][1] = t4[3];
                ldmx4(t4, sb + ROFF_BLO + b_off + kb + nh * 16 * RA_STR);
                bl[2 * nh][0] = t4[0]; bl[2 * nh][1] = t4[1];
                bl[2 * nh + 1][0] = t4[2]; bl[2 * nh + 1][1] = t4[3];
            }
#pragma unroll
            for (int nf = 0; nf < 4; nf++) {
                mma_f16(acc[nf], ah, bh[nf]);
                mma_f16(acc[nf], ah, bl[nf]);
            }
        }

        {
            const int qr = lane >> 2, qc = (lane & 3) << 1;
#pragma unroll
            for (int nf = 0; nf < 4; nf++) {
                const int col = wn * 32 + nf * 8 + qc;
                stg[(wm * 16 + qr) * 68 + col]     = acc[nf][0];
                stg[(wm * 16 + qr) * 68 + col + 1] = acc[nf][1];
                stg[(wm * 16 + qr + 8) * 68 + col]     = acc[nf][2];
                stg[(wm * 16 + qr + 8) * 68 + col + 1] = acc[nf][3];
            }
        }
        __syncthreads();

        {
            __half* dhh = &g_Hh[pb ^ 1][(size_t)Rr * 256 + j0 + c_up];
            const size_t hsoff = ((size_t)n_up * 128 + w) * 512 + dir * 256 + j0 + c_up;
            const float* zx = &zxs[r_up * 64 + c_up];
            float hv[4];
#pragma unroll
            for (int l = 0; l < 4; l++) {
                const float* sr = &stg[r_up * 68 + c_up + l];
                const float zi = sr[0]  + zx[l];
                const float zf = sr[16] + zx[16 + l];
                const float zg = sr[32] + zx[32 + l];
                const float zo = sr[48] + zx[48 + l];
                const float cn = hsig(zf) * creg[l] + hsig(zi) * tanhf(zg);
                creg[l] = cn;
                hv[l] = hsig(zo) * tanhf(cn);
            }
            const __half2 p0 = __half2(__float2half_rn(hv[0]), __float2half_rn(hv[1]));
            const __half2 p1 = __half2(__float2half_rn(hv[2]), __float2half_rn(hv[3]));
            *(__half2*)(dhh)     = p0;
            *(__half2*)(dhh + 2) = p1;
            *(__half2*)(g_HSh + hsoff)     = p0;
            *(__half2*)(g_HSh + hsoff + 2) = p1;
        }

        if (t < 127) group_barrier(tile_m);
    }
}

// ---------------- LayerNorm over (W,C)=65536, optional fused fp16 convert (stride 1024) ----------------
__global__ __launch_bounds__(256) void ln_kernel(
    const float* __restrict__ pre, const float* __restrict__ xres,
    const float* __restrict__ gamma, const float* __restrict__ beta,
    float* __restrict__ out, __half* __restrict__ sh, int mode)
{
    __shared__ float red[256];
    const int tid = threadIdx.x;
    const size_t base = (size_t)blockIdx.x * 65536;

    float s = 0.0f, ss = 0.0f;
    for (int i = tid * 4; i < 65536; i += 1024) {
        float4 v = *(const float4*)(pre + base + i);
        s  += v.x + v.y + v.z + v.w;
        ss += v.x * v.x + v.y * v.y + v.z * v.z + v.w * v.w;
    }
    red[tid] = s; __syncthreads();
    for (int off = 128; off; off >>= 1) { if (tid < off) red[tid] += red[tid + off]; __syncthreads(); }
    const float mean = red[0] * (1.0f / 65536.0f);
    __syncthreads();
    red[tid] = ss; __syncthreads();
    for (int off = 128; off; off >>= 1) { if (tid < off) red[tid] += red[tid + off]; __syncthreads(); }
    const float var = red[0] * (1.0f / 65536.0f) - mean * mean;
    const float rstd = rsqrtf(var + 1e-3f);

    for (int i = tid * 4; i < 65536; i += 1024) {
        float4 v = *(const float4*)(pre + base + i);
        float4 g = *(const float4*)(gamma + i);
        float4 bb = *(const float4*)(beta + i);
        float4 r;
        r.x = (v.x - mean) * rstd * g.x + bb.x;
        r.y = (v.y - mean) * rstd * g.y + bb.y;
        r.z = (v.z - mean) * rstd * g.z + bb.z;
        r.w = (v.w - mean) * rstd * g.w + bb.w;
        if (mode == 0) {
            float4 xr = *(const float4*)(xres + base + i);
            r.x += xr.x; r.y += xr.y; r.z += xr.z; r.w += xr.w;
        } else {
            float4 o = *(const float4*)(out + base + i);
            r.x += o.x; r.y += o.y; r.z += o.z; r.w += o.w;
        }
        *(float4*)(out + base + i) = r;
        if (sh) {
            const size_t f = base + i;
            const size_t so = (f >> 9) * 1024 + (f & 511);
            *(__half2*)(sh + so)     = __half2(__float2half_rn(r.x), __float2half_rn(r.y));
            *(__half2*)(sh + so + 2) = __half2(__float2half_rn(r.z), __float2half_rn(r.w));
        }
    }
}

// ---------------- launch ----------------
extern "C" void kernel_launch(void* const* d_in, const int* in_sizes, int n_in,
                              void* d_out, int out_size)
{
    const float* x    = (const float*)d_in[0];
    const float* h0   = (const float*)d_in[1];
    const float* c0   = (const float*)d_in[2];
    const float* Wf   = (const float*)d_in[3];
    const float* Uf   = (const float*)d_in[4];
    const float* bf   = (const float*)d_in[5];
    const float* Wb   = (const float*)d_in[6];
    const float* Ub   = (const float*)d_in[7];
    const float* bb   = (const float*)d_in[8];
    const float* Wfc1 = (const float*)d_in[9];
    const float* bfc1 = (const float*)d_in[10];
    const float* g1   = (const float*)d_in[11];
    const float* b1   = (const float*)d_in[12];
    const float* Wi   = (const float*)d_in[13];
    const float* Ui   = (const float*)d_in[14];
    const float* bi   = (const float*)d_in[15];
    const float* Wfc2 = (const float*)d_in[16];
    const float* bfc2 = (const float*)d_in[17];
    const float* g2   = (const float*)d_in[18];
    const float* b2   = (const float*)d_in[19];

    float* out = (float*)d_out;
    float* h_out = out + OUT0;
    float* c_out = out + 2 * OUT0;
    const int full_out = (out_size >= (int)(3 * OUT0)) || out_size <= 0;

    float *zx, *fc, *bfc, *biP;
    __half *ah, *bthi, *btlo, *uthi, *utlo, *hsh;
    cudaGetSymbolAddress((void**)&zx,  g_ZX);
    cudaGetSymbolAddress((void**)&fc,  g_FC);
    cudaGetSymbolAddress((void**)&bfc, g_bfc);
    cudaGetSymbolAddress((void**)&biP, g_biP);
    cudaGetSymbolAddress((void**)&ah,  g_Ah);
    cudaGetSymbolAddress((void**)&bthi, g_Bthi);
    cudaGetSymbolAddress((void**)&btlo, g_Btlo);
    cudaGetSymbolAddress((void**)&uthi, g_Uthi);
    cudaGetSymbolAddress((void**)&utlo, g_Utlo);
    cudaGetSymbolAddress((void**)&hsh, g_HSh);

    cudaFuncSetAttribute(tcgemm, cudaFuncAttributeMaxDynamicSharedMemorySize, GEMM_SMEM);
    cudaFuncSetAttribute(tcgemm_gates, cudaFuncAttributeMaxDynamicSharedMemorySize, GATES_SMEM);
    cudaFuncSetAttribute(recurrence2, cudaFuncAttributeMaxDynamicSharedMemorySize, RSMEM);

    const int n4A = MROWS * 512 / 4;

    // ---- combined intra input projection: ZX = x @ [Wf|Wb] + [bf|bb] ----
    cvt_kernel<<<n4A / 256, 256>>>(x, ah, n4A);
    bias_prep<<<16, 256>>>(bf, bb, bi, bfc, biP);
    splitT_kernel<<<dim3(32, 16), dim3(32, 8)>>>(Wf, bthi, btlo, 512, 1024);
    splitT_kernel<<<dim3(32, 16), dim3(32, 8)>>>(Wb, bthi + (size_t)1024 * 512, btlo + (size_t)1024 * 512, 512, 1024);
    tcgemm<<<dim3(16, 256), 256, GEMM_SMEM>>>(ah, bthi, btlo, zx, bfc, MROWS, 2048, 512, 0);

    // ---- recurrent weights + recurrence ----
    splitT_kernel<<<dim3(32, 8), dim3(32, 8)>>>(Uf, uthi, utlo, 256, 1024);
    splitT_kernel<<<dim3(32, 8), dim3(32, 8)>>>(Ub, uthi + 1024 * 256, utlo + 1024 * 256, 256, 1024);
    recurrence2<<<128, 256, RSMEM>>>(uthi, utlo);

    // ---- fc1 (A = HS hi) ----
    splitT_kernel<<<dim3(16, 16), dim3(32, 8)>>>(Wfc1, bthi, btlo, 512, 512);
    tcgemm<<<dim3(4, 256), 256, GEMM_SMEM>>>(hsh, bthi, btlo, fc, bfc1, MROWS, 512, 512, 0);

    // ---- LN1 + residual -> out, fused convert (concat A cols 0..511) ----
    ln_kernel<<<256, 256>>>(fc, x, g1, b1, out, ah, 0);

    // ---- inter: single K=1024 GEMM with fused gates (h hi -> g_HSh, no races) ----
    cvt_off_kernel<<<16384, 256>>>(h0, ah);
    splitT_perm_kernel<<<dim3(64, 16), dim3(32, 8)>>>(Wi, bthi, btlo, 2048, 1024, 0);
    splitT_perm_kernel<<<dim3(64, 16), dim3(32, 8)>>>(Ui, bthi, btlo, 2048, 1024, 512);
    float* hptr = full_out ? h_out : (zx);
    float* cptr = full_out ? c_out : (zx + (size_t)MROWS * 512);
    tcgemm_gates<<<dim3(16, 256), 256, GATES_SMEM>>>(ah, bthi, btlo, biP, c0,
                                                     hptr, cptr, hsh, 1024);

    // ---- fc2 (A = h hi in g_HSh) ----
    splitT_kernel<<<dim3(16, 16), dim3(32, 8)>>>(Wfc2, bthi, btlo, 512, 512);
    tcgemm<<<dim3(4, 256), 256, GEMM_SMEM>>>(hsh, bthi, btlo, fc, bfc2, MROWS, 512, 512, 0);

    // ---- LN2 accumulate into out ----
    ln_kernel<<<256, 256>>>(fc, nullptr, g2, b2, out, nullptr, 1);
}

// round 8
// speedup vs baseline: 5.2830x; 1.3462x over previous
#include <cuda_runtime.h>
#include <cuda_fp16.h>
#include <cstdint>
#include <math.h>

// Problem constants
#define NSAMP 256            // B*L
#define W_    128
#define C_    512
#define HD_   256
#define MROWS 32768          // B*W
#define OUT0  ((size_t)16777216)   // B*L*W*C

// ---------------- scratch (static device globals; no allocations) ----------------
__device__ float g_ZX [(size_t)MROWS * 2048];   // combined intra projections (fwd|bwd)
__device__ float g_FC [(size_t)MROWS * 512];
__device__ float g_bfc[2048];
__device__ float g_biP[2048];
__device__ unsigned long long g_barG[8 * 16];   // per-group monotonic tickets

// fp16 operand buffers
__device__ __half g_Ah [(size_t)MROWS * 1024];
__device__ __half g_Bt [(size_t)2048 * 1024];
// recurrence state / weights / outputs (fp16)
__device__ __half g_Hh[2][512 * 256];
__device__ __half g_Ut[(size_t)2048 * 256];
__device__ __half g_HSh[(size_t)MROWS * 512];

__device__ __forceinline__ float hsig(float x) {
    return fminf(fmaxf(fmaf(0.2f, x, 0.5f), 0.0f), 1.0f);
}

// ================= low-level helpers (sm_80-baseline ISA only) =================
__device__ __forceinline__ uint32_t smem_u32(const void* p) {
    uint32_t a;
    asm("{ .reg .u64 t; cvta.to.shared.u64 t, %1; cvt.u32.u64 %0, t; }" : "=r"(a) : "l"(p));
    return a;
}
#define CP_ASYNC16(dst, src) \
    asm volatile("cp.async.cg.shared.global [%0], [%1], 16;" :: "r"(dst), "l"(src) : "memory")
#define CP_COMMIT() asm volatile("cp.async.commit_group;" ::: "memory")
#define CP_WAIT1()  asm volatile("cp.async.wait_group 1;" ::: "memory")
#define CP_WAIT0()  asm volatile("cp.async.wait_group 0;" ::: "memory")

__device__ __forceinline__ void ldmx4(uint32_t* r, uint32_t addr) {
    asm volatile("ldmatrix.sync.aligned.m8n8.x4.shared.b16 {%0,%1,%2,%3}, [%4];"
        : "=r"(r[0]), "=r"(r[1]), "=r"(r[2]), "=r"(r[3]) : "r"(addr));
}
__device__ __forceinline__ void mma_f16(float* d, const uint32_t* a, const uint32_t* b) {
    asm volatile("mma.sync.aligned.m16n8k16.row.col.f32.f16.f16.f32 "
        "{%0,%1,%2,%3}, {%4,%5,%6,%7}, {%8,%9}, {%0,%1,%2,%3};"
        : "+f"(d[0]), "+f"(d[1]), "+f"(d[2]), "+f"(d[3])
        : "r"(a[0]), "r"(a[1]), "r"(a[2]), "r"(a[3]), "r"(b[0]), "r"(b[1]));
}

// ================= fp16 tensor-core GEMM =================
// C[M,N] = Ah[M,K] @ Bh[N,K]^T (+bias) (+=C). fp32 accumulate.
#define TILE_B   10240           // 128*80
#define STG_B    20480           // 2 tiles (Ah, Bh)
#define GEMM_SMEM  40960
#define GATES_SMEM 67584         // epilogue stg 128*132*4

__device__ __forceinline__ void load_chunk(uint32_t stage_base,
    const __half* __restrict__ Ah, const __half* __restrict__ Bh,
    int m0, int n0, int kk, int K, int tid)
{
#pragma unroll
    for (int i = 0; i < 2; i++) {
        const int c = tid + i * 256;
        const int row = c >> 2;
        const int seg = c & 3;
        const uint32_t doff = (uint32_t)(row * 80 + seg * 16);
        const size_t akoff = (size_t)kk + seg * 8;
        CP_ASYNC16(stage_base + 0 * TILE_B + doff, Ah + (size_t)(m0 + row) * K + akoff);
        CP_ASYNC16(stage_base + 1 * TILE_B + doff, Bh + (size_t)(n0 + row) * K + akoff);
    }
}

#define GEMM_MAINLOOP(Ah, Bh, m0, n0, K, acc)                                     \
    {                                                                             \
        const int NC = (K) >> 5;                                                  \
        load_chunk(sb, Ah, Bh, m0, n0, 0, K, tid);                                \
        CP_COMMIT();                                                              \
        load_chunk(sb + STG_B, Ah, Bh, m0, n0, 32, K, tid);                       \
        CP_COMMIT();                                                              \
        for (int c = 0; c < NC; c++) {                                            \
            CP_WAIT1();                                                           \
            __syncthreads();                                                      \
            const uint32_t st = sb + (c & 1) * STG_B;                             \
            _Pragma("unroll")                                                     \
            for (int ks = 0; ks < 2; ks++) {                                      \
                const uint32_t kb = st + ks * 32;                                 \
                uint32_t af[4][4], bhf[4][2], t4[4];                              \
                _Pragma("unroll")                                                 \
                for (int nh = 0; nh < 2; nh++) {                                  \
                    ldmx4(t4, kb + 1 * TILE_B + b_off + nh * 1280);               \
                    bhf[2*nh][0] = t4[0]; bhf[2*nh][1] = t4[1];                   \
                    bhf[2*nh+1][0] = t4[2]; bhf[2*nh+1][1] = t4[3];               \
                }                                                                 \
                _Pragma("unroll")                                                 \
                for (int mf = 0; mf < 4; mf++) ldmx4(af[mf], kb + a_off + mf * 1280); \
                _Pragma("unroll")                                                 \
                for (int mf = 0; mf < 4; mf++)                                    \
                    _Pragma("unroll")                                             \
                    for (int nf = 0; nf < 4; nf++)                                \
                        mma_f16(acc[mf][nf], af[mf], bhf[nf]);                    \
            }                                                                     \
            __syncthreads();                                                      \
            if (c + 2 < NC)                                                       \
                load_chunk(sb + (c & 1) * STG_B, Ah, Bh, m0, n0, (c + 2) << 5, K, tid); \
            CP_COMMIT();                                                          \
        }                                                                         \
    }

__global__ __launch_bounds__(256, 2) void tcgemm(
    const __half* __restrict__ Ah, const __half* __restrict__ Bh,
    float* __restrict__ Cmat, const float* __restrict__ bias,
    int M, int N, int K, int accumulate)
{
    extern __shared__ __align__(128) char smem_raw[];
    const uint32_t sb = smem_u32(smem_raw);

    const int tid = threadIdx.x;
    const int lane = tid & 31;
    const int wid = tid >> 5;
    const int wm = wid >> 2;
    const int wn = wid & 3;
    const int m0 = blockIdx.y << 7;
    const int n0 = blockIdx.x << 7;

    const uint32_t a_off = (uint32_t)((wm * 64 + (lane & 15)) * 80 + (lane >> 4) * 16);
    const int bsub = lane >> 3;
    const uint32_t b_off = (uint32_t)((wn * 32 + ((bsub >> 1) << 3) + (lane & 7)) * 80 + (bsub & 1) * 16);

    float acc[4][4][4];
#pragma unroll
    for (int mf = 0; mf < 4; mf++)
#pragma unroll
        for (int nf = 0; nf < 4; nf++)
#pragma unroll
            for (int r = 0; r < 4; r++) acc[mf][nf][r] = 0.0f;

    GEMM_MAINLOOP(Ah, Bh, m0, n0, K, acc);

    const int qr = lane >> 2;
    const int qc = (lane & 3) << 1;
#pragma unroll
    for (int mf = 0; mf < 4; mf++) {
        const int row = m0 + wm * 64 + mf * 16 + qr;
#pragma unroll
        for (int nf = 0; nf < 4; nf++) {
            const int col = n0 + wn * 32 + nf * 8 + qc;
            float2 v0 = make_float2(acc[mf][nf][0], acc[mf][nf][1]);
            float2 v1 = make_float2(acc[mf][nf][2], acc[mf][nf][3]);
            if (bias) {
                const float2 bv = *(const float2*)(bias + col);
                v0.x += bv.x; v0.y += bv.y; v1.x += bv.x; v1.y += bv.y;
            }
            float* p0 = Cmat + (size_t)row * N + col;
            float* p1 = p0 + 8 * (size_t)N;
            if (accumulate) {
                const float2 o0 = *(const float2*)p0;
                const float2 o1 = *(const float2*)p1;
                v0.x += o0.x; v0.y += o0.y; v1.x += o1.x; v1.y += o1.y;
            }
            *(float2*)p0 = v0;
            *(float2*)p1 = v1;
        }
    }
}

// ---- inter GEMM with fused LSTM gate epilogue (gate-interleaved B layout) ----
__global__ __launch_bounds__(256, 2) void tcgemm_gates(
    const __half* __restrict__ Ah, const __half* __restrict__ Bh,
    const float* __restrict__ biasP, const float* __restrict__ c0,
    float* __restrict__ h_out, float* __restrict__ c_out,
    __half* __restrict__ hh_out, int K)
{
    extern __shared__ __align__(128) char smem_raw[];
    const uint32_t sb = smem_u32(smem_raw);

    const int tid = threadIdx.x;
    const int lane = tid & 31;
    const int wid = tid >> 5;
    const int wm = wid >> 2;
    const int wn = wid & 3;
    const int m0 = blockIdx.y << 7;
    const int n0 = blockIdx.x << 7;
    const int hid0 = blockIdx.x << 5;

    const uint32_t a_off = (uint32_t)((wm * 64 + (lane & 15)) * 80 + (lane >> 4) * 16);
    const int bsub = lane >> 3;
    const uint32_t b_off = (uint32_t)((wn * 32 + ((bsub >> 1) << 3) + (lane & 7)) * 80 + (bsub & 1) * 16);

    float acc[4][4][4];
#pragma unroll
    for (int mf = 0; mf < 4; mf++)
#pragma unroll
        for (int nf = 0; nf < 4; nf++)
#pragma unroll
            for (int r = 0; r < 4; r++) acc[mf][nf][r] = 0.0f;

    GEMM_MAINLOOP(Ah, Bh, m0, n0, K, acc);

    __syncthreads();
    float* stg = (float*)smem_raw;    // 128 x 132
    const int qr = lane >> 2;
    const int qc = (lane & 3) << 1;
#pragma unroll
    for (int mf = 0; mf < 4; mf++) {
        const int rl = wm * 64 + mf * 16 + qr;
#pragma unroll
        for (int nf = 0; nf < 4; nf++) {
            const int col = wn * 32 + nf * 8 + qc;
            const float2 bv = *(const float2*)(biasP + n0 + col);
            stg[rl * 132 + col]           = acc[mf][nf][0] + bv.x;
            stg[rl * 132 + col + 1]       = acc[mf][nf][1] + bv.y;
            stg[(rl + 8) * 132 + col]     = acc[mf][nf][2] + bv.x;
            stg[(rl + 8) * 132 + col + 1] = acc[mf][nf][3] + bv.y;
        }
    }
    __syncthreads();

    {
        const int c = lane;
#pragma unroll
        for (int i = 0; i < 16; i++) {
            const int r = wid * 16 + i;
            const float zi = stg[r * 132 + c];
            const float zf = stg[r * 132 + 32 + c];
            const float zg = stg[r * 132 + 64 + c];
            const float zo = stg[r * 132 + 96 + c];
            const size_t go = (size_t)(m0 + r) * 512 + hid0 + c;
            const float cn = hsig(zf) * c0[go] + hsig(zi) * tanhf(zg);
            const float hv = hsig(zo) * tanhf(cn);
            c_out[go] = cn;
            h_out[go] = hv;
            hh_out[go] = __float2half_rn(hv);
        }
    }
}

// ================= convert kernels =================
// fp32 -> fp16, contiguous
__global__ __launch_bounds__(256) void cvt_kernel(
    const float* __restrict__ in, __half* __restrict__ out, int n4)
{
    const int i = blockIdx.x * blockDim.x + threadIdx.x;
    if (i >= n4) return;
    const float4 v = ((const float4*)in)[i];
    ((__half2*)out)[2 * i]     = __half2(__float2half_rn(v.x), __float2half_rn(v.y));
    ((__half2*)out)[2 * i + 1] = __half2(__float2half_rn(v.z), __float2half_rn(v.w));
}

// h0 [32768,512] -> g_Ah at row*1024 + 512 + col (concat A for inter GEMM)
__global__ __launch_bounds__(256) void cvt_off_kernel(
    const float* __restrict__ in, __half* __restrict__ out)
{
    const int q = blockIdx.x * blockDim.x + threadIdx.x;
    const int row = q >> 7;
    const int col = (q & 127) << 2;
    const float4 v = ((const float4*)in)[q];
    const size_t o = (size_t)row * 1024 + 512 + col;
    *(__half2*)(out + o)     = __half2(__float2half_rn(v.x), __float2half_rn(v.y));
    *(__half2*)(out + o + 2) = __half2(__float2half_rn(v.z), __float2half_rn(v.w));
}

// transpose-convert: W [K,N] fp32 -> [N,K] fp16
__global__ void cvtT_kernel(const float* __restrict__ Wm,
                            __half* __restrict__ dst, int K, int N)
{
    __shared__ float t[32][33];
    const int kb = blockIdx.y * 32, nb = blockIdx.x * 32;
    const int tx = threadIdx.x, ty = threadIdx.y;
    for (int r = ty; r < 32; r += 8)
        t[r][tx] = Wm[(size_t)(kb + r) * N + nb + tx];
    __syncthreads();
    for (int r = ty; r < 32; r += 8)
        dst[(size_t)(nb + r) * K + kb + tx] = __float2half_rn(t[tx][r]);
}

// transpose-convert with gate-interleave permutation; writes [2048, Kout] at koff
__global__ void cvtT_perm_kernel(const float* __restrict__ Wm,
                                 __half* __restrict__ dst, int N, int Kout, int koff)
{
    __shared__ float t[32][33];
    const int kb = blockIdx.y * 32, nb = blockIdx.x * 32;
    const int tx = threadIdx.x, ty = threadIdx.y;
    for (int r = ty; r < 32; r += 8)
        t[r][tx] = Wm[(size_t)(kb + r) * N + nb + tx];
    __syncthreads();
    for (int r = ty; r < 32; r += 8) {
        const int n = nb + r;
        const int g = n >> 9, s = n & 511;
        const int nr = ((s >> 5) << 7) + (g << 5) + (s & 31);
        dst[(size_t)nr * Kout + koff + kb + tx] = __float2half_rn(t[tx][r]);
    }
}

// bias prep: bfc = [bf|bb]; biP = gate-permuted bi
__global__ void bias_prep(const float* __restrict__ bf, const float* __restrict__ bb,
                          const float* __restrict__ bi,
                          float* __restrict__ bfc, float* __restrict__ biP)
{
    const int i = blockIdx.x * blockDim.x + threadIdx.x;
    if (i < 1024) bfc[i] = bf[i];
    else if (i < 2048) bfc[i] = bb[i - 1024];
    else {
        const int n = i - 2048;
        const int g = n >> 9, s = n & 511;
        const int nr = ((s >> 5) << 7) + (g << 5) + (s & 31);
        biP[nr] = bi[n];
    }
}

// ---------------- group barrier (16 CTAs per group) ----------------
__device__ __forceinline__ void group_barrier(int grp) {
    __threadfence();
    __syncthreads();
    if (threadIdx.x == 0) {
        unsigned long long* ctr = &g_barG[grp * 16];
        unsigned long long t = atomicAdd(ctr, 1ULL) + 1ULL;
        unsigned long long target = ((t + 15ULL) >> 4) << 4;
        volatile unsigned long long* p = ctr;
        while (*p < target) { __nanosleep(32); }
        __threadfence();
    }
    __syncthreads();
}

// ---------------- persistent bidirectional LSTM recurrence (pure fp16) ----------------
#define RA_STR   528
#define ROFF_BHI 33792
#define ROFF_STG 67584
#define ROFF_ZX  84992
#define RSMEM    101376

__global__ __launch_bounds__(256) void recurrence2(const __half* __restrict__ Ut)
{
    extern __shared__ __align__(128) char rsm[];
    const uint32_t sb = smem_u32(rsm);
    const int tid = threadIdx.x, lane = tid & 31, wid = tid >> 5;
    const int blk = blockIdx.x;
    const int tile_m = blk >> 4;         // 0..7 (= barrier group)
    const int tile_n = blk & 15;
    const int row0 = tile_m << 6;
    const int dir = (tile_m >= 4) ? 1 : 0;
    const int j0 = tile_n << 4;
    const int wm = wid & 3, wn = wid >> 2;

    // U^T slice resident: 64 rows (gate*16+c) x 256 k
    for (int i = tid; i < 2048; i += 256) {
        const int r = i >> 5, seg = i & 31;
        const int g = r >> 4, c = r & 15;
        const size_t gr = ((size_t)(dir * 1024 + g * 256 + j0 + c)) * 256 + seg * 8;
        *(uint4*)(rsm + ROFF_BHI + r * RA_STR + seg * 16) = *(const uint4*)(Ut + gr);
    }

    if (tile_n == 0) {
        uint32_t* h0 = (uint32_t*)&g_Hh[0][row0 * 256];
        for (int i = tid; i < 8192; i += 256) h0[i] = 0u;
    }

    const uint32_t a_off = (uint32_t)((wm * 16 + (lane & 15)) * RA_STR + (lane >> 4) * 16);
    const int bsub = lane >> 3;
    const uint32_t b_off = (uint32_t)((wn * 32 + ((bsub >> 1) << 3) + (lane & 7)) * RA_STR + (bsub & 1) * 16);

    const int r_up = tid >> 2;
    const int c_up = (tid & 3) << 2;
    const int Rr = row0 + r_up;
    const int n_up = Rr & 255;
    float* stg = (float*)(rsm + ROFF_STG);
    float* zxs = (float*)(rsm + ROFF_ZX);
    float creg[4] = {0.0f, 0.0f, 0.0f, 0.0f};

    group_barrier(tile_m);

    for (int t = 0; t < 128; t++) {
        const int pb = t & 1;
        const int w = dir ? (127 - t) : t;
        const __half* hh = g_Hh[pb];

        // ---- commit group 1: H k 0..127 ----
#pragma unroll
        for (int ii = 0; ii < 4; ii++) {
            const int i = tid + ii * 256;
            const int r = i >> 4, seg = i & 15;
            CP_ASYNC16(sb + r * RA_STR + seg * 16, hh + (size_t)(row0 + r) * 256 + seg * 8);
        }
        CP_COMMIT();
        // ---- commit group 2: H k 128..255 + zx prefetch ----
#pragma unroll
        for (int ii = 0; ii < 4; ii++) {
            const int i = tid + ii * 256;
            const int r = i >> 4, seg = 16 + (i & 15);
            CP_ASYNC16(sb + r * RA_STR + seg * 16, hh + (size_t)(row0 + r) * 256 + seg * 8);
        }
        {
            const float* zxrow = g_ZX + ((size_t)n_up * 128 + w) * 2048 + dir * 1024 + j0;
#pragma unroll
            for (int g = 0; g < 4; g++)
                CP_ASYNC16(sb + ROFF_ZX + r_up * 256 + g * 64 + c_up * 4,
                           zxrow + g * 256 + c_up);
        }
        CP_COMMIT();

        float acc[4][4];
#pragma unroll
        for (int nf = 0; nf < 4; nf++)
#pragma unroll
            for (int r = 0; r < 4; r++) acc[nf][r] = 0.0f;

        // ---- first half (k 0..127) while second half lands ----
        CP_WAIT1();
        __syncthreads();
#pragma unroll
        for (int ks = 0; ks < 8; ks++) {
            const uint32_t kb = ks * 32;
            uint32_t ah[4], bh[4][2], t4[4];
            ldmx4(ah, sb + a_off + kb);
#pragma unroll
            for (int nh = 0; nh < 2; nh++) {
                ldmx4(t4, sb + ROFF_BHI + b_off + kb + nh * 16 * RA_STR);
                bh[2 * nh][0] = t4[0]; bh[2 * nh][1] = t4[1];
                bh[2 * nh + 1][0] = t4[2]; bh[2 * nh + 1][1] = t4[3];
            }
#pragma unroll
            for (int nf = 0; nf < 4; nf++)
                mma_f16(acc[nf], ah, bh[nf]);
        }
        // ---- second half (k 128..255) ----
        CP_WAIT0();
        __syncthreads();
#pragma unroll
        for (int ks = 8; ks < 16; ks++) {
            const uint32_t kb = ks * 32;
            uint32_t ah[4], bh[4][2], t4[4];
            ldmx4(ah, sb + a_off + kb);
#pragma unroll
            for (int nh = 0; nh < 2; nh++) {
                ldmx4(t4, sb + ROFF_BHI + b_off + kb + nh * 16 * RA_STR);
                bh[2 * nh][0] = t4[0]; bh[2 * nh][1] = t4[1];
                bh[2 * nh + 1][0] = t4[2]; bh[2 * nh + 1][1] = t4[3];
            }
#pragma unroll
            for (int nf = 0; nf < 4; nf++)
                mma_f16(acc[nf], ah, bh[nf]);
        }

        {
            const int qr = lane >> 2, qc = (lane & 3) << 1;
#pragma unroll
            for (int nf = 0; nf < 4; nf++) {
                const int col = wn * 32 + nf * 8 + qc;
                stg[(wm * 16 + qr) * 68 + col]     = acc[nf][0];
                stg[(wm * 16 + qr) * 68 + col + 1] = acc[nf][1];
                stg[(wm * 16 + qr + 8) * 68 + col]     = acc[nf][2];
                stg[(wm * 16 + qr + 8) * 68 + col + 1] = acc[nf][3];
            }
        }
        __syncthreads();

        {
            __half* dhh = &g_Hh[pb ^ 1][(size_t)Rr * 256 + j0 + c_up];
            const size_t hsoff = ((size_t)n_up * 128 + w) * 512 + dir * 256 + j0 + c_up;
            const float* zx = &zxs[r_up * 64 + c_up];
            float hv[4];
#pragma unroll
            for (int l = 0; l < 4; l++) {
                const float* sr = &stg[r_up * 68 + c_up + l];
                const float zi = sr[0]  + zx[l];
                const float zf = sr[16] + zx[16 + l];
                const float zg = sr[32] + zx[32 + l];
                const float zo = sr[48] + zx[48 + l];
                const float cn = hsig(zf) * creg[l] + hsig(zi) * tanhf(zg);
                creg[l] = cn;
                hv[l] = hsig(zo) * tanhf(cn);
            }
            const __half2 p0 = __half2(__float2half_rn(hv[0]), __float2half_rn(hv[1]));
            const __half2 p1 = __half2(__float2half_rn(hv[2]), __float2half_rn(hv[3]));
            *(__half2*)(dhh)     = p0;
            *(__half2*)(dhh + 2) = p1;
            *(__half2*)(g_HSh + hsoff)     = p0;
            *(__half2*)(g_HSh + hsoff + 2) = p1;
        }

        if (t < 127) group_barrier(tile_m);
    }
}

// ---------------- LayerNorm over (W,C)=65536, optional fused fp16 convert (stride 1024) ----------------
__global__ __launch_bounds__(256) void ln_kernel(
    const float* __restrict__ pre, const float* __restrict__ xres,
    const float* __restrict__ gamma, const float* __restrict__ beta,
    float* __restrict__ out, __half* __restrict__ sh, int mode)
{
    __shared__ float red[256];
    const int tid = threadIdx.x;
    const size_t base = (size_t)blockIdx.x * 65536;

    float s = 0.0f, ss = 0.0f;
    for (int i = tid * 4; i < 65536; i += 1024) {
        float4 v = *(const float4*)(pre + base + i);
        s  += v.x + v.y + v.z + v.w;
        ss += v.x * v.x + v.y * v.y + v.z * v.z + v.w * v.w;
    }
    red[tid] = s; __syncthreads();
    for (int off = 128; off; off >>= 1) { if (tid < off) red[tid] += red[tid + off]; __syncthreads(); }
    const float mean = red[0] * (1.0f / 65536.0f);
    __syncthreads();
    red[tid] = ss; __syncthreads();
    for (int off = 128; off; off >>= 1) { if (tid < off) red[tid] += red[tid + off]; __syncthreads(); }
    const float var = red[0] * (1.0f / 65536.0f) - mean * mean;
    const float rstd = rsqrtf(var + 1e-3f);

    for (int i = tid * 4; i < 65536; i += 1024) {
        float4 v = *(const float4*)(pre + base + i);
        float4 g = *(const float4*)(gamma + i);
        float4 bb = *(const float4*)(beta + i);
        float4 r;
        r.x = (v.x - mean) * rstd * g.x + bb.x;
        r.y = (v.y - mean) * rstd * g.y + bb.y;
        r.z = (v.z - mean) * rstd * g.z + bb.z;
        r.w = (v.w - mean) * rstd * g.w + bb.w;
        if (mode == 0) {
            float4 xr = *(const float4*)(xres + base + i);
            r.x += xr.x; r.y += xr.y; r.z += xr.z; r.w += xr.w;
        } else {
            float4 o = *(const float4*)(out + base + i);
            r.x += o.x; r.y += o.y; r.z += o.z; r.w += o.w;
        }
        *(float4*)(out + base + i) = r;
        if (sh) {
            const size_t f = base + i;
            const size_t so = (f >> 9) * 1024 + (f & 511);
            *(__half2*)(sh + so)     = __half2(__float2half_rn(r.x), __float2half_rn(r.y));
            *(__half2*)(sh + so + 2) = __half2(__float2half_rn(r.z), __float2half_rn(r.w));
        }
    }
}

// ---------------- launch ----------------
extern "C" void kernel_launch(void* const* d_in, const int* in_sizes, int n_in,
                              void* d_out, int out_size)
{
    const float* x    = (const float*)d_in[0];
    const float* h0   = (const float*)d_in[1];
    const float* c0   = (const float*)d_in[2];
    const float* Wf   = (const float*)d_in[3];
    const float* Uf   = (const float*)d_in[4];
    const float* bf   = (const float*)d_in[5];
    const float* Wb   = (const float*)d_in[6];
    const float* Ub   = (const float*)d_in[7];
    const float* bb   = (const float*)d_in[8];
    const float* Wfc1 = (const float*)d_in[9];
    const float* bfc1 = (const float*)d_in[10];
    const float* g1   = (const float*)d_in[11];
    const float* b1   = (const float*)d_in[12];
    const float* Wi   = (const float*)d_in[13];
    const float* Ui   = (const float*)d_in[14];
    const float* bi   = (const float*)d_in[15];
    const float* Wfc2 = (const float*)d_in[16];
    const float* bfc2 = (const float*)d_in[17];
    const float* g2   = (const float*)d_in[18];
    const float* b2   = (const float*)d_in[19];

    float* out = (float*)d_out;
    float* h_out = out + OUT0;
    float* c_out = out + 2 * OUT0;
    const int full_out = (out_size >= (int)(3 * OUT0)) || out_size <= 0;

    float *zx, *fc, *bfc, *biP;
    __half *ah, *bt, *ut, *hsh;
    cudaGetSymbolAddress((void**)&zx,  g_ZX);
    cudaGetSymbolAddress((void**)&fc,  g_FC);
    cudaGetSymbolAddress((void**)&bfc, g_bfc);
    cudaGetSymbolAddress((void**)&biP, g_biP);
    cudaGetSymbolAddress((void**)&ah,  g_Ah);
    cudaGetSymbolAddress((void**)&bt,  g_Bt);
    cudaGetSymbolAddress((void**)&ut,  g_Ut);
    cudaGetSymbolAddress((void**)&hsh, g_HSh);

    cudaFuncSetAttribute(tcgemm, cudaFuncAttributeMaxDynamicSharedMemorySize, GEMM_SMEM);
    cudaFuncSetAttribute(tcgemm_gates, cudaFuncAttributeMaxDynamicSharedMemorySize, GATES_SMEM);
    cudaFuncSetAttribute(recurrence2, cudaFuncAttributeMaxDynamicSharedMemorySize, RSMEM);

    const int n4A = MROWS * 512 / 4;

    // ---- combined intra input projection: ZX = x @ [Wf|Wb] + [bf|bb] ----
    cvt_kernel<<<n4A / 256, 256>>>(x, ah, n4A);
    bias_prep<<<16, 256>>>(bf, bb, bi, bfc, biP);
    cvtT_kernel<<<dim3(32, 16), dim3(32, 8)>>>(Wf, bt, 512, 1024);
    cvtT_kernel<<<dim3(32, 16), dim3(32, 8)>>>(Wb, bt + (size_t)1024 * 512, 512, 1024);
    tcgemm<<<dim3(16, 256), 256, GEMM_SMEM>>>(ah, bt, zx, bfc, MROWS, 2048, 512, 0);

    // ---- recurrent weights + recurrence ----
    cvtT_kernel<<<dim3(32, 8), dim3(32, 8)>>>(Uf, ut, 256, 1024);
    cvtT_kernel<<<dim3(32, 8), dim3(32, 8)>>>(Ub, ut + 1024 * 256, 256, 1024);
    recurrence2<<<128, 256, RSMEM>>>(ut);

    // ---- fc1 (A = HS) ----
    cvtT_kernel<<<dim3(16, 16), dim3(32, 8)>>>(Wfc1, bt, 512, 512);
    tcgemm<<<dim3(4, 256), 256, GEMM_SMEM>>>(hsh, bt, fc, bfc1, MROWS, 512, 512, 0);

    // ---- LN1 + residual -> out, fused convert (concat A cols 0..511) ----
    ln_kernel<<<256, 256>>>(fc, x, g1, b1, out, ah, 0);

    // ---- inter: single K=1024 GEMM with fused gates ----
    cvt_off_kernel<<<16384, 256>>>(h0, ah);
    cvtT_perm_kernel<<<dim3(64, 16), dim3(32, 8)>>>(Wi, bt, 2048, 1024, 0);
    cvtT_perm_kernel<<<dim3(64, 16), dim3(32, 8)>>>(Ui, bt, 2048, 1024, 512);
    float* hptr = full_out ? h_out : (zx);
    float* cptr = full_out ? c_out : (zx + (size_t)MROWS * 512);
    tcgemm_gates<<<dim3(16, 256), 256, GATES_SMEM>>>(ah, bt, biP, c0,
                                                     hptr, cptr, hsh, 1024);

    // ---- fc2 (A = h in g_HSh) ----
    cvtT_kernel<<<dim3(16, 16), dim3(32, 8)>>>(Wfc2, bt, 512, 512);
    tcgemm<<<dim3(4, 256), 256, GEMM_SMEM>>>(hsh, bt, fc, bfc2, MROWS, 512, 512, 0);

    // ---- LN2 accumulate into out ----
    ln_kernel<<<256, 256>>>(fc, nullptr, g2, b2, out, nullptr, 1);
}